// round 8
// baseline (speedup 1.0000x reference)
#include <cuda_runtime.h>
#include <cuda_bf16.h>
#include <cstddef>
#include <cstdint>

#define Bsz 32
#define Ssz 128
#define Tsz 64
#define T1  63
#define Ed  256
#define Hd  512
#define Vsz 32000
#define FH  2048
#define NBLK 128
#define Mrows 2016       // Bsz*T1
#define MrowsPad 2048

// ---------------- device scratch ----------------
__device__ __align__(16) float g_src_emb[(size_t)Ssz * Bsz * Ed];
__device__ __align__(16) float g_dec_in [(size_t)T1  * Bsz * Ed];
__device__ __align__(16) float g_enc_xg [(size_t)Ssz * Bsz * FH];
__device__ __align__(16) float g_dec_xg [(size_t)T1  * Bsz * FH];
__device__ __align__(16) float g_enc_out[(size_t)Bsz * Ssz * Hd];
__device__ __align__(16) float g_enc_proj[(size_t)Bsz * Ssz * Hd];
__device__ __align__(16) float g_hs     [(size_t)Bsz * T1  * Hd];
__device__ __align__(16) float g_h[2][Bsz * Hd];
__device__ __align__(16) float g_c [Bsz * Hd];
__device__ __align__(16) float g_ctx[Bsz * Hd];
__device__ __align__(16) float g_hproj[Bsz * Hd];
__device__ __align__(16) float g_scores[Bsz * Ssz];
__device__ unsigned g_arrive[2][NBLK];   // per-block arrival slots (no atomic contention)
__device__ unsigned g_genw[2];           // generation words
// bf16 hi/lo split operands for the FC tensor GEMM
__device__ __align__(16) __nv_bfloat16 g_hs_hi[(size_t)MrowsPad * Hd];
__device__ __align__(16) __nv_bfloat16 g_hs_lo[(size_t)MrowsPad * Hd];
__device__ __align__(16) __nv_bfloat16 g_fcw_hi[(size_t)Vsz * Hd];
__device__ __align__(16) __nv_bfloat16 g_fcw_lo[(size_t)Vsz * Hd];

__device__ __forceinline__ float sigf(float x) { return 1.0f / (1.0f + expf(-x)); }
__device__ __forceinline__ float tanh_fast(float x) {
    float y;
    asm("tanh.approx.f32 %0, %1;" : "=f"(y) : "f"(x));
    return y;
}

// ---------------- packed f32x2 FMA ----------------
__device__ __forceinline__ void ffma2(unsigned long long& d, unsigned long long a, unsigned long long b) {
    asm("fma.rn.f32x2 %0, %1, %2, %0;" : "+l"(d) : "l"(a), "l"(b));
}
__device__ __forceinline__ float f32x2_sum(unsigned long long v) {
    float lo, hi;
    asm("mov.b64 {%0, %1}, %2;" : "=f"(lo), "=f"(hi) : "l"(v));
    return lo + hi;
}
__device__ __forceinline__ void f32x2_unpack(unsigned long long v, float& lo, float& hi) {
    asm("mov.b64 {%0, %1}, %2;" : "=f"(lo), "=f"(hi) : "l"(v));
}
__device__ __forceinline__ unsigned long long pack2(float lo, float hi) {
    unsigned long long v;
    asm("mov.b64 %0, {%1, %2};" : "=l"(v) : "f"(lo), "f"(hi));
    return v;
}

__device__ __forceinline__ uint32_t smem_to_u32(const void* p) {
    uint32_t a;
    asm("{ .reg .u64 t; cvta.to.shared.u64 t, %1; cvt.u32.u64 %0, t; }" : "=r"(a) : "l"(p));
    return a;
}
__device__ __forceinline__ void ldsm_x4(uint32_t* r, uint32_t addr) {
    asm volatile("ldmatrix.sync.aligned.m8n8.x4.shared.b16 {%0,%1,%2,%3}, [%4];"
        : "=r"(r[0]), "=r"(r[1]), "=r"(r[2]), "=r"(r[3]) : "r"(addr));
}
__device__ __forceinline__ void mma_bf16(float* d, const uint32_t* a, uint32_t b0, uint32_t b1) {
    asm volatile("mma.sync.aligned.m16n8k16.row.col.f32.bf16.bf16.f32 "
        "{%0,%1,%2,%3}, {%4,%5,%6,%7}, {%8,%9}, {%0,%1,%2,%3};"
        : "+f"(d[0]), "+f"(d[1]), "+f"(d[2]), "+f"(d[3])
        : "r"(a[0]), "r"(a[1]), "r"(a[2]), "r"(a[3]), "r"(b0), "r"(b1));
}
__device__ __forceinline__ void cp_async16(uint32_t dst, const void* src) {
    asm volatile("cp.async.cg.shared.global [%0], [%1], 16;" :: "r"(dst), "l"(src) : "memory");
}

// ---------------- atomic-free global barrier (store/poll, no L2-atomic serialization) ----------------
__device__ __forceinline__ void grid_bar(int which, unsigned target) {
    __threadfence();
    __syncthreads();
    volatile unsigned* arr = (volatile unsigned*)g_arrive[which];
    volatile unsigned* gen = (volatile unsigned*)&g_genw[which];
    if (blockIdx.x == 0) {
        if (threadIdx.x < 32) {
            if (threadIdx.x == 0) arr[0] = target;
            bool ok;
            do {
                ok = true;
                #pragma unroll
                for (int q = 0; q < 4; q++)
                    ok = ok && (arr[threadIdx.x + q * 32] >= target);
            } while (!__all_sync(0xffffffffu, ok));
            __threadfence();
            if (threadIdx.x == 0) *gen = target;
        }
    } else {
        if (threadIdx.x == 0) {
            arr[blockIdx.x] = target;
            while (*gen < target) { }
            __threadfence();
        }
    }
    __syncthreads();
}

__global__ void init_state_kernel() {
    int i = blockIdx.x * blockDim.x + threadIdx.x;
    if (i < Bsz * Hd) g_h[0][i] = 0.f;
    if (i < 2 * NBLK) ((unsigned*)g_arrive)[i] = 0u;
    if (i < 2) g_genw[i] = 0u;
}

// ---------------- embedding gathers ----------------
__global__ void gather_src_kernel(const int* __restrict__ src, const float* __restrict__ embed) {
    int row = blockIdx.x;           // s*B + b
    int s = row >> 5, b = row & 31;
    int idx = src[b * Ssz + s];
    g_src_emb[(size_t)row * Ed + threadIdx.x] = embed[(size_t)idx * Ed + threadIdx.x];
}
__global__ void gather_dec_kernel(const int* __restrict__ tgt, const float* __restrict__ embed) {
    int row = blockIdx.x;           // t*B + b
    int t = row >> 5, b = row & 31;
    int idx = tgt[b * Tsz + t];
    g_dec_in[(size_t)row * Ed + threadIdx.x] = embed[(size_t)idx * Ed + threadIdx.x];
}

// ---------------- fp32 SGEMM with f32x2 FMA (small GEMMs) ----------------
__global__ void __launch_bounds__(256) sgemm_bias_kernel(
    const float* __restrict__ A, int K,
    const float* __restrict__ W, int ldw, int woff,
    const float* __restrict__ b1, const float* __restrict__ b2,
    float* __restrict__ C, int M, int N)
{
    __shared__ __align__(16) float As[8][128];
    __shared__ __align__(16) float Bs[8][128];
    const int bm = blockIdx.y * 128;
    const int bn = blockIdx.x * 128;
    const int t  = threadIdx.x;
    const int tr = (t >> 4) * 8;
    const int tc = (t & 15) * 8;
    const int lr = t >> 1;
    const int lc = (t & 1) * 4;

    unsigned long long acc2[8][4];
    #pragma unroll
    for (int i = 0; i < 8; i++)
        #pragma unroll
        for (int j = 0; j < 4; j++) acc2[i][j] = 0ull;

    const bool aValid = (bm + lr) < M;
    const float* aRow = A + (size_t)(bm + lr) * K + lc;
    const float* wRow = W + (size_t)(bn + lr) * ldw + woff + lc;

    for (int k0 = 0; k0 < K; k0 += 8) {
        float4 av = aValid ? *(const float4*)(aRow + k0) : make_float4(0.f, 0.f, 0.f, 0.f);
        float4 wv = *(const float4*)(wRow + k0);
        As[lc + 0][lr] = av.x; As[lc + 1][lr] = av.y; As[lc + 2][lr] = av.z; As[lc + 3][lr] = av.w;
        Bs[lc + 0][lr] = wv.x; Bs[lc + 1][lr] = wv.y; Bs[lc + 2][lr] = wv.z; Bs[lc + 3][lr] = wv.w;
        __syncthreads();
        #pragma unroll
        for (int kk = 0; kk < 8; kk++) {
            float a[8];
            *(float4*)(a)      = *(const float4*)&As[kk][tr];
            *(float4*)(a + 4)  = *(const float4*)&As[kk][tr + 4];
            unsigned long long bb2[4];
            *(ulonglong2*)&bb2[0] = *(const ulonglong2*)&Bs[kk][tc];
            *(ulonglong2*)&bb2[2] = *(const ulonglong2*)&Bs[kk][tc + 4];
            #pragma unroll
            for (int i = 0; i < 8; i++) {
                unsigned long long ap = pack2(a[i], a[i]);
                #pragma unroll
                for (int j = 0; j < 4; j++) ffma2(acc2[i][j], ap, bb2[j]);
            }
        }
        __syncthreads();
    }

    float bias[8];
    #pragma unroll
    for (int j = 0; j < 8; j++) {
        int n = bn + tc + j;
        bias[j] = b1[n] + (b2 ? b2[n] : 0.f);
    }
    #pragma unroll
    for (int i = 0; i < 8; i++) {
        int m = bm + tr + i;
        if (m >= M) break;
        float* cp = C + (size_t)m * N + bn + tc;
        #pragma unroll
        for (int j = 0; j < 4; j++) {
            float lo, hi;
            f32x2_unpack(acc2[i][j], lo, hi);
            cp[j * 2]     = lo + bias[j * 2];
            cp[j * 2 + 1] = hi + bias[j * 2 + 1];
        }
    }
}

// ---------------- gate partial-GEMM helper (f32x2) ----------------
__device__ __forceinline__ void gates_partial(
    const float* sm, int wbase, int xbase, int jg, int bg, int ks, unsigned long long acc[4][4])
{
    const int k0 = ks * 64;
    #pragma unroll 4
    for (int k4 = 0; k4 < 16; k4++) {
        const int k = k0 + (k4 << 2);
        ulonglong2 wv[4], hv[4];
        #pragma unroll
        for (int jj = 0; jj < 4; jj++)
            wv[jj] = *(const ulonglong2*)&sm[wbase + (jj * 4 + jg) * 516 + k];
        #pragma unroll
        for (int bb = 0; bb < 4; bb++)
            hv[bb] = *(const ulonglong2*)&sm[xbase + (bb * 8 + bg) * 516 + k];
        #pragma unroll
        for (int jj = 0; jj < 4; jj++)
            #pragma unroll
            for (int bb = 0; bb < 4; bb++) {
                ffma2(acc[jj][bb], wv[jj].x, hv[bb].x);
                ffma2(acc[jj][bb], wv[jj].y, hv[bb].y);
            }
    }
}

// ---------------- persistent encoder scan ----------------
#define ENC_SMEM_BYTES (28992 * 4)
__global__ void __launch_bounds__(256, 1) enc_scan_kernel(const float* __restrict__ Whh) {
    extern __shared__ float sm[];
    const int tid = threadIdx.x, hG = blockIdx.x;
    const int W0 = 0, HX = 8256, RD = 24768;

    for (int i = tid; i < 16 * 128; i += 256) {
        int r = i >> 7, k4 = i & 127;
        int j = (r >> 2) * Hd + hG * 4 + (r & 3);
        *(float4*)&sm[W0 + r * 516 + k4 * 4] = *(const float4*)&Whh[(size_t)j * Hd + k4 * 4];
    }

    float c_reg = 0.f;
    const int jg = tid & 3, bg = (tid >> 2) & 7, ks = tid >> 5;
    unsigned bgen = 0;

    for (int s = 0; s < Ssz; s++) {
        const float* hin = g_h[s & 1];
        float* hout = g_h[(s + 1) & 1];
        for (int i = tid; i < 32 * 128; i += 256) {
            int b = i >> 7, k4 = i & 127;
            *(float4*)&sm[HX + b * 516 + k4 * 4] = __ldcg((const float4*)&hin[(b << 9) + k4 * 4]);
        }
        __syncthreads();

        unsigned long long acc[4][4];
        #pragma unroll
        for (int a = 0; a < 4; a++)
            #pragma unroll
            for (int b2 = 0; b2 < 4; b2++) acc[a][b2] = 0ull;
        gates_partial(sm, W0, HX, jg, bg, ks, acc);

        #pragma unroll
        for (int jj = 0; jj < 4; jj++)
            #pragma unroll
            for (int bb = 0; bb < 4; bb++)
                sm[RD + ks * 528 + (jj * 4 + jg) * 33 + bb * 8 + bg] = f32x2_sum(acc[jj][bb]);
        __syncthreads();

        if (tid < 128) {
            const int hl = tid >> 5, b = tid & 31;
            float g4[4];
            #pragma unroll
            for (int gate = 0; gate < 4; gate++) {
                int r = gate * 4 + hl;
                float a = 0.f;
                #pragma unroll
                for (int q = 0; q < 8; q++) a += sm[RD + q * 528 + r * 33 + b];
                g4[gate] = a + g_enc_xg[((size_t)s * Bsz + b) * FH + gate * Hd + hG * 4 + hl];
            }
            float cv = sigf(g4[1]) * c_reg + sigf(g4[0]) * tanhf(g4[2]);
            float hn = sigf(g4[3]) * tanhf(cv);
            c_reg = cv;
            hout[(b << 9) + hG * 4 + hl] = hn;
            g_enc_out[((size_t)b * Ssz + s) * Hd + hG * 4 + hl] = hn;
        }
        bgen++;
        grid_bar(0, bgen);
    }
    if (tid < 128) {
        const int hl = tid >> 5, b = tid & 31;
        g_c[(b << 9) + hG * 4 + hl] = c_reg;
    }
}

// ---------------- persistent decoder scan (attention fused) ----------------
#define DEC_SMEM_BYTES (40464 * 4)
__global__ void __launch_bounds__(256, 1) dec_scan_kernel(
    const float* __restrict__ Wih, const float* __restrict__ Whh,
    const float* __restrict__ attnW, const float* __restrict__ attnv)
{
    extern __shared__ float sm[];
    const int tid = threadIdx.x, hG = blockIdx.x;
    const int W0 = 0, WC = 8256, WA = 16512, HX = 18576, RD = 35088,
              HP = 39312, VS = 39824, SC = 40336;

    for (int i = tid; i < 16 * 128; i += 256) {
        int r = i >> 7, k4 = i & 127;
        int j = (r >> 2) * Hd + hG * 4 + (r & 3);
        *(float4*)&sm[W0 + r * 516 + k4 * 4] = *(const float4*)&Whh[(size_t)j * Hd + k4 * 4];
        *(float4*)&sm[WC + r * 516 + k4 * 4] = *(const float4*)&Wih[(size_t)j * (Ed + Hd) + Ed + k4 * 4];
    }
    for (int i = tid; i < 4 * 128; i += 256) {
        int r = i >> 7, k4 = i & 127;
        *(float4*)&sm[WA + r * 516 + k4 * 4] = *(const float4*)&attnW[(size_t)(hG * 4 + r) * (2 * Hd) + k4 * 4];
    }
    for (int i = tid; i < Hd; i += 256) sm[VS + i] = attnv[i];

    float c_reg = 0.f;
    if (tid < 128) {
        const int hl = tid >> 5, b = tid & 31;
        c_reg = __ldcg(&g_c[(b << 9) + hG * 4 + hl]);
    }

    const int jg = tid & 3, bg = (tid >> 2) & 7, ks = tid >> 5;
    const int bB = hG >> 2;
    unsigned bgen = 0;

    for (int t = 0; t < T1; t++) {
        const float* hin = g_h[t & 1];
        float* hout = g_h[(t + 1) & 1];

        // ---- phase A ----
        for (int i = tid; i < 32 * 128; i += 256) {
            int b = i >> 7, k4 = i & 127;
            *(float4*)&sm[HX + b * 516 + k4 * 4] = __ldcg((const float4*)&hin[(b << 9) + k4 * 4]);
        }
        __syncthreads();
        {
            const int ko = tid >> 6, bh = (tid >> 1) & 31, kh = tid & 1;
            float a = 0.f;
            const int kb = kh << 8;
            #pragma unroll 4
            for (int k = kb; k < kb + 256; k += 4) {
                float4 w4 = *(const float4*)&sm[WA + ko * 516 + k];
                float4 h4 = *(const float4*)&sm[HX + bh * 516 + k];
                a += w4.x * h4.x + w4.y * h4.y + w4.z * h4.z + w4.w * h4.w;
            }
            a += __shfl_xor_sync(0xffffffffu, a, 1);
            if (!kh) g_hproj[(bh << 9) + hG * 4 + ko] = a;
        }
        unsigned long long acc[4][4];
        #pragma unroll
        for (int a2 = 0; a2 < 4; a2++)
            #pragma unroll
            for (int b2 = 0; b2 < 4; b2++) acc[a2][b2] = 0ull;
        gates_partial(sm, W0, HX, jg, bg, ks, acc);
        bgen++; grid_bar(1, bgen);

        // ---- phase B ----
        for (int i = tid; i < Hd; i += 256) sm[HP + i] = __ldcg(&g_hproj[(bB << 9) + i]);
        __syncthreads();
        {
            const int s0 = (hG & 3) * 32, w = tid >> 5, lane = tid & 31;
            #pragma unroll
            for (int q = 0; q < 4; q++) {
                int s2 = s0 + w * 4 + q;
                const float* ep = g_enc_proj + ((size_t)bB * Ssz + s2) * Hd;
                float a = 0.f;
                for (int kk = lane; kk < Hd; kk += 32)
                    a += tanh_fast(sm[HP + kk] + ep[kk]) * sm[VS + kk];
                #pragma unroll
                for (int off = 16; off; off >>= 1) a += __shfl_xor_sync(0xffffffffu, a, off);
                if (!lane) g_scores[bB * Ssz + s2] = a;
            }
        }
        bgen++; grid_bar(1, bgen);

        // ---- phase C ----
        if (tid < 128) sm[SC + tid] = __ldcg(&g_scores[bB * Ssz + tid]);
        __syncthreads();
        float m = -1e30f;
        for (int i2 = 0; i2 < 128; i2++) m = fmaxf(m, sm[SC + i2]);
        __syncthreads();
        if (tid < 128) sm[SC + tid] = expf(sm[SC + tid] - m);
        __syncthreads();
        float ssum = 0.f;
        for (int i2 = 0; i2 < 128; i2++) ssum += sm[SC + i2];
        {
            const float inv = 1.f / ssum;
            const int h0 = (hG & 3) * 128, h = h0 + (tid >> 1), sh = tid & 1;
            const float* eo = g_enc_out + ((size_t)bB * Ssz + (sh << 6)) * Hd + h;
            float a = 0.f;
            #pragma unroll 4
            for (int s2 = 0; s2 < 64; s2++) a += sm[SC + (sh << 6) + s2] * eo[(size_t)s2 * Hd];
            a += __shfl_xor_sync(0xffffffffu, a, 1);
            if (!sh) g_ctx[(bB << 9) + h] = a * inv;
        }
        bgen++; grid_bar(1, bgen);

        // ---- phase D ----
        for (int i = tid; i < 32 * 128; i += 256) {
            int b = i >> 7, k4 = i & 127;
            *(float4*)&sm[HX + b * 516 + k4 * 4] = __ldcg((const float4*)&g_ctx[(b << 9) + k4 * 4]);
        }
        __syncthreads();
        gates_partial(sm, WC, HX, jg, bg, ks, acc);

        #pragma unroll
        for (int jj = 0; jj < 4; jj++)
            #pragma unroll
            for (int bb = 0; bb < 4; bb++)
                sm[RD + ks * 528 + (jj * 4 + jg) * 33 + bb * 8 + bg] = f32x2_sum(acc[jj][bb]);
        __syncthreads();

        if (tid < 128) {
            const int hl = tid >> 5, b = tid & 31;
            float g4[4];
            #pragma unroll
            for (int gate = 0; gate < 4; gate++) {
                int r = gate * 4 + hl;
                float a = 0.f;
                #pragma unroll
                for (int q = 0; q < 8; q++) a += sm[RD + q * 528 + r * 33 + b];
                g4[gate] = a + g_dec_xg[((size_t)t * Bsz + b) * FH + gate * Hd + hG * 4 + hl];
            }
            float cv = sigf(g4[1]) * c_reg + sigf(g4[0]) * tanhf(g4[2]);
            float hn = sigf(g4[3]) * tanhf(cv);
            c_reg = cv;
            hout[(b << 9) + hG * 4 + hl] = hn;
            g_hs[((size_t)b * T1 + t) * Hd + hG * 4 + hl] = hn;
        }
        bgen++; grid_bar(1, bgen);
    }
}

// ---------------- bf16 hi/lo split conversions ----------------
__global__ void conv_hs_kernel() {
    size_t i = ((size_t)blockIdx.x * 256 + threadIdx.x) * 4;
    if (i >= (size_t)MrowsPad * Hd) return;
    float4 x = (i < (size_t)Mrows * Hd) ? *(const float4*)&g_hs[i] : make_float4(0.f, 0.f, 0.f, 0.f);
    float v[4] = {x.x, x.y, x.z, x.w};
    #pragma unroll
    for (int j = 0; j < 4; j++) {
        __nv_bfloat16 hi = __float2bfloat16(v[j]);
        g_hs_hi[i + j] = hi;
        g_hs_lo[i + j] = __float2bfloat16(v[j] - __bfloat162float(hi));
    }
}
__global__ void conv_w_kernel(const float* __restrict__ fc_W) {
    size_t i = ((size_t)blockIdx.x * 256 + threadIdx.x) * 4;
    if (i >= (size_t)Vsz * Hd) return;
    float4 x = *(const float4*)&fc_W[i];
    float v[4] = {x.x, x.y, x.z, x.w};
    #pragma unroll
    for (int j = 0; j < 4; j++) {
        __nv_bfloat16 hi = __float2bfloat16(v[j]);
        g_fcw_hi[i + j] = hi;
        g_fcw_lo[i + j] = __float2bfloat16(v[j] - __bfloat162float(hi));
    }
}

// ---------------- FC GEMM via mma.sync bf16 (hi/lo split), cp.async 2-stage ----------------
#define FC_TS 9216                       // bf16 elems per tile (128*72)
#define FC_STAGE (4 * FC_TS)             // bf16 elems per stage
#define FC_SMEM_BYTES (2 * FC_STAGE * 2) // 147456
__global__ void __launch_bounds__(256, 1) fc_mma_kernel(
    const float* __restrict__ fc_b, float* __restrict__ out)
{
    extern __shared__ __nv_bfloat16 smb[];
    const int tid = threadIdx.x, lane = tid & 31, wid = tid >> 5;
    const int wm = wid & 3, wn = wid >> 2;
    const int m0 = blockIdx.x * 128, n0 = blockIdx.y * 128;
    const uint32_t smem_base = smem_to_u32(smb);

    const __nv_bfloat16* base0 = g_hs_hi  + (size_t)m0 * Hd;
    const __nv_bfloat16* base1 = g_hs_lo  + (size_t)m0 * Hd;
    const __nv_bfloat16* base2 = g_fcw_hi + (size_t)n0 * Hd;
    const __nv_bfloat16* base3 = g_fcw_lo + (size_t)n0 * Hd;

    float acc[2][8][4];
    #pragma unroll
    for (int a = 0; a < 2; a++)
        #pragma unroll
        for (int b = 0; b < 8; b++)
            #pragma unroll
            for (int c = 0; c < 4; c++) acc[a][b][c] = 0.f;

    const int lrow = ((lane >> 3) & 1) * 8 + (lane & 7);
    const int lcol = (lane >> 4) * 8;

    auto issue_stage = [&](int kc, int stg) {
        uint32_t sbase = smem_base + (uint32_t)stg * (FC_STAGE * 2);
        #pragma unroll
        for (int tt = 0; tt < 4; tt++) {
            int idx = tid + tt * 256;
            int r = idx >> 3, c8 = idx & 7;
            uint32_t doff = (uint32_t)(r * 144 + c8 * 16);
            size_t gi = (size_t)r * Hd + kc * 64 + c8 * 8;
            cp_async16(sbase + doff,                    base0 + gi);
            cp_async16(sbase + FC_TS * 2 + doff,        base1 + gi);
            cp_async16(sbase + FC_TS * 4 + doff,        base2 + gi);
            cp_async16(sbase + FC_TS * 6 + doff,        base3 + gi);
        }
        asm volatile("cp.async.commit_group;" ::: "memory");
    };

    issue_stage(0, 0);

    for (int kc = 0; kc < 8; kc++) {
        const int stg = kc & 1;
        if (kc < 7) {
            issue_stage(kc + 1, stg ^ 1);
            asm volatile("cp.async.wait_group 1;" ::: "memory");
        } else {
            asm volatile("cp.async.wait_group 0;" ::: "memory");
        }
        __syncthreads();

        const uint32_t sb = smem_base + (uint32_t)stg * (FC_STAGE * 2);
        #pragma unroll
        for (int kk = 0; kk < 4; kk++) {
            uint32_t ah[2][4], al[2][4];
            #pragma unroll
            for (int mt = 0; mt < 2; mt++) {
                uint32_t off = sb + (uint32_t)(((wm * 32 + mt * 16 + lrow) * 72 + kk * 16 + lcol) * 2);
                ldsm_x4(ah[mt], off);
                ldsm_x4(al[mt], off + FC_TS * 2);
            }
            #pragma unroll
            for (int ng = 0; ng < 4; ng++) {
                uint32_t off = sb + (uint32_t)(((wn * 64 + ng * 16 + lrow) * 72 + kk * 16 + lcol) * 2);
                uint32_t bh[4], bl[4];
                ldsm_x4(bh, off + FC_TS * 4);
                ldsm_x4(bl, off + FC_TS * 6);
                #pragma unroll
                for (int mt = 0; mt < 2; mt++) {
                    mma_bf16(acc[mt][ng * 2],     ah[mt], bh[0], bh[2]);
                    mma_bf16(acc[mt][ng * 2],     ah[mt], bl[0], bl[2]);
                    mma_bf16(acc[mt][ng * 2],     al[mt], bh[0], bh[2]);
                    mma_bf16(acc[mt][ng * 2 + 1], ah[mt], bh[1], bh[3]);
                    mma_bf16(acc[mt][ng * 2 + 1], ah[mt], bl[1], bl[3]);
                    mma_bf16(acc[mt][ng * 2 + 1], al[mt], bh[1], bh[3]);
                }
            }
        }
        __syncthreads();
    }

    const int rbase = m0 + wm * 32 + (lane >> 2);
    const int cbase = n0 + wn * 64 + (lane & 3) * 2;
    #pragma unroll
    for (int mt = 0; mt < 2; mt++)
        #pragma unroll
        for (int nt = 0; nt < 8; nt++) {
            int c = cbase + nt * 8;
            float b0 = fc_b[c], b1 = fc_b[c + 1];
            int r0 = rbase + mt * 16;
            if (r0 < Mrows) {
                float2 v = make_float2(acc[mt][nt][0] + b0, acc[mt][nt][1] + b1);
                *(float2*)&out[(size_t)r0 * Vsz + c] = v;
            }
            int r1 = r0 + 8;
            if (r1 < Mrows) {
                float2 v = make_float2(acc[mt][nt][2] + b0, acc[mt][nt][3] + b1);
                *(float2*)&out[(size_t)r1 * Vsz + c] = v;
            }
        }
}

// ---------------- launch ----------------
extern "C" void kernel_launch(void* const* d_in, const int* in_sizes, int n_in,
                              void* d_out, int out_size)
{
    const int*   src     = (const int*)d_in[0];
    const int*   tgt     = (const int*)d_in[1];
    const float* embed   = (const float*)d_in[2];
    const float* enc_Wih = (const float*)d_in[3];
    const float* enc_Whh = (const float*)d_in[4];
    const float* enc_bih = (const float*)d_in[5];
    const float* enc_bhh = (const float*)d_in[6];
    const float* dec_Wih = (const float*)d_in[7];
    const float* dec_Whh = (const float*)d_in[8];
    const float* dec_bih = (const float*)d_in[9];
    const float* dec_bhh = (const float*)d_in[10];
    const float* attn_W  = (const float*)d_in[11];
    const float* attn_b  = (const float*)d_in[12];
    const float* attn_v  = (const float*)d_in[13];
    const float* fc_W    = (const float*)d_in[14];
    const float* fc_b    = (const float*)d_in[15];
    float* out = (float*)d_out;

    float *p_src_emb, *p_dec_in, *p_enc_xg, *p_dec_xg, *p_enc_out, *p_enc_proj;
    cudaGetSymbolAddress((void**)&p_src_emb,  g_src_emb);
    cudaGetSymbolAddress((void**)&p_dec_in,   g_dec_in);
    cudaGetSymbolAddress((void**)&p_enc_xg,   g_enc_xg);
    cudaGetSymbolAddress((void**)&p_dec_xg,   g_dec_xg);
    cudaGetSymbolAddress((void**)&p_enc_out,  g_enc_out);
    cudaGetSymbolAddress((void**)&p_enc_proj, g_enc_proj);

    cudaFuncSetAttribute(enc_scan_kernel, cudaFuncAttributeMaxDynamicSharedMemorySize, ENC_SMEM_BYTES);
    cudaFuncSetAttribute(dec_scan_kernel, cudaFuncAttributeMaxDynamicSharedMemorySize, DEC_SMEM_BYTES);
    cudaFuncSetAttribute(fc_mma_kernel,  cudaFuncAttributeMaxDynamicSharedMemorySize, FC_SMEM_BYTES);

    init_state_kernel<<<(Bsz * Hd + 255) / 256, 256>>>();
    gather_src_kernel<<<Ssz * Bsz, Ed>>>(src, embed);
    gather_dec_kernel<<<T1 * Bsz, Ed>>>(tgt, embed);

    // fc_W bf16-split (independent; overlaps pipeline head)
    conv_w_kernel<<<(Vsz * Hd / 4 + 255) / 256, 256>>>(fc_W);

    {   // enc_xg
        dim3 grid(FH / 128, (Ssz * Bsz + 127) / 128);
        sgemm_bias_kernel<<<grid, 256>>>(p_src_emb, Ed, enc_Wih, Ed, 0,
                                         enc_bih, enc_bhh, p_enc_xg, Ssz * Bsz, FH);
    }
    {   // dec_xg
        dim3 grid(FH / 128, (T1 * Bsz + 127) / 128);
        sgemm_bias_kernel<<<grid, 256>>>(p_dec_in, Ed, dec_Wih, Ed + Hd, 0,
                                         dec_bih, dec_bhh, p_dec_xg, T1 * Bsz, FH);
    }

    enc_scan_kernel<<<NBLK, 256, ENC_SMEM_BYTES>>>(enc_Whh);

    {   // enc_proj
        dim3 grid(Hd / 128, (Bsz * Ssz + 127) / 128);
        sgemm_bias_kernel<<<grid, 256>>>(p_enc_out, Hd, attn_W, 2 * Hd, Hd,
                                         attn_b, nullptr, p_enc_proj, Bsz * Ssz, Hd);
    }

    dec_scan_kernel<<<NBLK, 256, DEC_SMEM_BYTES>>>(dec_Wih, dec_Whh, attn_W, attn_v);

    conv_hs_kernel<<<(MrowsPad * Hd / 4 + 255) / 256, 256>>>();
    fc_mma_kernel<<<dim3(MrowsPad / 128, Vsz / 128), 256, FC_SMEM_BYTES>>>(fc_b, out);
}

// round 9
// speedup vs baseline: 1.1413x; 1.1413x over previous
#include <cuda_runtime.h>
#include <cuda_bf16.h>
#include <cstddef>
#include <cstdint>

#define Bsz 32
#define Ssz 128
#define Tsz 64
#define T1  63
#define Ed  256
#define Hd  512
#define Vsz 32000
#define FH  2048
#define NBLK 128
#define Mrows 2016       // Bsz*T1
#define MrowsPad 2048

// ---------------- device scratch ----------------
__device__ __align__(16) float g_src_emb[(size_t)Ssz * Bsz * Ed];
__device__ __align__(16) float g_dec_in [(size_t)T1  * Bsz * Ed];
__device__ __align__(16) float g_enc_xg [(size_t)Ssz * Bsz * FH];
__device__ __align__(16) float g_dec_xg [(size_t)T1  * Bsz * FH];
__device__ __align__(16) float g_enc_out[(size_t)Bsz * Ssz * Hd];
__device__ __align__(16) float g_enc_proj[(size_t)Bsz * Ssz * Hd];
__device__ __align__(16) float g_hs     [(size_t)Bsz * T1  * Hd];
__device__ __align__(16) float g_h[2][Bsz * Hd];
__device__ __align__(16) float g_c [Bsz * Hd];
__device__ __align__(16) float g_ctx[Bsz * Hd];
__device__ __align__(16) float g_hproj[Bsz * Hd];
__device__ __align__(16) float g_attp[Bsz][4][516];   // per-part: ctx[512], m@512, l@513
__device__ unsigned g_cnt[2];
__device__ unsigned g_gen[2];
// bf16 hi/lo split operands for the FC tensor GEMM
__device__ __align__(16) __nv_bfloat16 g_hs_hi[(size_t)MrowsPad * Hd];
__device__ __align__(16) __nv_bfloat16 g_hs_lo[(size_t)MrowsPad * Hd];
__device__ __align__(16) __nv_bfloat16 g_fcw_hi[(size_t)Vsz * Hd];
__device__ __align__(16) __nv_bfloat16 g_fcw_lo[(size_t)Vsz * Hd];

__device__ __forceinline__ float sigf(float x) { return 1.0f / (1.0f + expf(-x)); }
__device__ __forceinline__ float tanh_fast(float x) {
    float y;
    asm("tanh.approx.f32 %0, %1;" : "=f"(y) : "f"(x));
    return y;
}

// ---------------- packed f32x2 FMA ----------------
__device__ __forceinline__ void ffma2(unsigned long long& d, unsigned long long a, unsigned long long b) {
    asm("fma.rn.f32x2 %0, %1, %2, %0;" : "+l"(d) : "l"(a), "l"(b));
}
__device__ __forceinline__ float f32x2_sum(unsigned long long v) {
    float lo, hi;
    asm("mov.b64 {%0, %1}, %2;" : "=f"(lo), "=f"(hi) : "l"(v));
    return lo + hi;
}
__device__ __forceinline__ void f32x2_unpack(unsigned long long v, float& lo, float& hi) {
    asm("mov.b64 {%0, %1}, %2;" : "=f"(lo), "=f"(hi) : "l"(v));
}
__device__ __forceinline__ unsigned long long pack2(float lo, float hi) {
    unsigned long long v;
    asm("mov.b64 %0, {%1, %2};" : "=l"(v) : "f"(lo), "f"(hi));
    return v;
}

__device__ __forceinline__ uint32_t smem_to_u32(const void* p) {
    uint32_t a;
    asm("{ .reg .u64 t; cvta.to.shared.u64 t, %1; cvt.u32.u64 %0, t; }" : "=r"(a) : "l"(p));
    return a;
}
__device__ __forceinline__ void ldsm_x4(uint32_t* r, uint32_t addr) {
    asm volatile("ldmatrix.sync.aligned.m8n8.x4.shared.b16 {%0,%1,%2,%3}, [%4];"
        : "=r"(r[0]), "=r"(r[1]), "=r"(r[2]), "=r"(r[3]) : "r"(addr));
}
__device__ __forceinline__ void mma_bf16(float* d, const uint32_t* a, uint32_t b0, uint32_t b1) {
    asm volatile("mma.sync.aligned.m16n8k16.row.col.f32.bf16.bf16.f32 "
        "{%0,%1,%2,%3}, {%4,%5,%6,%7}, {%8,%9}, {%0,%1,%2,%3};"
        : "+f"(d[0]), "+f"(d[1]), "+f"(d[2]), "+f"(d[3])
        : "r"(a[0]), "r"(a[1]), "r"(a[2]), "r"(a[3]), "r"(b0), "r"(b1));
}
__device__ __forceinline__ void cp_async16(uint32_t dst, const void* src) {
    asm volatile("cp.async.cg.shared.global [%0], [%1], 16;" :: "r"(dst), "l"(src) : "memory");
}

// ---------------- global barrier (R7 atomic version — measured fastest) ----------------
__device__ __forceinline__ void grid_bar(int which, unsigned target) {
    __threadfence();
    __syncthreads();
    if (threadIdx.x == 0) {
        unsigned arr = atomicAdd(&g_cnt[which], 1u);
        if (arr == NBLK - 1u) {
            g_cnt[which] = 0u;
            __threadfence();
            atomicAdd(&g_gen[which], 1u);
        } else {
            while (atomicAdd(&g_gen[which], 0u) < target) { }
        }
    }
    __syncthreads();
}

__global__ void init_state_kernel() {
    int i = blockIdx.x * blockDim.x + threadIdx.x;
    if (i < Bsz * Hd) g_h[0][i] = 0.f;
    if (i < 2) { g_cnt[i] = 0u; g_gen[i] = 0u; }
}

// ---------------- embedding gathers ----------------
__global__ void gather_src_kernel(const int* __restrict__ src, const float* __restrict__ embed) {
    int row = blockIdx.x;           // s*B + b
    int s = row >> 5, b = row & 31;
    int idx = src[b * Ssz + s];
    g_src_emb[(size_t)row * Ed + threadIdx.x] = embed[(size_t)idx * Ed + threadIdx.x];
}
__global__ void gather_dec_kernel(const int* __restrict__ tgt, const float* __restrict__ embed) {
    int row = blockIdx.x;           // t*B + b
    int t = row >> 5, b = row & 31;
    int idx = tgt[b * Tsz + t];
    g_dec_in[(size_t)row * Ed + threadIdx.x] = embed[(size_t)idx * Ed + threadIdx.x];
}

// ---------------- fp32 SGEMM with f32x2 FMA (small GEMMs) ----------------
__global__ void __launch_bounds__(256) sgemm_bias_kernel(
    const float* __restrict__ A, int K,
    const float* __restrict__ W, int ldw, int woff,
    const float* __restrict__ b1, const float* __restrict__ b2,
    float* __restrict__ C, int M, int N)
{
    __shared__ __align__(16) float As[8][128];
    __shared__ __align__(16) float Bs[8][128];
    const int bm = blockIdx.y * 128;
    const int bn = blockIdx.x * 128;
    const int t  = threadIdx.x;
    const int tr = (t >> 4) * 8;
    const int tc = (t & 15) * 8;
    const int lr = t >> 1;
    const int lc = (t & 1) * 4;

    unsigned long long acc2[8][4];
    #pragma unroll
    for (int i = 0; i < 8; i++)
        #pragma unroll
        for (int j = 0; j < 4; j++) acc2[i][j] = 0ull;

    const bool aValid = (bm + lr) < M;
    const float* aRow = A + (size_t)(bm + lr) * K + lc;
    const float* wRow = W + (size_t)(bn + lr) * ldw + woff + lc;

    for (int k0 = 0; k0 < K; k0 += 8) {
        float4 av = aValid ? *(const float4*)(aRow + k0) : make_float4(0.f, 0.f, 0.f, 0.f);
        float4 wv = *(const float4*)(wRow + k0);
        As[lc + 0][lr] = av.x; As[lc + 1][lr] = av.y; As[lc + 2][lr] = av.z; As[lc + 3][lr] = av.w;
        Bs[lc + 0][lr] = wv.x; Bs[lc + 1][lr] = wv.y; Bs[lc + 2][lr] = wv.z; Bs[lc + 3][lr] = wv.w;
        __syncthreads();
        #pragma unroll
        for (int kk = 0; kk < 8; kk++) {
            float a[8];
            *(float4*)(a)      = *(const float4*)&As[kk][tr];
            *(float4*)(a + 4)  = *(const float4*)&As[kk][tr + 4];
            unsigned long long bb2[4];
            *(ulonglong2*)&bb2[0] = *(const ulonglong2*)&Bs[kk][tc];
            *(ulonglong2*)&bb2[2] = *(const ulonglong2*)&Bs[kk][tc + 4];
            #pragma unroll
            for (int i = 0; i < 8; i++) {
                unsigned long long ap = pack2(a[i], a[i]);
                #pragma unroll
                for (int j = 0; j < 4; j++) ffma2(acc2[i][j], ap, bb2[j]);
            }
        }
        __syncthreads();
    }

    float bias[8];
    #pragma unroll
    for (int j = 0; j < 8; j++) {
        int n = bn + tc + j;
        bias[j] = b1[n] + (b2 ? b2[n] : 0.f);
    }
    #pragma unroll
    for (int i = 0; i < 8; i++) {
        int m = bm + tr + i;
        if (m >= M) break;
        float* cp = C + (size_t)m * N + bn + tc;
        #pragma unroll
        for (int j = 0; j < 4; j++) {
            float lo, hi;
            f32x2_unpack(acc2[i][j], lo, hi);
            cp[j * 2]     = lo + bias[j * 2];
            cp[j * 2 + 1] = hi + bias[j * 2 + 1];
        }
    }
}

// ---------------- gate partial-GEMM helper (f32x2) ----------------
__device__ __forceinline__ void gates_partial(
    const float* sm, int wbase, int xbase, int jg, int bg, int ks, unsigned long long acc[4][4])
{
    const int k0 = ks * 64;
    #pragma unroll 4
    for (int k4 = 0; k4 < 16; k4++) {
        const int k = k0 + (k4 << 2);
        ulonglong2 wv[4], hv[4];
        #pragma unroll
        for (int jj = 0; jj < 4; jj++)
            wv[jj] = *(const ulonglong2*)&sm[wbase + (jj * 4 + jg) * 516 + k];
        #pragma unroll
        for (int bb = 0; bb < 4; bb++)
            hv[bb] = *(const ulonglong2*)&sm[xbase + (bb * 8 + bg) * 516 + k];
        #pragma unroll
        for (int jj = 0; jj < 4; jj++)
            #pragma unroll
            for (int bb = 0; bb < 4; bb++) {
                ffma2(acc[jj][bb], wv[jj].x, hv[bb].x);
                ffma2(acc[jj][bb], wv[jj].y, hv[bb].y);
            }
    }
}

// ---------------- persistent encoder scan ----------------
#define ENC_SMEM_BYTES (28992 * 4)
__global__ void __launch_bounds__(256, 1) enc_scan_kernel(const float* __restrict__ Whh) {
    extern __shared__ float sm[];
    const int tid = threadIdx.x, hG = blockIdx.x;
    const int W0 = 0, HX = 8256, RD = 24768;

    for (int i = tid; i < 16 * 128; i += 256) {
        int r = i >> 7, k4 = i & 127;
        int j = (r >> 2) * Hd + hG * 4 + (r & 3);
        *(float4*)&sm[W0 + r * 516 + k4 * 4] = *(const float4*)&Whh[(size_t)j * Hd + k4 * 4];
    }

    float c_reg = 0.f;
    const int jg = tid & 3, bg = (tid >> 2) & 7, ks = tid >> 5;
    const int hl = tid >> 5, bq = tid & 31;
    unsigned bgen = 0;

    for (int s = 0; s < Ssz; s++) {
        const float* hin = g_h[s & 1];
        float* hout = g_h[(s + 1) & 1];

        // prefetch xg for this step (overlaps h-load + gates)
        float xg[4];
        if (tid < 128) {
            #pragma unroll
            for (int gate = 0; gate < 4; gate++)
                xg[gate] = __ldcg(&g_enc_xg[((size_t)s * Bsz + bq) * FH + gate * Hd + hG * 4 + hl]);
        }

        for (int i = tid; i < 32 * 128; i += 256) {
            int b = i >> 7, k4 = i & 127;
            *(float4*)&sm[HX + b * 516 + k4 * 4] = __ldcg((const float4*)&hin[(b << 9) + k4 * 4]);
        }
        __syncthreads();

        unsigned long long acc[4][4];
        #pragma unroll
        for (int a = 0; a < 4; a++)
            #pragma unroll
            for (int b2 = 0; b2 < 4; b2++) acc[a][b2] = 0ull;
        gates_partial(sm, W0, HX, jg, bg, ks, acc);

        #pragma unroll
        for (int jj = 0; jj < 4; jj++)
            #pragma unroll
            for (int bb = 0; bb < 4; bb++)
                sm[RD + ks * 528 + (jj * 4 + jg) * 33 + bb * 8 + bg] = f32x2_sum(acc[jj][bb]);
        __syncthreads();

        if (tid < 128) {
            float g4[4];
            #pragma unroll
            for (int gate = 0; gate < 4; gate++) {
                int r = gate * 4 + hl;
                float a = 0.f;
                #pragma unroll
                for (int q = 0; q < 8; q++) a += sm[RD + q * 528 + r * 33 + bq];
                g4[gate] = a + xg[gate];
            }
            float cv = sigf(g4[1]) * c_reg + sigf(g4[0]) * tanhf(g4[2]);
            float hn = sigf(g4[3]) * tanhf(cv);
            c_reg = cv;
            hout[(bq << 9) + hG * 4 + hl] = hn;
            g_enc_out[((size_t)bq * Ssz + s) * Hd + hG * 4 + hl] = hn;
        }
        bgen++;
        grid_bar(0, bgen);
    }
    if (tid < 128) {
        g_c[(bq << 9) + hG * 4 + hl] = c_reg;
    }
}

// ---------------- persistent decoder scan (attention fused, online softmax) ----------------
#define DEC_SMEM_BYTES (40464 * 4)
__global__ void __launch_bounds__(256, 1) dec_scan_kernel(
    const float* __restrict__ Wih, const float* __restrict__ Whh,
    const float* __restrict__ attnW, const float* __restrict__ attnv)
{
    extern __shared__ float sm[];
    const int tid = threadIdx.x, hG = blockIdx.x;
    const int W0 = 0, WC = 8256, WA = 16512, HX = 18576, RD = 35088,
              HP = 39312, VS = 39824, SC = 40336;

    for (int i = tid; i < 16 * 128; i += 256) {
        int r = i >> 7, k4 = i & 127;
        int j = (r >> 2) * Hd + hG * 4 + (r & 3);
        *(float4*)&sm[W0 + r * 516 + k4 * 4] = *(const float4*)&Whh[(size_t)j * Hd + k4 * 4];
        *(float4*)&sm[WC + r * 516 + k4 * 4] = *(const float4*)&Wih[(size_t)j * (Ed + Hd) + Ed + k4 * 4];
    }
    for (int i = tid; i < 4 * 128; i += 256) {
        int r = i >> 7, k4 = i & 127;
        *(float4*)&sm[WA + r * 516 + k4 * 4] = *(const float4*)&attnW[(size_t)(hG * 4 + r) * (2 * Hd) + k4 * 4];
    }
    for (int i = tid; i < Hd; i += 256) sm[VS + i] = attnv[i];

    float c_reg = 0.f;
    const int hl = tid >> 5, bq = tid & 31;
    if (tid < 128) c_reg = __ldcg(&g_c[(bq << 9) + hG * 4 + hl]);

    const int jg = tid & 3, bg = (tid >> 2) & 7, ks = tid >> 5;
    const int bB = hG >> 2;
    const int part = hG & 3;
    unsigned bgen = 0;

    for (int t = 0; t < T1; t++) {
        const float* hin = g_h[t & 1];
        float* hout = g_h[(t + 1) & 1];

        // ---- phase A: load h, hproj, gates h-part ----
        for (int i = tid; i < 32 * 128; i += 256) {
            int b = i >> 7, k4 = i & 127;
            *(float4*)&sm[HX + b * 516 + k4 * 4] = __ldcg((const float4*)&hin[(b << 9) + k4 * 4]);
        }
        __syncthreads();
        {
            const int ko = tid >> 6, bh = (tid >> 1) & 31, kh = tid & 1;
            float a = 0.f;
            const int kb = kh << 8;
            #pragma unroll 4
            for (int k = kb; k < kb + 256; k += 4) {
                float4 w4 = *(const float4*)&sm[WA + ko * 516 + k];
                float4 h4 = *(const float4*)&sm[HX + bh * 516 + k];
                a += w4.x * h4.x + w4.y * h4.y + w4.z * h4.z + w4.w * h4.w;
            }
            a += __shfl_xor_sync(0xffffffffu, a, 1);
            if (!kh) g_hproj[(bh << 9) + hG * 4 + ko] = a;
        }
        unsigned long long acc[4][4];
        #pragma unroll
        for (int a2 = 0; a2 < 4; a2++)
            #pragma unroll
            for (int b2 = 0; b2 < 4; b2++) acc[a2][b2] = 0ull;
        gates_partial(sm, W0, HX, jg, bg, ks, acc);
        bgen++; grid_bar(1, bgen);

        // ---- phase B: attention partials for (bB, 32-s chunk `part`) ----
        for (int i = tid; i < Hd; i += 256) sm[HP + i] = __ldcg(&g_hproj[(bB << 9) + i]);
        __syncthreads();
        {
            const int s0 = part * 32, w = tid >> 5, lane = tid & 31;
            #pragma unroll
            for (int q = 0; q < 4; q++) {
                int sl = w * 4 + q;
                const float* ep = g_enc_proj + ((size_t)bB * Ssz + s0 + sl) * Hd;
                float a = 0.f;
                for (int kk = lane; kk < Hd; kk += 32)
                    a += tanh_fast(sm[HP + kk] + ep[kk]) * sm[VS + kk];
                #pragma unroll
                for (int off = 16; off; off >>= 1) a += __shfl_xor_sync(0xffffffffu, a, off);
                if (!lane) sm[SC + sl] = a;
            }
        }
        __syncthreads();
        {
            float mloc = sm[SC + 0];
            #pragma unroll
            for (int i2 = 1; i2 < 32; i2++) mloc = fmaxf(mloc, sm[SC + i2]);
            if (tid < 32) sm[SC + 32 + tid] = expf(sm[SC + tid] - mloc);
            __syncthreads();
            float lloc = 0.f;
            #pragma unroll
            for (int i2 = 0; i2 < 32; i2++) lloc += sm[SC + 32 + i2];

            // exp-weighted partial context: 256 threads, each 2 h-dims
            const int s0 = part * 32;
            float a0 = 0.f, a1 = 0.f;
            const float* eo = g_enc_out + ((size_t)bB * Ssz + s0) * Hd;
            #pragma unroll 4
            for (int s2 = 0; s2 < 32; s2++) {
                float p = sm[SC + 32 + s2];
                a0 += p * eo[(size_t)s2 * Hd + tid];
                a1 += p * eo[(size_t)s2 * Hd + tid + 256];
            }
            float* ap = g_attp[bB][part];
            ap[tid] = a0;
            ap[tid + 256] = a1;
            if (tid == 0) { ap[512] = mloc; ap[513] = lloc; }
        }
        bgen++; grid_bar(1, bgen);

        // ---- phase C: combine 4 partials -> g_ctx (this block: bB, 128-h chunk) ----
        if (tid < 128) {
            const int h = part * 128 + tid;
            float m0 = __ldcg(&g_attp[bB][0][512]);
            float m1 = __ldcg(&g_attp[bB][1][512]);
            float m2 = __ldcg(&g_attp[bB][2][512]);
            float m3 = __ldcg(&g_attp[bB][3][512]);
            float M = fmaxf(fmaxf(m0, m1), fmaxf(m2, m3));
            float w0 = expf(m0 - M), w1 = expf(m1 - M), w2 = expf(m2 - M), w3 = expf(m3 - M);
            float l = w0 * __ldcg(&g_attp[bB][0][513]) + w1 * __ldcg(&g_attp[bB][1][513])
                    + w2 * __ldcg(&g_attp[bB][2][513]) + w3 * __ldcg(&g_attp[bB][3][513]);
            float cx = w0 * __ldcg(&g_attp[bB][0][h]) + w1 * __ldcg(&g_attp[bB][1][h])
                     + w2 * __ldcg(&g_attp[bB][2][h]) + w3 * __ldcg(&g_attp[bB][3][h]);
            g_ctx[(bB << 9) + h] = cx / l;
        }
        bgen++; grid_bar(1, bgen);

        // ---- phase D: gates ctx-part + pointwise ----
        float xg[4];
        if (tid < 128) {
            #pragma unroll
            for (int gate = 0; gate < 4; gate++)
                xg[gate] = __ldcg(&g_dec_xg[((size_t)t * Bsz + bq) * FH + gate * Hd + hG * 4 + hl]);
        }
        for (int i = tid; i < 32 * 128; i += 256) {
            int b = i >> 7, k4 = i & 127;
            *(float4*)&sm[HX + b * 516 + k4 * 4] = __ldcg((const float4*)&g_ctx[(b << 9) + k4 * 4]);
        }
        __syncthreads();
        gates_partial(sm, WC, HX, jg, bg, ks, acc);

        #pragma unroll
        for (int jj = 0; jj < 4; jj++)
            #pragma unroll
            for (int bb = 0; bb < 4; bb++)
                sm[RD + ks * 528 + (jj * 4 + jg) * 33 + bb * 8 + bg] = f32x2_sum(acc[jj][bb]);
        __syncthreads();

        if (tid < 128) {
            float g4[4];
            #pragma unroll
            for (int gate = 0; gate < 4; gate++) {
                int r = gate * 4 + hl;
                float a = 0.f;
                #pragma unroll
                for (int q = 0; q < 8; q++) a += sm[RD + q * 528 + r * 33 + bq];
                g4[gate] = a + xg[gate];
            }
            float cv = sigf(g4[1]) * c_reg + sigf(g4[0]) * tanhf(g4[2]);
            float hn = sigf(g4[3]) * tanhf(cv);
            c_reg = cv;
            hout[(bq << 9) + hG * 4 + hl] = hn;
            g_hs[((size_t)bq * T1 + t) * Hd + hG * 4 + hl] = hn;
        }
        bgen++; grid_bar(1, bgen);
    }
}

// ---------------- bf16 hi/lo split conversions ----------------
__global__ void conv_hs_kernel() {
    size_t i = ((size_t)blockIdx.x * 256 + threadIdx.x) * 4;
    if (i >= (size_t)MrowsPad * Hd) return;
    float4 x = (i < (size_t)Mrows * Hd) ? *(const float4*)&g_hs[i] : make_float4(0.f, 0.f, 0.f, 0.f);
    float v[4] = {x.x, x.y, x.z, x.w};
    #pragma unroll
    for (int j = 0; j < 4; j++) {
        __nv_bfloat16 hi = __float2bfloat16(v[j]);
        g_hs_hi[i + j] = hi;
        g_hs_lo[i + j] = __float2bfloat16(v[j] - __bfloat162float(hi));
    }
}
__global__ void conv_w_kernel(const float* __restrict__ fc_W) {
    size_t i = ((size_t)blockIdx.x * 256 + threadIdx.x) * 4;
    if (i >= (size_t)Vsz * Hd) return;
    float4 x = *(const float4*)&fc_W[i];
    float v[4] = {x.x, x.y, x.z, x.w};
    #pragma unroll
    for (int j = 0; j < 4; j++) {
        __nv_bfloat16 hi = __float2bfloat16(v[j]);
        g_fcw_hi[i + j] = hi;
        g_fcw_lo[i + j] = __float2bfloat16(v[j] - __bfloat162float(hi));
    }
}

// ---------------- FC GEMM via mma.sync bf16 (hi/lo split), cp.async 2-stage ----------------
#define FC_TS 9216                       // bf16 elems per tile (128*72)
#define FC_STAGE (4 * FC_TS)             // bf16 elems per stage
#define FC_SMEM_BYTES (2 * FC_STAGE * 2) // 147456
__global__ void __launch_bounds__(256, 1) fc_mma_kernel(
    const float* __restrict__ fc_b, float* __restrict__ out)
{
    extern __shared__ __nv_bfloat16 smb[];
    const int tid = threadIdx.x, lane = tid & 31, wid = tid >> 5;
    const int wm = wid & 3, wn = wid >> 2;
    const int m0 = blockIdx.x * 128, n0 = blockIdx.y * 128;
    const uint32_t smem_base = smem_to_u32(smb);

    const __nv_bfloat16* base0 = g_hs_hi  + (size_t)m0 * Hd;
    const __nv_bfloat16* base1 = g_hs_lo  + (size_t)m0 * Hd;
    const __nv_bfloat16* base2 = g_fcw_hi + (size_t)n0 * Hd;
    const __nv_bfloat16* base3 = g_fcw_lo + (size_t)n0 * Hd;

    float acc[2][8][4];
    #pragma unroll
    for (int a = 0; a < 2; a++)
        #pragma unroll
        for (int b = 0; b < 8; b++)
            #pragma unroll
            for (int c = 0; c < 4; c++) acc[a][b][c] = 0.f;

    const int lrow = ((lane >> 3) & 1) * 8 + (lane & 7);
    const int lcol = (lane >> 4) * 8;

    auto issue_stage = [&](int kc, int stg) {
        uint32_t sbase = smem_base + (uint32_t)stg * (FC_STAGE * 2);
        #pragma unroll
        for (int tt = 0; tt < 4; tt++) {
            int idx = tid + tt * 256;
            int r = idx >> 3, c8 = idx & 7;
            uint32_t doff = (uint32_t)(r * 144 + c8 * 16);
            size_t gi = (size_t)r * Hd + kc * 64 + c8 * 8;
            cp_async16(sbase + doff,                    base0 + gi);
            cp_async16(sbase + FC_TS * 2 + doff,        base1 + gi);
            cp_async16(sbase + FC_TS * 4 + doff,        base2 + gi);
            cp_async16(sbase + FC_TS * 6 + doff,        base3 + gi);
        }
        asm volatile("cp.async.commit_group;" ::: "memory");
    };

    issue_stage(0, 0);

    for (int kc = 0; kc < 8; kc++) {
        const int stg = kc & 1;
        if (kc < 7) {
            issue_stage(kc + 1, stg ^ 1);
            asm volatile("cp.async.wait_group 1;" ::: "memory");
        } else {
            asm volatile("cp.async.wait_group 0;" ::: "memory");
        }
        __syncthreads();

        const uint32_t sb = smem_base + (uint32_t)stg * (FC_STAGE * 2);
        #pragma unroll
        for (int kk = 0; kk < 4; kk++) {
            uint32_t ah[2][4], al[2][4];
            #pragma unroll
            for (int mt = 0; mt < 2; mt++) {
                uint32_t off = sb + (uint32_t)(((wm * 32 + mt * 16 + lrow) * 72 + kk * 16 + lcol) * 2);
                ldsm_x4(ah[mt], off);
                ldsm_x4(al[mt], off + FC_TS * 2);
            }
            #pragma unroll
            for (int ng = 0; ng < 4; ng++) {
                uint32_t off = sb + (uint32_t)(((wn * 64 + ng * 16 + lrow) * 72 + kk * 16 + lcol) * 2);
                uint32_t bh[4], bl[4];
                ldsm_x4(bh, off + FC_TS * 4);
                ldsm_x4(bl, off + FC_TS * 6);
                #pragma unroll
                for (int mt = 0; mt < 2; mt++) {
                    mma_bf16(acc[mt][ng * 2],     ah[mt], bh[0], bh[2]);
                    mma_bf16(acc[mt][ng * 2],     ah[mt], bl[0], bl[2]);
                    mma_bf16(acc[mt][ng * 2],     al[mt], bh[0], bh[2]);
                    mma_bf16(acc[mt][ng * 2 + 1], ah[mt], bh[1], bh[3]);
                    mma_bf16(acc[mt][ng * 2 + 1], ah[mt], bl[1], bl[3]);
                    mma_bf16(acc[mt][ng * 2 + 1], al[mt], bh[1], bh[3]);
                }
            }
        }
        __syncthreads();
    }

    const int rbase = m0 + wm * 32 + (lane >> 2);
    const int cbase = n0 + wn * 64 + (lane & 3) * 2;
    #pragma unroll
    for (int mt = 0; mt < 2; mt++)
        #pragma unroll
        for (int nt = 0; nt < 8; nt++) {
            int c = cbase + nt * 8;
            float b0 = fc_b[c], b1 = fc_b[c + 1];
            int r0 = rbase + mt * 16;
            if (r0 < Mrows) {
                float2 v = make_float2(acc[mt][nt][0] + b0, acc[mt][nt][1] + b1);
                *(float2*)&out[(size_t)r0 * Vsz + c] = v;
            }
            int r1 = r0 + 8;
            if (r1 < Mrows) {
                float2 v = make_float2(acc[mt][nt][2] + b0, acc[mt][nt][3] + b1);
                *(float2*)&out[(size_t)r1 * Vsz + c] = v;
            }
        }
}

// ---------------- launch ----------------
extern "C" void kernel_launch(void* const* d_in, const int* in_sizes, int n_in,
                              void* d_out, int out_size)
{
    const int*   src     = (const int*)d_in[0];
    const int*   tgt     = (const int*)d_in[1];
    const float* embed   = (const float*)d_in[2];
    const float* enc_Wih = (const float*)d_in[3];
    const float* enc_Whh = (const float*)d_in[4];
    const float* enc_bih = (const float*)d_in[5];
    const float* enc_bhh = (const float*)d_in[6];
    const float* dec_Wih = (const float*)d_in[7];
    const float* dec_Whh = (const float*)d_in[8];
    const float* dec_bih = (const float*)d_in[9];
    const float* dec_bhh = (const float*)d_in[10];
    const float* attn_W  = (const float*)d_in[11];
    const float* attn_b  = (const float*)d_in[12];
    const float* attn_v  = (const float*)d_in[13];
    const float* fc_W    = (const float*)d_in[14];
    const float* fc_b    = (const float*)d_in[15];
    float* out = (float*)d_out;

    float *p_src_emb, *p_dec_in, *p_enc_xg, *p_dec_xg, *p_enc_out, *p_enc_proj;
    cudaGetSymbolAddress((void**)&p_src_emb,  g_src_emb);
    cudaGetSymbolAddress((void**)&p_dec_in,   g_dec_in);
    cudaGetSymbolAddress((void**)&p_enc_xg,   g_enc_xg);
    cudaGetSymbolAddress((void**)&p_dec_xg,   g_dec_xg);
    cudaGetSymbolAddress((void**)&p_enc_out,  g_enc_out);
    cudaGetSymbolAddress((void**)&p_enc_proj, g_enc_proj);

    cudaFuncSetAttribute(enc_scan_kernel, cudaFuncAttributeMaxDynamicSharedMemorySize, ENC_SMEM_BYTES);
    cudaFuncSetAttribute(dec_scan_kernel, cudaFuncAttributeMaxDynamicSharedMemorySize, DEC_SMEM_BYTES);
    cudaFuncSetAttribute(fc_mma_kernel,  cudaFuncAttributeMaxDynamicSharedMemorySize, FC_SMEM_BYTES);

    init_state_kernel<<<(Bsz * Hd + 255) / 256, 256>>>();
    gather_src_kernel<<<Ssz * Bsz, Ed>>>(src, embed);
    gather_dec_kernel<<<T1 * Bsz, Ed>>>(tgt, embed);

    // fc_W bf16-split (independent; overlaps pipeline head)
    conv_w_kernel<<<(Vsz * Hd / 4 + 255) / 256, 256>>>(fc_W);

    {   // enc_xg
        dim3 grid(FH / 128, (Ssz * Bsz + 127) / 128);
        sgemm_bias_kernel<<<grid, 256>>>(p_src_emb, Ed, enc_Wih, Ed, 0,
                                         enc_bih, enc_bhh, p_enc_xg, Ssz * Bsz, FH);
    }
    {   // dec_xg
        dim3 grid(FH / 128, (T1 * Bsz + 127) / 128);
        sgemm_bias_kernel<<<grid, 256>>>(p_dec_in, Ed, dec_Wih, Ed + Hd, 0,
                                         dec_bih, dec_bhh, p_dec_xg, T1 * Bsz, FH);
    }

    enc_scan_kernel<<<NBLK, 256, ENC_SMEM_BYTES>>>(enc_Whh);

    {   // enc_proj
        dim3 grid(Hd / 128, (Bsz * Ssz + 127) / 128);
        sgemm_bias_kernel<<<grid, 256>>>(p_enc_out, Hd, attn_W, 2 * Hd, Hd,
                                         attn_b, nullptr, p_enc_proj, Bsz * Ssz, Hd);
    }

    dec_scan_kernel<<<NBLK, 256, DEC_SMEM_BYTES>>>(dec_Wih, dec_Whh, attn_W, attn_v);

    conv_hs_kernel<<<(MrowsPad * Hd / 4 + 255) / 256, 256>>>();
    fc_mma_kernel<<<dim3(MrowsPad / 128, Vsz / 128), 256, FC_SMEM_BYTES>>>(fc_b, out);
}

// round 10
// speedup vs baseline: 1.1448x; 1.0031x over previous
#include <cuda_runtime.h>
#include <cuda_bf16.h>
#include <cstddef>
#include <cstdint>

#define Bsz 32
#define Ssz 128
#define Tsz 64
#define T1  63
#define Ed  256
#define Hd  512
#define Vsz 32000
#define FH  2048
#define NBLK 128
#define Mrows 2016       // Bsz*T1
#define MrowsPad 2048

// ---------------- device scratch ----------------
__device__ __align__(16) float g_src_emb[(size_t)Ssz * Bsz * Ed];
__device__ __align__(16) float g_dec_in [(size_t)T1  * Bsz * Ed];
__device__ __align__(16) float g_enc_xg [(size_t)Ssz * Bsz * FH];
__device__ __align__(16) float g_dec_xg [(size_t)T1  * Bsz * FH];
__device__ __align__(16) float g_enc_out[(size_t)Bsz * Ssz * Hd];
__device__ __align__(16) float g_enc_proj[(size_t)Bsz * Ssz * Hd];
__device__ __align__(16) float g_hs     [(size_t)Bsz * T1  * Hd];
__device__ __align__(16) float g_h[2][Bsz * Hd];
__device__ __align__(16) float g_c [Bsz * Hd];
__device__ __align__(16) float g_ctx[Bsz * Hd];
__device__ __align__(16) float g_hproj[Bsz * Hd];
__device__ __align__(16) float g_attp[Bsz][4][516];   // per-part: ctx[512], m@512, l@513
__device__ unsigned g_cnt[2];
__device__ unsigned g_gen[2];
// bf16 hi/lo split operands for the FC tensor GEMM
__device__ __align__(16) __nv_bfloat16 g_hs_hi[(size_t)MrowsPad * Hd];
__device__ __align__(16) __nv_bfloat16 g_hs_lo[(size_t)MrowsPad * Hd];
__device__ __align__(16) __nv_bfloat16 g_fcw_hi[(size_t)Vsz * Hd];
__device__ __align__(16) __nv_bfloat16 g_fcw_lo[(size_t)Vsz * Hd];

__device__ __forceinline__ float sigf(float x) { return 1.0f / (1.0f + expf(-x)); }
__device__ __forceinline__ float tanh_fast(float x) {
    float y;
    asm("tanh.approx.f32 %0, %1;" : "=f"(y) : "f"(x));
    return y;
}

// ---------------- packed f32x2 FMA ----------------
__device__ __forceinline__ void ffma2(unsigned long long& d, unsigned long long a, unsigned long long b) {
    asm("fma.rn.f32x2 %0, %1, %2, %0;" : "+l"(d) : "l"(a), "l"(b));
}
__device__ __forceinline__ float f32x2_sum(unsigned long long v) {
    float lo, hi;
    asm("mov.b64 {%0, %1}, %2;" : "=f"(lo), "=f"(hi) : "l"(v));
    return lo + hi;
}
__device__ __forceinline__ void f32x2_unpack(unsigned long long v, float& lo, float& hi) {
    asm("mov.b64 {%0, %1}, %2;" : "=f"(lo), "=f"(hi) : "l"(v));
}
__device__ __forceinline__ unsigned long long pack2(float lo, float hi) {
    unsigned long long v;
    asm("mov.b64 %0, {%1, %2};" : "=l"(v) : "f"(lo), "f"(hi));
    return v;
}

__device__ __forceinline__ uint32_t smem_to_u32(const void* p) {
    uint32_t a;
    asm("{ .reg .u64 t; cvta.to.shared.u64 t, %1; cvt.u32.u64 %0, t; }" : "=r"(a) : "l"(p));
    return a;
}
__device__ __forceinline__ void ldsm_x4(uint32_t* r, uint32_t addr) {
    asm volatile("ldmatrix.sync.aligned.m8n8.x4.shared.b16 {%0,%1,%2,%3}, [%4];"
        : "=r"(r[0]), "=r"(r[1]), "=r"(r[2]), "=r"(r[3]) : "r"(addr));
}
__device__ __forceinline__ void mma_bf16(float* d, const uint32_t* a, uint32_t b0, uint32_t b1) {
    asm volatile("mma.sync.aligned.m16n8k16.row.col.f32.bf16.bf16.f32 "
        "{%0,%1,%2,%3}, {%4,%5,%6,%7}, {%8,%9}, {%0,%1,%2,%3};"
        : "+f"(d[0]), "+f"(d[1]), "+f"(d[2]), "+f"(d[3])
        : "r"(a[0]), "r"(a[1]), "r"(a[2]), "r"(a[3]), "r"(b0), "r"(b1));
}
__device__ __forceinline__ void cp_async16(uint32_t dst, const void* src) {
    asm volatile("cp.async.cg.shared.global [%0], [%1], 16;" :: "r"(dst), "l"(src) : "memory");
}

// ---------------- global barrier (R7 atomic version — measured fastest) ----------------
__device__ __forceinline__ void grid_bar(int which, unsigned target) {
    __threadfence();
    __syncthreads();
    if (threadIdx.x == 0) {
        unsigned arr = atomicAdd(&g_cnt[which], 1u);
        if (arr == NBLK - 1u) {
            g_cnt[which] = 0u;
            __threadfence();
            atomicAdd(&g_gen[which], 1u);
        } else {
            while (atomicAdd(&g_gen[which], 0u) < target) { }
        }
    }
    __syncthreads();
}

__global__ void init_state_kernel() {
    int i = blockIdx.x * blockDim.x + threadIdx.x;
    if (i < Bsz * Hd) g_h[0][i] = 0.f;
    if (i < 2) { g_cnt[i] = 0u; g_gen[i] = 0u; }
}

// ---------------- embedding gathers ----------------
__global__ void gather_src_kernel(const int* __restrict__ src, const float* __restrict__ embed) {
    int row = blockIdx.x;           // s*B + b
    int s = row >> 5, b = row & 31;
    int idx = src[b * Ssz + s];
    g_src_emb[(size_t)row * Ed + threadIdx.x] = embed[(size_t)idx * Ed + threadIdx.x];
}
__global__ void gather_dec_kernel(const int* __restrict__ tgt, const float* __restrict__ embed) {
    int row = blockIdx.x;           // t*B + b
    int t = row >> 5, b = row & 31;
    int idx = tgt[b * Tsz + t];
    g_dec_in[(size_t)row * Ed + threadIdx.x] = embed[(size_t)idx * Ed + threadIdx.x];
}

// ---------------- fp32 SGEMM with f32x2 FMA (small GEMMs) ----------------
__global__ void __launch_bounds__(256) sgemm_bias_kernel(
    const float* __restrict__ A, int K,
    const float* __restrict__ W, int ldw, int woff,
    const float* __restrict__ b1, const float* __restrict__ b2,
    float* __restrict__ C, int M, int N)
{
    __shared__ __align__(16) float As[8][128];
    __shared__ __align__(16) float Bs[8][128];
    const int bm = blockIdx.y * 128;
    const int bn = blockIdx.x * 128;
    const int t  = threadIdx.x;
    const int tr = (t >> 4) * 8;
    const int tc = (t & 15) * 8;
    const int lr = t >> 1;
    const int lc = (t & 1) * 4;

    unsigned long long acc2[8][4];
    #pragma unroll
    for (int i = 0; i < 8; i++)
        #pragma unroll
        for (int j = 0; j < 4; j++) acc2[i][j] = 0ull;

    const bool aValid = (bm + lr) < M;
    const float* aRow = A + (size_t)(bm + lr) * K + lc;
    const float* wRow = W + (size_t)(bn + lr) * ldw + woff + lc;

    for (int k0 = 0; k0 < K; k0 += 8) {
        float4 av = aValid ? *(const float4*)(aRow + k0) : make_float4(0.f, 0.f, 0.f, 0.f);
        float4 wv = *(const float4*)(wRow + k0);
        As[lc + 0][lr] = av.x; As[lc + 1][lr] = av.y; As[lc + 2][lr] = av.z; As[lc + 3][lr] = av.w;
        Bs[lc + 0][lr] = wv.x; Bs[lc + 1][lr] = wv.y; Bs[lc + 2][lr] = wv.z; Bs[lc + 3][lr] = wv.w;
        __syncthreads();
        #pragma unroll
        for (int kk = 0; kk < 8; kk++) {
            float a[8];
            *(float4*)(a)      = *(const float4*)&As[kk][tr];
            *(float4*)(a + 4)  = *(const float4*)&As[kk][tr + 4];
            unsigned long long bb2[4];
            *(ulonglong2*)&bb2[0] = *(const ulonglong2*)&Bs[kk][tc];
            *(ulonglong2*)&bb2[2] = *(const ulonglong2*)&Bs[kk][tc + 4];
            #pragma unroll
            for (int i = 0; i < 8; i++) {
                unsigned long long ap = pack2(a[i], a[i]);
                #pragma unroll
                for (int j = 0; j < 4; j++) ffma2(acc2[i][j], ap, bb2[j]);
            }
        }
        __syncthreads();
    }

    float bias[8];
    #pragma unroll
    for (int j = 0; j < 8; j++) {
        int n = bn + tc + j;
        bias[j] = b1[n] + (b2 ? b2[n] : 0.f);
    }
    #pragma unroll
    for (int i = 0; i < 8; i++) {
        int m = bm + tr + i;
        if (m >= M) break;
        float* cp = C + (size_t)m * N + bn + tc;
        #pragma unroll
        for (int j = 0; j < 4; j++) {
            float lo, hi;
            f32x2_unpack(acc2[i][j], lo, hi);
            cp[j * 2]     = lo + bias[j * 2];
            cp[j * 2 + 1] = hi + bias[j * 2 + 1];
        }
    }
}

// ---------------- gate partial-GEMM helper (f32x2) ----------------
__device__ __forceinline__ void gates_partial(
    const float* sm, int wbase, int xbase, int jg, int bg, int ks, unsigned long long acc[4][4])
{
    const int k0 = ks * 64;
    #pragma unroll 4
    for (int k4 = 0; k4 < 16; k4++) {
        const int k = k0 + (k4 << 2);
        ulonglong2 wv[4], hv[4];
        #pragma unroll
        for (int jj = 0; jj < 4; jj++)
            wv[jj] = *(const ulonglong2*)&sm[wbase + (jj * 4 + jg) * 516 + k];
        #pragma unroll
        for (int bb = 0; bb < 4; bb++)
            hv[bb] = *(const ulonglong2*)&sm[xbase + (bb * 8 + bg) * 516 + k];
        #pragma unroll
        for (int jj = 0; jj < 4; jj++)
            #pragma unroll
            for (int bb = 0; bb < 4; bb++) {
                ffma2(acc[jj][bb], wv[jj].x, hv[bb].x);
                ffma2(acc[jj][bb], wv[jj].y, hv[bb].y);
            }
    }
}

// ---------------- persistent encoder scan ----------------
#define ENC_SMEM_BYTES (28992 * 4)
__global__ void __launch_bounds__(256, 1) enc_scan_kernel(const float* __restrict__ Whh) {
    extern __shared__ float sm[];
    const int tid = threadIdx.x, hG = blockIdx.x;
    const int W0 = 0, HX = 8256, RD = 24768;

    for (int i = tid; i < 16 * 128; i += 256) {
        int r = i >> 7, k4 = i & 127;
        int j = (r >> 2) * Hd + hG * 4 + (r & 3);
        *(float4*)&sm[W0 + r * 516 + k4 * 4] = *(const float4*)&Whh[(size_t)j * Hd + k4 * 4];
    }

    float c_reg = 0.f;
    const int jg = tid & 3, bg = (tid >> 2) & 7, ks = tid >> 5;
    const int hl = tid >> 5, bq = tid & 31;
    unsigned bgen = 0;

    for (int s = 0; s < Ssz; s++) {
        const float* hin = g_h[s & 1];
        float* hout = g_h[(s + 1) & 1];

        float xg[4];
        if (tid < 128) {
            #pragma unroll
            for (int gate = 0; gate < 4; gate++)
                xg[gate] = __ldcg(&g_enc_xg[((size_t)s * Bsz + bq) * FH + gate * Hd + hG * 4 + hl]);
        }

        for (int i = tid; i < 32 * 128; i += 256) {
            int b = i >> 7, k4 = i & 127;
            *(float4*)&sm[HX + b * 516 + k4 * 4] = __ldcg((const float4*)&hin[(b << 9) + k4 * 4]);
        }
        __syncthreads();

        unsigned long long acc[4][4];
        #pragma unroll
        for (int a = 0; a < 4; a++)
            #pragma unroll
            for (int b2 = 0; b2 < 4; b2++) acc[a][b2] = 0ull;
        gates_partial(sm, W0, HX, jg, bg, ks, acc);

        #pragma unroll
        for (int jj = 0; jj < 4; jj++)
            #pragma unroll
            for (int bb = 0; bb < 4; bb++)
                sm[RD + ks * 528 + (jj * 4 + jg) * 33 + bb * 8 + bg] = f32x2_sum(acc[jj][bb]);
        __syncthreads();

        if (tid < 128) {
            float g4[4];
            #pragma unroll
            for (int gate = 0; gate < 4; gate++) {
                int r = gate * 4 + hl;
                float a = 0.f;
                #pragma unroll
                for (int q = 0; q < 8; q++) a += sm[RD + q * 528 + r * 33 + bq];
                g4[gate] = a + xg[gate];
            }
            float cv = sigf(g4[1]) * c_reg + sigf(g4[0]) * tanhf(g4[2]);
            float hn = sigf(g4[3]) * tanhf(cv);
            c_reg = cv;
            hout[(bq << 9) + hG * 4 + hl] = hn;
            g_enc_out[((size_t)bq * Ssz + s) * Hd + hG * 4 + hl] = hn;
        }
        bgen++;
        grid_bar(0, bgen);
    }
    if (tid < 128) {
        g_c[(bq << 9) + hG * 4 + hl] = c_reg;
    }
}

// ---------------- persistent decoder scan (attention fused, online softmax) ----------------
#define DEC_SMEM_BYTES (40464 * 4)
__global__ void __launch_bounds__(256, 1) dec_scan_kernel(
    const float* __restrict__ Wih, const float* __restrict__ Whh,
    const float* __restrict__ attnW, const float* __restrict__ attnv)
{
    extern __shared__ float sm[];
    const int tid = threadIdx.x, hG = blockIdx.x;
    const int W0 = 0, WC = 8256, WA = 16512, HX = 18576, RD = 35088,
              HP = 39312, VS = 39824, SC = 40336;

    for (int i = tid; i < 16 * 128; i += 256) {
        int r = i >> 7, k4 = i & 127;
        int j = (r >> 2) * Hd + hG * 4 + (r & 3);
        *(float4*)&sm[W0 + r * 516 + k4 * 4] = *(const float4*)&Whh[(size_t)j * Hd + k4 * 4];
        *(float4*)&sm[WC + r * 516 + k4 * 4] = *(const float4*)&Wih[(size_t)j * (Ed + Hd) + Ed + k4 * 4];
    }
    for (int i = tid; i < 4 * 128; i += 256) {
        int r = i >> 7, k4 = i & 127;
        *(float4*)&sm[WA + r * 516 + k4 * 4] = *(const float4*)&attnW[(size_t)(hG * 4 + r) * (2 * Hd) + k4 * 4];
    }
    for (int i = tid; i < Hd; i += 256) sm[VS + i] = attnv[i];

    float c_reg = 0.f;
    const int hl = tid >> 5, bq = tid & 31;
    if (tid < 128) c_reg = __ldcg(&g_c[(bq << 9) + hG * 4 + hl]);

    const int jg = tid & 3, bg = (tid >> 2) & 7, ks = tid >> 5;
    const int bB = hG >> 2;
    const int part = hG & 3;
    unsigned bgen = 0;

    for (int t = 0; t < T1; t++) {
        const float* hin = g_h[t & 1];
        float* hout = g_h[(t + 1) & 1];

        // ---- phase A: load h, hproj, gates h-part ----
        for (int i = tid; i < 32 * 128; i += 256) {
            int b = i >> 7, k4 = i & 127;
            *(float4*)&sm[HX + b * 516 + k4 * 4] = __ldcg((const float4*)&hin[(b << 9) + k4 * 4]);
        }
        __syncthreads();
        {
            const int ko = tid >> 6, bh = (tid >> 1) & 31, kh = tid & 1;
            float a = 0.f;
            const int kb = kh << 8;
            #pragma unroll 4
            for (int k = kb; k < kb + 256; k += 4) {
                float4 w4 = *(const float4*)&sm[WA + ko * 516 + k];
                float4 h4 = *(const float4*)&sm[HX + bh * 516 + k];
                a += w4.x * h4.x + w4.y * h4.y + w4.z * h4.z + w4.w * h4.w;
            }
            a += __shfl_xor_sync(0xffffffffu, a, 1);
            if (!kh) g_hproj[(bh << 9) + hG * 4 + ko] = a;
        }
        unsigned long long acc[4][4];
        #pragma unroll
        for (int a2 = 0; a2 < 4; a2++)
            #pragma unroll
            for (int b2 = 0; b2 < 4; b2++) acc[a2][b2] = 0ull;
        gates_partial(sm, W0, HX, jg, bg, ks, acc);
        bgen++; grid_bar(1, bgen);

        // ---- phase B: attention partials for (bB, 32-s chunk `part`) ----
        for (int i = tid; i < Hd; i += 256) sm[HP + i] = __ldcg(&g_hproj[(bB << 9) + i]);
        __syncthreads();
        {
            const int s0 = part * 32, w = tid >> 5, lane = tid & 31;
            #pragma unroll
            for (int q = 0; q < 4; q++) {
                int sl = w * 4 + q;
                const float* ep = g_enc_proj + ((size_t)bB * Ssz + s0 + sl) * Hd;
                float a = 0.f;
                for (int kk = lane; kk < Hd; kk += 32)
                    a += tanh_fast(sm[HP + kk] + ep[kk]) * sm[VS + kk];
                #pragma unroll
                for (int off = 16; off; off >>= 1) a += __shfl_xor_sync(0xffffffffu, a, off);
                if (!lane) sm[SC + sl] = a;
            }
        }
        __syncthreads();
        {
            float mloc = sm[SC + 0];
            #pragma unroll
            for (int i2 = 1; i2 < 32; i2++) mloc = fmaxf(mloc, sm[SC + i2]);
            if (tid < 32) sm[SC + 32 + tid] = expf(sm[SC + tid] - mloc);
            __syncthreads();
            float lloc = 0.f;
            #pragma unroll
            for (int i2 = 0; i2 < 32; i2++) lloc += sm[SC + 32 + i2];

            const int s0 = part * 32;
            float a0 = 0.f, a1 = 0.f;
            const float* eo = g_enc_out + ((size_t)bB * Ssz + s0) * Hd;
            #pragma unroll 4
            for (int s2 = 0; s2 < 32; s2++) {
                float p = sm[SC + 32 + s2];
                a0 += p * eo[(size_t)s2 * Hd + tid];
                a1 += p * eo[(size_t)s2 * Hd + tid + 256];
            }
            float* ap = g_attp[bB][part];
            ap[tid] = a0;
            ap[tid + 256] = a1;
            if (tid == 0) { ap[512] = mloc; ap[513] = lloc; }
        }
        bgen++; grid_bar(1, bgen);

        // ---- phase C: combine 4 partials -> g_ctx ----
        if (tid < 128) {
            const int h = part * 128 + tid;
            float m0 = __ldcg(&g_attp[bB][0][512]);
            float m1 = __ldcg(&g_attp[bB][1][512]);
            float m2 = __ldcg(&g_attp[bB][2][512]);
            float m3 = __ldcg(&g_attp[bB][3][512]);
            float M = fmaxf(fmaxf(m0, m1), fmaxf(m2, m3));
            float w0 = expf(m0 - M), w1 = expf(m1 - M), w2 = expf(m2 - M), w3 = expf(m3 - M);
            float l = w0 * __ldcg(&g_attp[bB][0][513]) + w1 * __ldcg(&g_attp[bB][1][513])
                    + w2 * __ldcg(&g_attp[bB][2][513]) + w3 * __ldcg(&g_attp[bB][3][513]);
            float cx = w0 * __ldcg(&g_attp[bB][0][h]) + w1 * __ldcg(&g_attp[bB][1][h])
                     + w2 * __ldcg(&g_attp[bB][2][h]) + w3 * __ldcg(&g_attp[bB][3][h]);
            g_ctx[(bB << 9) + h] = cx / l;
        }
        bgen++; grid_bar(1, bgen);

        // ---- phase D: gates ctx-part + pointwise ----
        float xg[4];
        if (tid < 128) {
            #pragma unroll
            for (int gate = 0; gate < 4; gate++)
                xg[gate] = __ldcg(&g_dec_xg[((size_t)t * Bsz + bq) * FH + gate * Hd + hG * 4 + hl]);
        }
        for (int i = tid; i < 32 * 128; i += 256) {
            int b = i >> 7, k4 = i & 127;
            *(float4*)&sm[HX + b * 516 + k4 * 4] = __ldcg((const float4*)&g_ctx[(b << 9) + k4 * 4]);
        }
        __syncthreads();
        gates_partial(sm, WC, HX, jg, bg, ks, acc);

        #pragma unroll
        for (int jj = 0; jj < 4; jj++)
            #pragma unroll
            for (int bb = 0; bb < 4; bb++)
                sm[RD + ks * 528 + (jj * 4 + jg) * 33 + bb * 8 + bg] = f32x2_sum(acc[jj][bb]);
        __syncthreads();

        if (tid < 128) {
            float g4[4];
            #pragma unroll
            for (int gate = 0; gate < 4; gate++) {
                int r = gate * 4 + hl;
                float a = 0.f;
                #pragma unroll
                for (int q = 0; q < 8; q++) a += sm[RD + q * 528 + r * 33 + bq];
                g4[gate] = a + xg[gate];
            }
            float cv = sigf(g4[1]) * c_reg + sigf(g4[0]) * tanhf(g4[2]);
            float hn = sigf(g4[3]) * tanhf(cv);
            c_reg = cv;
            hout[(bq << 9) + hG * 4 + hl] = hn;
            g_hs[((size_t)bq * T1 + t) * Hd + hG * 4 + hl] = hn;
        }
        bgen++; grid_bar(1, bgen);
    }
}

// ---------------- bf16 hi/lo split conversions ----------------
__global__ void conv_hs_kernel() {
    size_t i = ((size_t)blockIdx.x * 256 + threadIdx.x) * 4;
    if (i >= (size_t)MrowsPad * Hd) return;
    float4 x = (i < (size_t)Mrows * Hd) ? *(const float4*)&g_hs[i] : make_float4(0.f, 0.f, 0.f, 0.f);
    float v[4] = {x.x, x.y, x.z, x.w};
    #pragma unroll
    for (int j = 0; j < 4; j++) {
        __nv_bfloat16 hi = __float2bfloat16(v[j]);
        g_hs_hi[i + j] = hi;
        g_hs_lo[i + j] = __float2bfloat16(v[j] - __bfloat162float(hi));
    }
}
__global__ void conv_w_kernel(const float* __restrict__ fc_W) {
    size_t i = ((size_t)blockIdx.x * 256 + threadIdx.x) * 4;
    if (i >= (size_t)Vsz * Hd) return;
    float4 x = *(const float4*)&fc_W[i];
    float v[4] = {x.x, x.y, x.z, x.w};
    #pragma unroll
    for (int j = 0; j < 4; j++) {
        __nv_bfloat16 hi = __float2bfloat16(v[j]);
        g_fcw_hi[i + j] = hi;
        g_fcw_lo[i + j] = __float2bfloat16(v[j] - __bfloat162float(hi));
    }
}

// ---------------- FC GEMM via mma.sync bf16 (hi/lo split), cp.async 2-stage ----------------
// Pass-reordered: all main-products first, then each correction pass, so
// same-accumulator MMAs are spaced 16 independent MMAs apart (hide RAW latency).
#define FC_TS 9216                       // bf16 elems per tile (128*72)
#define FC_STAGE (4 * FC_TS)             // bf16 elems per stage
#define FC_SMEM_BYTES (2 * FC_STAGE * 2) // 147456
__global__ void __launch_bounds__(256, 1) fc_mma_kernel(
    const float* __restrict__ fc_b, float* __restrict__ out)
{
    extern __shared__ __nv_bfloat16 smb[];
    const int tid = threadIdx.x, lane = tid & 31, wid = tid >> 5;
    const int wm = wid & 3, wn = wid >> 2;
    const int m0 = blockIdx.x * 128, n0 = blockIdx.y * 128;
    const uint32_t smem_base = smem_to_u32(smb);

    const __nv_bfloat16* base0 = g_hs_hi  + (size_t)m0 * Hd;
    const __nv_bfloat16* base1 = g_hs_lo  + (size_t)m0 * Hd;
    const __nv_bfloat16* base2 = g_fcw_hi + (size_t)n0 * Hd;
    const __nv_bfloat16* base3 = g_fcw_lo + (size_t)n0 * Hd;

    float acc[2][8][4];
    #pragma unroll
    for (int a = 0; a < 2; a++)
        #pragma unroll
        for (int b = 0; b < 8; b++)
            #pragma unroll
            for (int c = 0; c < 4; c++) acc[a][b][c] = 0.f;

    const int lrow = ((lane >> 3) & 1) * 8 + (lane & 7);
    const int lcol = (lane >> 4) * 8;

    auto issue_stage = [&](int kc, int stg) {
        uint32_t sbase = smem_base + (uint32_t)stg * (FC_STAGE * 2);
        #pragma unroll
        for (int tt = 0; tt < 4; tt++) {
            int idx = tid + tt * 256;
            int r = idx >> 3, c8 = idx & 7;
            uint32_t doff = (uint32_t)(r * 144 + c8 * 16);
            size_t gi = (size_t)r * Hd + kc * 64 + c8 * 8;
            cp_async16(sbase + doff,                    base0 + gi);
            cp_async16(sbase + FC_TS * 2 + doff,        base1 + gi);
            cp_async16(sbase + FC_TS * 4 + doff,        base2 + gi);
            cp_async16(sbase + FC_TS * 6 + doff,        base3 + gi);
        }
        asm volatile("cp.async.commit_group;" ::: "memory");
    };

    issue_stage(0, 0);

    for (int kc = 0; kc < 8; kc++) {
        const int stg = kc & 1;
        if (kc < 7) {
            issue_stage(kc + 1, stg ^ 1);
            asm volatile("cp.async.wait_group 1;" ::: "memory");
        } else {
            asm volatile("cp.async.wait_group 0;" ::: "memory");
        }
        __syncthreads();

        const uint32_t sb = smem_base + (uint32_t)stg * (FC_STAGE * 2);
        #pragma unroll
        for (int kk = 0; kk < 4; kk++) {
            uint32_t ah[2][4], al[2][4], bh[4][4], bl[4][4];
            #pragma unroll
            for (int mt = 0; mt < 2; mt++) {
                uint32_t off = sb + (uint32_t)(((wm * 32 + mt * 16 + lrow) * 72 + kk * 16 + lcol) * 2);
                ldsm_x4(ah[mt], off);
                ldsm_x4(al[mt], off + FC_TS * 2);
            }
            #pragma unroll
            for (int ng = 0; ng < 4; ng++) {
                uint32_t off = sb + (uint32_t)(((wn * 64 + ng * 16 + lrow) * 72 + kk * 16 + lcol) * 2);
                ldsm_x4(bh[ng], off + FC_TS * 4);
                ldsm_x4(bl[ng], off + FC_TS * 6);
            }
            // pass 1: main Ah*Bh (16 independent MMAs)
            #pragma unroll
            for (int mt = 0; mt < 2; mt++)
                #pragma unroll
                for (int ng = 0; ng < 4; ng++) {
                    mma_bf16(acc[mt][ng * 2],     ah[mt], bh[ng][0], bh[ng][2]);
                    mma_bf16(acc[mt][ng * 2 + 1], ah[mt], bh[ng][1], bh[ng][3]);
                }
            // pass 2: Ah*Bl correction
            #pragma unroll
            for (int mt = 0; mt < 2; mt++)
                #pragma unroll
                for (int ng = 0; ng < 4; ng++) {
                    mma_bf16(acc[mt][ng * 2],     ah[mt], bl[ng][0], bl[ng][2]);
                    mma_bf16(acc[mt][ng * 2 + 1], ah[mt], bl[ng][1], bl[ng][3]);
                }
            // pass 3: Al*Bh correction
            #pragma unroll
            for (int mt = 0; mt < 2; mt++)
                #pragma unroll
                for (int ng = 0; ng < 4; ng++) {
                    mma_bf16(acc[mt][ng * 2],     al[mt], bh[ng][0], bh[ng][2]);
                    mma_bf16(acc[mt][ng * 2 + 1], al[mt], bh[ng][1], bh[ng][3]);
                }
        }
        __syncthreads();
    }

    const int rbase = m0 + wm * 32 + (lane >> 2);
    const int cbase = n0 + wn * 64 + (lane & 3) * 2;
    #pragma unroll
    for (int mt = 0; mt < 2; mt++)
        #pragma unroll
        for (int nt = 0; nt < 8; nt++) {
            int c = cbase + nt * 8;
            float b0 = fc_b[c], b1 = fc_b[c + 1];
            int r0 = rbase + mt * 16;
            if (r0 < Mrows) {
                float2 v = make_float2(acc[mt][nt][0] + b0, acc[mt][nt][1] + b1);
                *(float2*)&out[(size_t)r0 * Vsz + c] = v;
            }
            int r1 = r0 + 8;
            if (r1 < Mrows) {
                float2 v = make_float2(acc[mt][nt][2] + b0, acc[mt][nt][3] + b1);
                *(float2*)&out[(size_t)r1 * Vsz + c] = v;
            }
        }
}

// ---------------- launch ----------------
extern "C" void kernel_launch(void* const* d_in, const int* in_sizes, int n_in,
                              void* d_out, int out_size)
{
    const int*   src     = (const int*)d_in[0];
    const int*   tgt     = (const int*)d_in[1];
    const float* embed   = (const float*)d_in[2];
    const float* enc_Wih = (const float*)d_in[3];
    const float* enc_Whh = (const float*)d_in[4];
    const float* enc_bih = (const float*)d_in[5];
    const float* enc_bhh = (const float*)d_in[6];
    const float* dec_Wih = (const float*)d_in[7];
    const float* dec_Whh = (const float*)d_in[8];
    const float* dec_bih = (const float*)d_in[9];
    const float* dec_bhh = (const float*)d_in[10];
    const float* attn_W  = (const float*)d_in[11];
    const float* attn_b  = (const float*)d_in[12];
    const float* attn_v  = (const float*)d_in[13];
    const float* fc_W    = (const float*)d_in[14];
    const float* fc_b    = (const float*)d_in[15];
    float* out = (float*)d_out;

    float *p_src_emb, *p_dec_in, *p_enc_xg, *p_dec_xg, *p_enc_out, *p_enc_proj;
    cudaGetSymbolAddress((void**)&p_src_emb,  g_src_emb);
    cudaGetSymbolAddress((void**)&p_dec_in,   g_dec_in);
    cudaGetSymbolAddress((void**)&p_enc_xg,   g_enc_xg);
    cudaGetSymbolAddress((void**)&p_dec_xg,   g_dec_xg);
    cudaGetSymbolAddress((void**)&p_enc_out,  g_enc_out);
    cudaGetSymbolAddress((void**)&p_enc_proj, g_enc_proj);

    cudaFuncSetAttribute(enc_scan_kernel, cudaFuncAttributeMaxDynamicSharedMemorySize, ENC_SMEM_BYTES);
    cudaFuncSetAttribute(dec_scan_kernel, cudaFuncAttributeMaxDynamicSharedMemorySize, DEC_SMEM_BYTES);
    cudaFuncSetAttribute(fc_mma_kernel,  cudaFuncAttributeMaxDynamicSharedMemorySize, FC_SMEM_BYTES);

    init_state_kernel<<<(Bsz * Hd + 255) / 256, 256>>>();
    gather_src_kernel<<<Ssz * Bsz, Ed>>>(src, embed);
    gather_dec_kernel<<<T1 * Bsz, Ed>>>(tgt, embed);

    conv_w_kernel<<<(Vsz * Hd / 4 + 255) / 256, 256>>>(fc_W);

    {   // enc_xg
        dim3 grid(FH / 128, (Ssz * Bsz + 127) / 128);
        sgemm_bias_kernel<<<grid, 256>>>(p_src_emb, Ed, enc_Wih, Ed, 0,
                                         enc_bih, enc_bhh, p_enc_xg, Ssz * Bsz, FH);
    }
    {   // dec_xg
        dim3 grid(FH / 128, (T1 * Bsz + 127) / 128);
        sgemm_bias_kernel<<<grid, 256>>>(p_dec_in, Ed, dec_Wih, Ed + Hd, 0,
                                         dec_bih, dec_bhh, p_dec_xg, T1 * Bsz, FH);
    }

    enc_scan_kernel<<<NBLK, 256, ENC_SMEM_BYTES>>>(enc_Whh);

    {   // enc_proj
        dim3 grid(Hd / 128, (Bsz * Ssz + 127) / 128);
        sgemm_bias_kernel<<<grid, 256>>>(p_enc_out, Hd, attn_W, 2 * Hd, Hd,
                                         attn_b, nullptr, p_enc_proj, Bsz * Ssz, Hd);
    }

    dec_scan_kernel<<<NBLK, 256, DEC_SMEM_BYTES>>>(dec_Wih, dec_Whh, attn_W, attn_v);

    conv_hs_kernel<<<(MrowsPad * Hd / 4 + 255) / 256, 256>>>();
    fc_mma_kernel<<<dim3(MrowsPad / 128, Vsz / 128), 256, FC_SMEM_BYTES>>>(fc_b, out);
}

// round 11
// speedup vs baseline: 1.1532x; 1.0074x over previous
#include <cuda_runtime.h>
#include <cuda_bf16.h>
#include <cstddef>
#include <cstdint>

#define Bsz 32
#define Ssz 128
#define Tsz 64
#define T1  63
#define Ed  256
#define Hd  512
#define Vsz 32000
#define FH  2048
#define NBLK 128
#define Mrows 2016       // Bsz*T1
#define MrowsPad 2048

// ---------------- device scratch ----------------
__device__ __align__(16) float g_src_emb[(size_t)Ssz * Bsz * Ed];
__device__ __align__(16) float g_dec_in [(size_t)T1  * Bsz * Ed];
__device__ __align__(16) float g_enc_xg [(size_t)Ssz * Bsz * FH];
__device__ __align__(16) float g_dec_xg [(size_t)T1  * Bsz * FH];
__device__ __align__(16) float g_enc_out[(size_t)Bsz * Ssz * Hd];
__device__ __align__(16) float g_enc_proj[(size_t)Bsz * Ssz * Hd];
__device__ __align__(16) float g_h[2][Bsz * Hd];
__device__ __align__(16) float g_c [Bsz * Hd];
__device__ __align__(16) float g_ctx[Bsz * Hd];
__device__ __align__(16) float g_hproj[Bsz * Hd];
__device__ __align__(16) float g_attp[Bsz][4][516];   // per-part: ctx[512], m@512, l@513
__device__ unsigned g_cnt[2];
__device__ unsigned g_gen[2];
// bf16 hi/lo split operands for the FC tensor GEMM
__device__ __align__(16) __nv_bfloat16 g_hs_hi[(size_t)MrowsPad * Hd];
__device__ __align__(16) __nv_bfloat16 g_hs_lo[(size_t)MrowsPad * Hd];
__device__ __align__(16) __nv_bfloat16 g_fcw_hi[(size_t)Vsz * Hd];
__device__ __align__(16) __nv_bfloat16 g_fcw_lo[(size_t)Vsz * Hd];

__device__ __forceinline__ float sigf(float x) { return 1.0f / (1.0f + expf(-x)); }
__device__ __forceinline__ float tanh_fast(float x) {
    float y;
    asm("tanh.approx.f32 %0, %1;" : "=f"(y) : "f"(x));
    return y;
}

// ---------------- packed f32x2 FMA ----------------
__device__ __forceinline__ void ffma2(unsigned long long& d, unsigned long long a, unsigned long long b) {
    asm("fma.rn.f32x2 %0, %1, %2, %0;" : "+l"(d) : "l"(a), "l"(b));
}
__device__ __forceinline__ float f32x2_sum(unsigned long long v) {
    float lo, hi;
    asm("mov.b64 {%0, %1}, %2;" : "=f"(lo), "=f"(hi) : "l"(v));
    return lo + hi;
}
__device__ __forceinline__ void f32x2_unpack(unsigned long long v, float& lo, float& hi) {
    asm("mov.b64 {%0, %1}, %2;" : "=f"(lo), "=f"(hi) : "l"(v));
}
__device__ __forceinline__ unsigned long long pack2(float lo, float hi) {
    unsigned long long v;
    asm("mov.b64 %0, {%1, %2};" : "=l"(v) : "f"(lo), "f"(hi));
    return v;
}

__device__ __forceinline__ uint32_t smem_to_u32(const void* p) {
    uint32_t a;
    asm("{ .reg .u64 t; cvta.to.shared.u64 t, %1; cvt.u32.u64 %0, t; }" : "=r"(a) : "l"(p));
    return a;
}
__device__ __forceinline__ void ldsm_x4(uint32_t* r, uint32_t addr) {
    asm volatile("ldmatrix.sync.aligned.m8n8.x4.shared.b16 {%0,%1,%2,%3}, [%4];"
        : "=r"(r[0]), "=r"(r[1]), "=r"(r[2]), "=r"(r[3]) : "r"(addr));
}
__device__ __forceinline__ void mma_bf16(float* d, const uint32_t* a, uint32_t b0, uint32_t b1) {
    asm volatile("mma.sync.aligned.m16n8k16.row.col.f32.bf16.bf16.f32 "
        "{%0,%1,%2,%3}, {%4,%5,%6,%7}, {%8,%9}, {%0,%1,%2,%3};"
        : "+f"(d[0]), "+f"(d[1]), "+f"(d[2]), "+f"(d[3])
        : "r"(a[0]), "r"(a[1]), "r"(a[2]), "r"(a[3]), "r"(b0), "r"(b1));
}
__device__ __forceinline__ void cp_async16(uint32_t dst, const void* src) {
    asm volatile("cp.async.cg.shared.global [%0], [%1], 16;" :: "r"(dst), "l"(src) : "memory");
}

// ---------------- global barrier (atomic; measured fastest) ----------------
__device__ __forceinline__ void grid_bar(int which, unsigned target) {
    __threadfence();
    __syncthreads();
    if (threadIdx.x == 0) {
        unsigned arr = atomicAdd(&g_cnt[which], 1u);
        if (arr == NBLK - 1u) {
            g_cnt[which] = 0u;
            __threadfence();
            atomicAdd(&g_gen[which], 1u);
        } else {
            while (atomicAdd(&g_gen[which], 0u) < target) { }
        }
    }
    __syncthreads();
}

__global__ void init_state_kernel() {
    int i = blockIdx.x * blockDim.x + threadIdx.x;
    if (i < Bsz * Hd) g_h[0][i] = 0.f;
    if (i < 2) { g_cnt[i] = 0u; g_gen[i] = 0u; }
    // zero the M-padding rows of hs_hi/lo (rows 2016..2047) — 32*512 = 16384 elems
    if (i < (MrowsPad - Mrows) * Hd) {
        g_hs_hi[(size_t)Mrows * Hd + i] = __float2bfloat16(0.f);
        g_hs_lo[(size_t)Mrows * Hd + i] = __float2bfloat16(0.f);
    }
}

// ---------------- embedding gathers ----------------
__global__ void gather_src_kernel(const int* __restrict__ src, const float* __restrict__ embed) {
    int row = blockIdx.x;           // s*B + b
    int s = row >> 5, b = row & 31;
    int idx = src[b * Ssz + s];
    g_src_emb[(size_t)row * Ed + threadIdx.x] = embed[(size_t)idx * Ed + threadIdx.x];
}
__global__ void gather_dec_kernel(const int* __restrict__ tgt, const float* __restrict__ embed) {
    int row = blockIdx.x;           // t*B + b
    int t = row >> 5, b = row & 31;
    int idx = tgt[b * Tsz + t];
    g_dec_in[(size_t)row * Ed + threadIdx.x] = embed[(size_t)idx * Ed + threadIdx.x];
}

// ---------------- fp32 SGEMM with f32x2 FMA (small GEMMs) ----------------
__global__ void __launch_bounds__(256) sgemm_bias_kernel(
    const float* __restrict__ A, int K,
    const float* __restrict__ W, int ldw, int woff,
    const float* __restrict__ b1, const float* __restrict__ b2,
    float* __restrict__ C, int M, int N)
{
    __shared__ __align__(16) float As[8][128];
    __shared__ __align__(16) float Bs[8][128];
    const int bm = blockIdx.y * 128;
    const int bn = blockIdx.x * 128;
    const int t  = threadIdx.x;
    const int tr = (t >> 4) * 8;
    const int tc = (t & 15) * 8;
    const int lr = t >> 1;
    const int lc = (t & 1) * 4;

    unsigned long long acc2[8][4];
    #pragma unroll
    for (int i = 0; i < 8; i++)
        #pragma unroll
        for (int j = 0; j < 4; j++) acc2[i][j] = 0ull;

    const bool aValid = (bm + lr) < M;
    const float* aRow = A + (size_t)(bm + lr) * K + lc;
    const float* wRow = W + (size_t)(bn + lr) * ldw + woff + lc;

    for (int k0 = 0; k0 < K; k0 += 8) {
        float4 av = aValid ? *(const float4*)(aRow + k0) : make_float4(0.f, 0.f, 0.f, 0.f);
        float4 wv = *(const float4*)(wRow + k0);
        As[lc + 0][lr] = av.x; As[lc + 1][lr] = av.y; As[lc + 2][lr] = av.z; As[lc + 3][lr] = av.w;
        Bs[lc + 0][lr] = wv.x; Bs[lc + 1][lr] = wv.y; Bs[lc + 2][lr] = wv.z; Bs[lc + 3][lr] = wv.w;
        __syncthreads();
        #pragma unroll
        for (int kk = 0; kk < 8; kk++) {
            float a[8];
            *(float4*)(a)      = *(const float4*)&As[kk][tr];
            *(float4*)(a + 4)  = *(const float4*)&As[kk][tr + 4];
            unsigned long long bb2[4];
            *(ulonglong2*)&bb2[0] = *(const ulonglong2*)&Bs[kk][tc];
            *(ulonglong2*)&bb2[2] = *(const ulonglong2*)&Bs[kk][tc + 4];
            #pragma unroll
            for (int i = 0; i < 8; i++) {
                unsigned long long ap = pack2(a[i], a[i]);
                #pragma unroll
                for (int j = 0; j < 4; j++) ffma2(acc2[i][j], ap, bb2[j]);
            }
        }
        __syncthreads();
    }

    float bias[8];
    #pragma unroll
    for (int j = 0; j < 8; j++) {
        int n = bn + tc + j;
        bias[j] = b1[n] + (b2 ? b2[n] : 0.f);
    }
    #pragma unroll
    for (int i = 0; i < 8; i++) {
        int m = bm + tr + i;
        if (m >= M) break;
        float* cp = C + (size_t)m * N + bn + tc;
        #pragma unroll
        for (int j = 0; j < 4; j++) {
            float lo, hi;
            f32x2_unpack(acc2[i][j], lo, hi);
            cp[j * 2]     = lo + bias[j * 2];
            cp[j * 2 + 1] = hi + bias[j * 2 + 1];
        }
    }
}

// ---------------- gate partial-GEMM helper (f32x2) ----------------
__device__ __forceinline__ void gates_partial(
    const float* sm, int wbase, int xbase, int jg, int bg, int ks, unsigned long long acc[4][4])
{
    const int k0 = ks * 64;
    #pragma unroll 4
    for (int k4 = 0; k4 < 16; k4++) {
        const int k = k0 + (k4 << 2);
        ulonglong2 wv[4], hv[4];
        #pragma unroll
        for (int jj = 0; jj < 4; jj++)
            wv[jj] = *(const ulonglong2*)&sm[wbase + (jj * 4 + jg) * 516 + k];
        #pragma unroll
        for (int bb = 0; bb < 4; bb++)
            hv[bb] = *(const ulonglong2*)&sm[xbase + (bb * 8 + bg) * 516 + k];
        #pragma unroll
        for (int jj = 0; jj < 4; jj++)
            #pragma unroll
            for (int bb = 0; bb < 4; bb++) {
                ffma2(acc[jj][bb], wv[jj].x, hv[bb].x);
                ffma2(acc[jj][bb], wv[jj].y, hv[bb].y);
            }
    }
}

// ---------------- persistent encoder scan ----------------
#define ENC_SMEM_BYTES (28992 * 4)
__global__ void __launch_bounds__(256, 1) enc_scan_kernel(const float* __restrict__ Whh) {
    extern __shared__ float sm[];
    const int tid = threadIdx.x, hG = blockIdx.x;
    const int W0 = 0, HX = 8256, RD = 24768;

    for (int i = tid; i < 16 * 128; i += 256) {
        int r = i >> 7, k4 = i & 127;
        int j = (r >> 2) * Hd + hG * 4 + (r & 3);
        *(float4*)&sm[W0 + r * 516 + k4 * 4] = *(const float4*)&Whh[(size_t)j * Hd + k4 * 4];
    }

    float c_reg = 0.f;
    const int jg = tid & 3, bg = (tid >> 2) & 7, ks = tid >> 5;
    const int hl = tid >> 5, bq = tid & 31;
    unsigned bgen = 0;

    for (int s = 0; s < Ssz; s++) {
        const float* hin = g_h[s & 1];
        float* hout = g_h[(s + 1) & 1];

        float xg[4];
        if (tid < 128) {
            #pragma unroll
            for (int gate = 0; gate < 4; gate++)
                xg[gate] = __ldcg(&g_enc_xg[((size_t)s * Bsz + bq) * FH + gate * Hd + hG * 4 + hl]);
        }

        for (int i = tid; i < 32 * 128; i += 256) {
            int b = i >> 7, k4 = i & 127;
            *(float4*)&sm[HX + b * 516 + k4 * 4] = __ldcg((const float4*)&hin[(b << 9) + k4 * 4]);
        }
        __syncthreads();

        unsigned long long acc[4][4];
        #pragma unroll
        for (int a = 0; a < 4; a++)
            #pragma unroll
            for (int b2 = 0; b2 < 4; b2++) acc[a][b2] = 0ull;
        gates_partial(sm, W0, HX, jg, bg, ks, acc);

        #pragma unroll
        for (int jj = 0; jj < 4; jj++)
            #pragma unroll
            for (int bb = 0; bb < 4; bb++)
                sm[RD + ks * 528 + (jj * 4 + jg) * 33 + bb * 8 + bg] = f32x2_sum(acc[jj][bb]);
        __syncthreads();

        if (tid < 128) {
            float g4[4];
            #pragma unroll
            for (int gate = 0; gate < 4; gate++) {
                int r = gate * 4 + hl;
                float a = 0.f;
                #pragma unroll
                for (int q = 0; q < 8; q++) a += sm[RD + q * 528 + r * 33 + bq];
                g4[gate] = a + xg[gate];
            }
            float cv = sigf(g4[1]) * c_reg + sigf(g4[0]) * tanhf(g4[2]);
            float hn = sigf(g4[3]) * tanhf(cv);
            c_reg = cv;
            hout[(bq << 9) + hG * 4 + hl] = hn;
            g_enc_out[((size_t)bq * Ssz + s) * Hd + hG * 4 + hl] = hn;
        }
        bgen++;
        grid_bar(0, bgen);
    }
    if (tid < 128) {
        g_c[(bq << 9) + hG * 4 + hl] = c_reg;
    }
}

// ---------------- persistent decoder scan (attention fused, online softmax) ----------------
#define DEC_SMEM_BYTES (40464 * 4)
__global__ void __launch_bounds__(256, 1) dec_scan_kernel(
    const float* __restrict__ Wih, const float* __restrict__ Whh,
    const float* __restrict__ attnW, const float* __restrict__ attnv)
{
    extern __shared__ float sm[];
    const int tid = threadIdx.x, hG = blockIdx.x;
    const int W0 = 0, WC = 8256, WA = 16512, HX = 18576, RD = 35088,
              HP = 39312, VS = 39824, SC = 40336;

    for (int i = tid; i < 16 * 128; i += 256) {
        int r = i >> 7, k4 = i & 127;
        int j = (r >> 2) * Hd + hG * 4 + (r & 3);
        *(float4*)&sm[W0 + r * 516 + k4 * 4] = *(const float4*)&Whh[(size_t)j * Hd + k4 * 4];
        *(float4*)&sm[WC + r * 516 + k4 * 4] = *(const float4*)&Wih[(size_t)j * (Ed + Hd) + Ed + k4 * 4];
    }
    for (int i = tid; i < 4 * 128; i += 256) {
        int r = i >> 7, k4 = i & 127;
        *(float4*)&sm[WA + r * 516 + k4 * 4] = *(const float4*)&attnW[(size_t)(hG * 4 + r) * (2 * Hd) + k4 * 4];
    }
    for (int i = tid; i < Hd; i += 256) sm[VS + i] = attnv[i];

    float c_reg = 0.f;
    const int hl = tid >> 5, bq = tid & 31;
    if (tid < 128) c_reg = __ldcg(&g_c[(bq << 9) + hG * 4 + hl]);

    const int jg = tid & 3, bg = (tid >> 2) & 7, ks = tid >> 5;
    const int bB = hG >> 2;
    const int part = hG & 3;
    unsigned bgen = 0;

    for (int t = 0; t < T1; t++) {
        const float* hin = g_h[t & 1];
        float* hout = g_h[(t + 1) & 1];

        // ---- phase A: load h, hproj, gates h-part ----
        for (int i = tid; i < 32 * 128; i += 256) {
            int b = i >> 7, k4 = i & 127;
            *(float4*)&sm[HX + b * 516 + k4 * 4] = __ldcg((const float4*)&hin[(b << 9) + k4 * 4]);
        }
        __syncthreads();
        {
            const int ko = tid >> 6, bh = (tid >> 1) & 31, kh = tid & 1;
            float a = 0.f;
            const int kb = kh << 8;
            #pragma unroll 4
            for (int k = kb; k < kb + 256; k += 4) {
                float4 w4 = *(const float4*)&sm[WA + ko * 516 + k];
                float4 h4 = *(const float4*)&sm[HX + bh * 516 + k];
                a += w4.x * h4.x + w4.y * h4.y + w4.z * h4.z + w4.w * h4.w;
            }
            a += __shfl_xor_sync(0xffffffffu, a, 1);
            if (!kh) g_hproj[(bh << 9) + hG * 4 + ko] = a;
        }
        unsigned long long acc[4][4];
        #pragma unroll
        for (int a2 = 0; a2 < 4; a2++)
            #pragma unroll
            for (int b2 = 0; b2 < 4; b2++) acc[a2][b2] = 0ull;
        gates_partial(sm, W0, HX, jg, bg, ks, acc);
        bgen++; grid_bar(1, bgen);

        // ---- phase B: attention partials for (bB, 32-s chunk `part`) ----
        for (int i = tid; i < Hd; i += 256) sm[HP + i] = __ldcg(&g_hproj[(bB << 9) + i]);
        __syncthreads();
        {
            const int s0 = part * 32, w = tid >> 5, lane = tid & 31;
            #pragma unroll
            for (int q = 0; q < 4; q++) {
                int sl = w * 4 + q;
                const float* ep = g_enc_proj + ((size_t)bB * Ssz + s0 + sl) * Hd;
                float a = 0.f;
                for (int kk = lane; kk < Hd; kk += 32)
                    a += tanh_fast(sm[HP + kk] + ep[kk]) * sm[VS + kk];
                #pragma unroll
                for (int off = 16; off; off >>= 1) a += __shfl_xor_sync(0xffffffffu, a, off);
                if (!lane) sm[SC + sl] = a;
            }
        }
        __syncthreads();
        {
            float mloc = sm[SC + 0];
            #pragma unroll
            for (int i2 = 1; i2 < 32; i2++) mloc = fmaxf(mloc, sm[SC + i2]);
            if (tid < 32) sm[SC + 32 + tid] = expf(sm[SC + tid] - mloc);
            __syncthreads();
            float lloc = 0.f;
            #pragma unroll
            for (int i2 = 0; i2 < 32; i2++) lloc += sm[SC + 32 + i2];

            const int s0 = part * 32;
            float a0 = 0.f, a1 = 0.f;
            const float* eo = g_enc_out + ((size_t)bB * Ssz + s0) * Hd;
            #pragma unroll 4
            for (int s2 = 0; s2 < 32; s2++) {
                float p = sm[SC + 32 + s2];
                a0 += p * eo[(size_t)s2 * Hd + tid];
                a1 += p * eo[(size_t)s2 * Hd + tid + 256];
            }
            float* ap = g_attp[bB][part];
            ap[tid] = a0;
            ap[tid + 256] = a1;
            if (tid == 0) { ap[512] = mloc; ap[513] = lloc; }
        }
        bgen++; grid_bar(1, bgen);

        // ---- phase C: combine 4 partials -> g_ctx ----
        if (tid < 128) {
            const int h = part * 128 + tid;
            float m0 = __ldcg(&g_attp[bB][0][512]);
            float m1 = __ldcg(&g_attp[bB][1][512]);
            float m2 = __ldcg(&g_attp[bB][2][512]);
            float m3 = __ldcg(&g_attp[bB][3][512]);
            float M = fmaxf(fmaxf(m0, m1), fmaxf(m2, m3));
            float w0 = expf(m0 - M), w1 = expf(m1 - M), w2 = expf(m2 - M), w3 = expf(m3 - M);
            float l = w0 * __ldcg(&g_attp[bB][0][513]) + w1 * __ldcg(&g_attp[bB][1][513])
                    + w2 * __ldcg(&g_attp[bB][2][513]) + w3 * __ldcg(&g_attp[bB][3][513]);
            float cx = w0 * __ldcg(&g_attp[bB][0][h]) + w1 * __ldcg(&g_attp[bB][1][h])
                     + w2 * __ldcg(&g_attp[bB][2][h]) + w3 * __ldcg(&g_attp[bB][3][h]);
            g_ctx[(bB << 9) + h] = cx / l;
        }
        bgen++; grid_bar(1, bgen);

        // ---- phase D: gates ctx-part + pointwise ----
        float xg[4];
        if (tid < 128) {
            #pragma unroll
            for (int gate = 0; gate < 4; gate++)
                xg[gate] = __ldcg(&g_dec_xg[((size_t)t * Bsz + bq) * FH + gate * Hd + hG * 4 + hl]);
        }
        for (int i = tid; i < 32 * 128; i += 256) {
            int b = i >> 7, k4 = i & 127;
            *(float4*)&sm[HX + b * 516 + k4 * 4] = __ldcg((const float4*)&g_ctx[(b << 9) + k4 * 4]);
        }
        __syncthreads();
        gates_partial(sm, WC, HX, jg, bg, ks, acc);

        #pragma unroll
        for (int jj = 0; jj < 4; jj++)
            #pragma unroll
            for (int bb = 0; bb < 4; bb++)
                sm[RD + ks * 528 + (jj * 4 + jg) * 33 + bb * 8 + bg] = f32x2_sum(acc[jj][bb]);
        __syncthreads();

        if (tid < 128) {
            float g4[4];
            #pragma unroll
            for (int gate = 0; gate < 4; gate++) {
                int r = gate * 4 + hl;
                float a = 0.f;
                #pragma unroll
                for (int q = 0; q < 8; q++) a += sm[RD + q * 528 + r * 33 + bq];
                g4[gate] = a + xg[gate];
            }
            float cv = sigf(g4[1]) * c_reg + sigf(g4[0]) * tanhf(g4[2]);
            float hn = sigf(g4[3]) * tanhf(cv);
            c_reg = cv;
            hout[(bq << 9) + hG * 4 + hl] = hn;
            // direct bf16 hi/lo split store for the FC GEMM (replaces conv_hs)
            size_t mi = ((size_t)bq * T1 + t) * Hd + hG * 4 + hl;
            __nv_bfloat16 hhi = __float2bfloat16(hn);
            g_hs_hi[mi] = hhi;
            g_hs_lo[mi] = __float2bfloat16(hn - __bfloat162float(hhi));
        }
        bgen++; grid_bar(1, bgen);
    }
}

// ---------------- fc_W bf16 hi/lo split ----------------
__global__ void conv_w_kernel(const float* __restrict__ fc_W) {
    size_t i = ((size_t)blockIdx.x * 256 + threadIdx.x) * 4;
    if (i >= (size_t)Vsz * Hd) return;
    float4 x = *(const float4*)&fc_W[i];
    float v[4] = {x.x, x.y, x.z, x.w};
    #pragma unroll
    for (int j = 0; j < 4; j++) {
        __nv_bfloat16 hi = __float2bfloat16(v[j]);
        g_fcw_hi[i + j] = hi;
        g_fcw_lo[i + j] = __float2bfloat16(v[j] - __bfloat162float(hi));
    }
}

// ---------------- FC GEMM: 64x128 tile, 2 CTAs/SM, cp.async 2-stage ----------------
// 8 warps = 2(m) x 4(n); warp tile 32x32 (2 m16 x 4 n8). K=512 in 8 chunks of 64.
// Per stage: Ah(64x72), Al(64x72), Bh(128x72), Bl(128x72) bf16 = 55296 B; 2 stages = 110592 B.
#define FCA_B  9216u                     // A tile bytes (64*72*2)
#define FCB_B  18432u                    // B tile bytes (128*72*2)
#define FCSTG  55296u                    // stage bytes
#define FC_SMEM_BYTES (2 * FCSTG)        // 110592
__global__ void __launch_bounds__(256, 2) fc_mma_kernel(
    const float* __restrict__ fc_b, float* __restrict__ out)
{
    extern __shared__ __nv_bfloat16 smb[];
    const int tid = threadIdx.x, lane = tid & 31, wid = tid >> 5;
    const int wm = wid & 1, wn = wid >> 1;
    const int m0 = blockIdx.x * 64, n0 = blockIdx.y * 128;
    const uint32_t smem_base = smem_to_u32(smb);

    const __nv_bfloat16* baseAh = g_hs_hi  + (size_t)m0 * Hd;
    const __nv_bfloat16* baseAl = g_hs_lo  + (size_t)m0 * Hd;
    const __nv_bfloat16* baseBh = g_fcw_hi + (size_t)n0 * Hd;
    const __nv_bfloat16* baseBl = g_fcw_lo + (size_t)n0 * Hd;

    float acc[2][4][4];
    #pragma unroll
    for (int a = 0; a < 2; a++)
        #pragma unroll
        for (int b = 0; b < 4; b++)
            #pragma unroll
            for (int c = 0; c < 4; c++) acc[a][b][c] = 0.f;

    const int lrow = ((lane >> 3) & 1) * 8 + (lane & 7);
    const int lcol = (lane >> 4) * 8;

    auto issue_stage = [&](int kc, int stg) {
        uint32_t sb = smem_base + (uint32_t)stg * FCSTG;
        // A tiles: 64 rows x 8 chunks = 512 cps each
        #pragma unroll
        for (int tt = 0; tt < 2; tt++) {
            int idx = tid + tt * 256;
            int r = idx >> 3, c8 = idx & 7;
            uint32_t doff = (uint32_t)(r * 144 + c8 * 16);
            size_t gi = (size_t)r * Hd + kc * 64 + c8 * 8;
            cp_async16(sb + doff,          baseAh + gi);
            cp_async16(sb + FCA_B + doff,  baseAl + gi);
        }
        // B tiles: 128 rows x 8 chunks = 1024 cps each
        #pragma unroll
        for (int tt = 0; tt < 4; tt++) {
            int idx = tid + tt * 256;
            int r = idx >> 3, c8 = idx & 7;
            uint32_t doff = (uint32_t)(r * 144 + c8 * 16);
            size_t gi = (size_t)r * Hd + kc * 64 + c8 * 8;
            cp_async16(sb + 2 * FCA_B + doff,         baseBh + gi);
            cp_async16(sb + 2 * FCA_B + FCB_B + doff, baseBl + gi);
        }
        asm volatile("cp.async.commit_group;" ::: "memory");
    };

    issue_stage(0, 0);

    for (int kc = 0; kc < 8; kc++) {
        const int stg = kc & 1;
        if (kc < 7) {
            issue_stage(kc + 1, stg ^ 1);
            asm volatile("cp.async.wait_group 1;" ::: "memory");
        } else {
            asm volatile("cp.async.wait_group 0;" ::: "memory");
        }
        __syncthreads();

        const uint32_t sb = smem_base + (uint32_t)stg * FCSTG;
        #pragma unroll
        for (int kk = 0; kk < 4; kk++) {
            uint32_t ah[2][4], al[2][4], bh[2][4], bl[2][4];
            #pragma unroll
            for (int mt = 0; mt < 2; mt++) {
                uint32_t off = sb + (uint32_t)(((wm * 32 + mt * 16 + lrow) * 72 + kk * 16 + lcol) * 2);
                ldsm_x4(ah[mt], off);
                ldsm_x4(al[mt], off + FCA_B);
            }
            #pragma unroll
            for (int ng = 0; ng < 2; ng++) {
                uint32_t off = sb + 2 * FCA_B +
                    (uint32_t)(((wn * 32 + ng * 16 + lrow) * 72 + kk * 16 + lcol) * 2);
                ldsm_x4(bh[ng], off);
                ldsm_x4(bl[ng], off + FCB_B);
            }
            // pass 1: Ah*Bh
            #pragma unroll
            for (int mt = 0; mt < 2; mt++)
                #pragma unroll
                for (int ng = 0; ng < 2; ng++) {
                    mma_bf16(acc[mt][ng * 2],     ah[mt], bh[ng][0], bh[ng][2]);
                    mma_bf16(acc[mt][ng * 2 + 1], ah[mt], bh[ng][1], bh[ng][3]);
                }
            // pass 2: Ah*Bl
            #pragma unroll
            for (int mt = 0; mt < 2; mt++)
                #pragma unroll
                for (int ng = 0; ng < 2; ng++) {
                    mma_bf16(acc[mt][ng * 2],     ah[mt], bl[ng][0], bl[ng][2]);
                    mma_bf16(acc[mt][ng * 2 + 1], ah[mt], bl[ng][1], bl[ng][3]);
                }
            // pass 3: Al*Bh
            #pragma unroll
            for (int mt = 0; mt < 2; mt++)
                #pragma unroll
                for (int ng = 0; ng < 2; ng++) {
                    mma_bf16(acc[mt][ng * 2],     al[mt], bh[ng][0], bh[ng][2]);
                    mma_bf16(acc[mt][ng * 2 + 1], al[mt], bh[ng][1], bh[ng][3]);
                }
        }
        __syncthreads();
    }

    const int rbase = m0 + wm * 32 + (lane >> 2);
    const int cbase = n0 + wn * 32 + (lane & 3) * 2;
    #pragma unroll
    for (int mt = 0; mt < 2; mt++)
        #pragma unroll
        for (int nt = 0; nt < 4; nt++) {
            int c = cbase + nt * 8;
            float b0 = fc_b[c], b1 = fc_b[c + 1];
            int r0 = rbase + mt * 16;
            if (r0 < Mrows) {
                float2 v = make_float2(acc[mt][nt][0] + b0, acc[mt][nt][1] + b1);
                *(float2*)&out[(size_t)r0 * Vsz + c] = v;
            }
            int r1 = r0 + 8;
            if (r1 < Mrows) {
                float2 v = make_float2(acc[mt][nt][2] + b0, acc[mt][nt][3] + b1);
                *(float2*)&out[(size_t)r1 * Vsz + c] = v;
            }
        }
}

// ---------------- launch ----------------
extern "C" void kernel_launch(void* const* d_in, const int* in_sizes, int n_in,
                              void* d_out, int out_size)
{
    const int*   src     = (const int*)d_in[0];
    const int*   tgt     = (const int*)d_in[1];
    const float* embed   = (const float*)d_in[2];
    const float* enc_Wih = (const float*)d_in[3];
    const float* enc_Whh = (const float*)d_in[4];
    const float* enc_bih = (const float*)d_in[5];
    const float* enc_bhh = (const float*)d_in[6];
    const float* dec_Wih = (const float*)d_in[7];
    const float* dec_Whh = (const float*)d_in[8];
    const float* dec_bih = (const float*)d_in[9];
    const float* dec_bhh = (const float*)d_in[10];
    const float* attn_W  = (const float*)d_in[11];
    const float* attn_b  = (const float*)d_in[12];
    const float* attn_v  = (const float*)d_in[13];
    const float* fc_W    = (const float*)d_in[14];
    const float* fc_b    = (const float*)d_in[15];
    float* out = (float*)d_out;

    float *p_src_emb, *p_dec_in, *p_enc_xg, *p_dec_xg, *p_enc_out, *p_enc_proj;
    cudaGetSymbolAddress((void**)&p_src_emb,  g_src_emb);
    cudaGetSymbolAddress((void**)&p_dec_in,   g_dec_in);
    cudaGetSymbolAddress((void**)&p_enc_xg,   g_enc_xg);
    cudaGetSymbolAddress((void**)&p_dec_xg,   g_dec_xg);
    cudaGetSymbolAddress((void**)&p_enc_out,  g_enc_out);
    cudaGetSymbolAddress((void**)&p_enc_proj, g_enc_proj);

    cudaFuncSetAttribute(enc_scan_kernel, cudaFuncAttributeMaxDynamicSharedMemorySize, ENC_SMEM_BYTES);
    cudaFuncSetAttribute(dec_scan_kernel, cudaFuncAttributeMaxDynamicSharedMemorySize, DEC_SMEM_BYTES);
    cudaFuncSetAttribute(fc_mma_kernel,  cudaFuncAttributeMaxDynamicSharedMemorySize, FC_SMEM_BYTES);

    init_state_kernel<<<(Bsz * Hd + 255) / 256, 256>>>();
    gather_src_kernel<<<Ssz * Bsz, Ed>>>(src, embed);
    gather_dec_kernel<<<T1 * Bsz, Ed>>>(tgt, embed);

    conv_w_kernel<<<(Vsz * Hd / 4 + 255) / 256, 256>>>(fc_W);

    {   // enc_xg
        dim3 grid(FH / 128, (Ssz * Bsz + 127) / 128);
        sgemm_bias_kernel<<<grid, 256>>>(p_src_emb, Ed, enc_Wih, Ed, 0,
                                         enc_bih, enc_bhh, p_enc_xg, Ssz * Bsz, FH);
    }
    {   // dec_xg
        dim3 grid(FH / 128, (T1 * Bsz + 127) / 128);
        sgemm_bias_kernel<<<grid, 256>>>(p_dec_in, Ed, dec_Wih, Ed + Hd, 0,
                                         dec_bih, dec_bhh, p_dec_xg, T1 * Bsz, FH);
    }

    enc_scan_kernel<<<NBLK, 256, ENC_SMEM_BYTES>>>(enc_Whh);

    {   // enc_proj
        dim3 grid(Hd / 128, (Bsz * Ssz + 127) / 128);
        sgemm_bias_kernel<<<grid, 256>>>(p_enc_out, Hd, attn_W, 2 * Hd, Hd,
                                         attn_b, nullptr, p_enc_proj, Bsz * Ssz, Hd);
    }

    dec_scan_kernel<<<NBLK, 256, DEC_SMEM_BYTES>>>(dec_Wih, dec_Whh, attn_W, attn_v);

    fc_mma_kernel<<<dim3(MrowsPad / 64, Vsz / 128), 256, FC_SMEM_BYTES>>>(fc_b, out);
}

// round 12
// speedup vs baseline: 1.3071x; 1.1334x over previous
#include <cuda_runtime.h>
#include <cuda_bf16.h>
#include <cuda_fp16.h>
#include <cstddef>
#include <cstdint>

#define Bsz 32
#define Ssz 128
#define Tsz 64
#define T1  63
#define Ed  256
#define Hd  512
#define Vsz 32000
#define FH  2048
#define NBLK 128
#define Mrows 2016       // Bsz*T1
#define MrowsPad 2048

// ---------------- device scratch ----------------
__device__ __align__(16) float g_src_emb[(size_t)Ssz * Bsz * Ed];
__device__ __align__(16) float g_dec_in [(size_t)T1  * Bsz * Ed];
__device__ __align__(16) float g_enc_xg [(size_t)Ssz * Bsz * FH];
__device__ __align__(16) float g_dec_xg [(size_t)T1  * Bsz * FH];
__device__ __align__(16) float g_enc_out[(size_t)Bsz * Ssz * Hd];
__device__ __align__(16) float g_enc_proj[(size_t)Bsz * Ssz * Hd];
__device__ __align__(16) float g_h[2][Bsz * Hd];
__device__ __align__(16) float g_c [Bsz * Hd];
__device__ __align__(16) float g_ctx[Bsz * Hd];
__device__ __align__(16) float g_hproj[Bsz * Hd];
__device__ __align__(16) float g_attp[Bsz][4][516];   // per-part: ctx[512], m@512, l@513
__device__ unsigned g_cnt[2];
__device__ unsigned g_gen[2];
// fp16 operands for the FC tensor GEMM (single-pass)
__device__ __align__(16) __half g_hs_f16 [(size_t)MrowsPad * Hd];
__device__ __align__(16) __half g_fcw_f16[(size_t)Vsz * Hd];

__device__ __forceinline__ float sigf(float x) { return 1.0f / (1.0f + expf(-x)); }
__device__ __forceinline__ float tanh_fast(float x) {
    float y;
    asm("tanh.approx.f32 %0, %1;" : "=f"(y) : "f"(x));
    return y;
}

// ---------------- packed f32x2 FMA ----------------
__device__ __forceinline__ void ffma2(unsigned long long& d, unsigned long long a, unsigned long long b) {
    asm("fma.rn.f32x2 %0, %1, %2, %0;" : "+l"(d) : "l"(a), "l"(b));
}
__device__ __forceinline__ float f32x2_sum(unsigned long long v) {
    float lo, hi;
    asm("mov.b64 {%0, %1}, %2;" : "=f"(lo), "=f"(hi) : "l"(v));
    return lo + hi;
}
__device__ __forceinline__ void f32x2_unpack(unsigned long long v, float& lo, float& hi) {
    asm("mov.b64 {%0, %1}, %2;" : "=f"(lo), "=f"(hi) : "l"(v));
}
__device__ __forceinline__ unsigned long long pack2(float lo, float hi) {
    unsigned long long v;
    asm("mov.b64 %0, {%1, %2};" : "=l"(v) : "f"(lo), "f"(hi));
    return v;
}

__device__ __forceinline__ uint32_t smem_to_u32(const void* p) {
    uint32_t a;
    asm("{ .reg .u64 t; cvta.to.shared.u64 t, %1; cvt.u32.u64 %0, t; }" : "=r"(a) : "l"(p));
    return a;
}
__device__ __forceinline__ void ldsm_x4(uint32_t* r, uint32_t addr) {
    asm volatile("ldmatrix.sync.aligned.m8n8.x4.shared.b16 {%0,%1,%2,%3}, [%4];"
        : "=r"(r[0]), "=r"(r[1]), "=r"(r[2]), "=r"(r[3]) : "r"(addr));
}
__device__ __forceinline__ void mma_f16(float* d, const uint32_t* a, uint32_t b0, uint32_t b1) {
    asm volatile("mma.sync.aligned.m16n8k16.row.col.f32.f16.f16.f32 "
        "{%0,%1,%2,%3}, {%4,%5,%6,%7}, {%8,%9}, {%0,%1,%2,%3};"
        : "+f"(d[0]), "+f"(d[1]), "+f"(d[2]), "+f"(d[3])
        : "r"(a[0]), "r"(a[1]), "r"(a[2]), "r"(a[3]), "r"(b0), "r"(b1));
}
__device__ __forceinline__ void cp_async16(uint32_t dst, const void* src) {
    asm volatile("cp.async.cg.shared.global [%0], [%1], 16;" :: "r"(dst), "l"(src) : "memory");
}

// ---------------- global barrier (atomic; measured fastest) ----------------
__device__ __forceinline__ void grid_bar(int which, unsigned target) {
    __threadfence();
    __syncthreads();
    if (threadIdx.x == 0) {
        unsigned arr = atomicAdd(&g_cnt[which], 1u);
        if (arr == NBLK - 1u) {
            g_cnt[which] = 0u;
            __threadfence();
            atomicAdd(&g_gen[which], 1u);
        } else {
            while (atomicAdd(&g_gen[which], 0u) < target) { }
        }
    }
    __syncthreads();
}

__global__ void init_state_kernel() {
    int i = blockIdx.x * blockDim.x + threadIdx.x;
    if (i < Bsz * Hd) g_h[0][i] = 0.f;
    if (i < 2) { g_cnt[i] = 0u; g_gen[i] = 0u; }
    // zero the M-padding rows of hs_f16 (rows 2016..2047)
    if (i < (MrowsPad - Mrows) * Hd) {
        g_hs_f16[(size_t)Mrows * Hd + i] = __float2half(0.f);
    }
}

// ---------------- embedding gathers ----------------
__global__ void gather_src_kernel(const int* __restrict__ src, const float* __restrict__ embed) {
    int row = blockIdx.x;           // s*B + b
    int s = row >> 5, b = row & 31;
    int idx = src[b * Ssz + s];
    g_src_emb[(size_t)row * Ed + threadIdx.x] = embed[(size_t)idx * Ed + threadIdx.x];
}
__global__ void gather_dec_kernel(const int* __restrict__ tgt, const float* __restrict__ embed) {
    int row = blockIdx.x;           // t*B + b
    int t = row >> 5, b = row & 31;
    int idx = tgt[b * Tsz + t];
    g_dec_in[(size_t)row * Ed + threadIdx.x] = embed[(size_t)idx * Ed + threadIdx.x];
}

// ---------------- fp32 SGEMM with f32x2 FMA (small GEMMs) ----------------
__global__ void __launch_bounds__(256) sgemm_bias_kernel(
    const float* __restrict__ A, int K,
    const float* __restrict__ W, int ldw, int woff,
    const float* __restrict__ b1, const float* __restrict__ b2,
    float* __restrict__ C, int M, int N)
{
    __shared__ __align__(16) float As[8][128];
    __shared__ __align__(16) float Bs[8][128];
    const int bm = blockIdx.y * 128;
    const int bn = blockIdx.x * 128;
    const int t  = threadIdx.x;
    const int tr = (t >> 4) * 8;
    const int tc = (t & 15) * 8;
    const int lr = t >> 1;
    const int lc = (t & 1) * 4;

    unsigned long long acc2[8][4];
    #pragma unroll
    for (int i = 0; i < 8; i++)
        #pragma unroll
        for (int j = 0; j < 4; j++) acc2[i][j] = 0ull;

    const bool aValid = (bm + lr) < M;
    const float* aRow = A + (size_t)(bm + lr) * K + lc;
    const float* wRow = W + (size_t)(bn + lr) * ldw + woff + lc;

    for (int k0 = 0; k0 < K; k0 += 8) {
        float4 av = aValid ? *(const float4*)(aRow + k0) : make_float4(0.f, 0.f, 0.f, 0.f);
        float4 wv = *(const float4*)(wRow + k0);
        As[lc + 0][lr] = av.x; As[lc + 1][lr] = av.y; As[lc + 2][lr] = av.z; As[lc + 3][lr] = av.w;
        Bs[lc + 0][lr] = wv.x; Bs[lc + 1][lr] = wv.y; Bs[lc + 2][lr] = wv.z; Bs[lc + 3][lr] = wv.w;
        __syncthreads();
        #pragma unroll
        for (int kk = 0; kk < 8; kk++) {
            float a[8];
            *(float4*)(a)      = *(const float4*)&As[kk][tr];
            *(float4*)(a + 4)  = *(const float4*)&As[kk][tr + 4];
            unsigned long long bb2[4];
            *(ulonglong2*)&bb2[0] = *(const ulonglong2*)&Bs[kk][tc];
            *(ulonglong2*)&bb2[2] = *(const ulonglong2*)&Bs[kk][tc + 4];
            #pragma unroll
            for (int i = 0; i < 8; i++) {
                unsigned long long ap = pack2(a[i], a[i]);
                #pragma unroll
                for (int j = 0; j < 4; j++) ffma2(acc2[i][j], ap, bb2[j]);
            }
        }
        __syncthreads();
    }

    float bias[8];
    #pragma unroll
    for (int j = 0; j < 8; j++) {
        int n = bn + tc + j;
        bias[j] = b1[n] + (b2 ? b2[n] : 0.f);
    }
    #pragma unroll
    for (int i = 0; i < 8; i++) {
        int m = bm + tr + i;
        if (m >= M) break;
        float* cp = C + (size_t)m * N + bn + tc;
        #pragma unroll
        for (int j = 0; j < 4; j++) {
            float lo, hi;
            f32x2_unpack(acc2[i][j], lo, hi);
            cp[j * 2]     = lo + bias[j * 2];
            cp[j * 2 + 1] = hi + bias[j * 2 + 1];
        }
    }
}

// ---------------- gate partial-GEMM helper (f32x2) ----------------
__device__ __forceinline__ void gates_partial(
    const float* sm, int wbase, int xbase, int jg, int bg, int ks, unsigned long long acc[4][4])
{
    const int k0 = ks * 64;
    #pragma unroll 4
    for (int k4 = 0; k4 < 16; k4++) {
        const int k = k0 + (k4 << 2);
        ulonglong2 wv[4], hv[4];
        #pragma unroll
        for (int jj = 0; jj < 4; jj++)
            wv[jj] = *(const ulonglong2*)&sm[wbase + (jj * 4 + jg) * 516 + k];
        #pragma unroll
        for (int bb = 0; bb < 4; bb++)
            hv[bb] = *(const ulonglong2*)&sm[xbase + (bb * 8 + bg) * 516 + k];
        #pragma unroll
        for (int jj = 0; jj < 4; jj++)
            #pragma unroll
            for (int bb = 0; bb < 4; bb++) {
                ffma2(acc[jj][bb], wv[jj].x, hv[bb].x);
                ffma2(acc[jj][bb], wv[jj].y, hv[bb].y);
            }
    }
}

// ---------------- persistent encoder scan ----------------
#define ENC_SMEM_BYTES (28992 * 4)
__global__ void __launch_bounds__(256, 1) enc_scan_kernel(const float* __restrict__ Whh) {
    extern __shared__ float sm[];
    const int tid = threadIdx.x, hG = blockIdx.x;
    const int W0 = 0, HX = 8256, RD = 24768;

    for (int i = tid; i < 16 * 128; i += 256) {
        int r = i >> 7, k4 = i & 127;
        int j = (r >> 2) * Hd + hG * 4 + (r & 3);
        *(float4*)&sm[W0 + r * 516 + k4 * 4] = *(const float4*)&Whh[(size_t)j * Hd + k4 * 4];
    }

    float c_reg = 0.f;
    const int jg = tid & 3, bg = (tid >> 2) & 7, ks = tid >> 5;
    const int hl = tid >> 5, bq = tid & 31;
    unsigned bgen = 0;

    for (int s = 0; s < Ssz; s++) {
        const float* hin = g_h[s & 1];
        float* hout = g_h[(s + 1) & 1];

        float xg[4];
        if (tid < 128) {
            #pragma unroll
            for (int gate = 0; gate < 4; gate++)
                xg[gate] = __ldcg(&g_enc_xg[((size_t)s * Bsz + bq) * FH + gate * Hd + hG * 4 + hl]);
        }

        for (int i = tid; i < 32 * 128; i += 256) {
            int b = i >> 7, k4 = i & 127;
            *(float4*)&sm[HX + b * 516 + k4 * 4] = __ldcg((const float4*)&hin[(b << 9) + k4 * 4]);
        }
        __syncthreads();

        unsigned long long acc[4][4];
        #pragma unroll
        for (int a = 0; a < 4; a++)
            #pragma unroll
            for (int b2 = 0; b2 < 4; b2++) acc[a][b2] = 0ull;
        gates_partial(sm, W0, HX, jg, bg, ks, acc);

        #pragma unroll
        for (int jj = 0; jj < 4; jj++)
            #pragma unroll
            for (int bb = 0; bb < 4; bb++)
                sm[RD + ks * 528 + (jj * 4 + jg) * 33 + bb * 8 + bg] = f32x2_sum(acc[jj][bb]);
        __syncthreads();

        if (tid < 128) {
            float g4[4];
            #pragma unroll
            for (int gate = 0; gate < 4; gate++) {
                int r = gate * 4 + hl;
                float a = 0.f;
                #pragma unroll
                for (int q = 0; q < 8; q++) a += sm[RD + q * 528 + r * 33 + bq];
                g4[gate] = a + xg[gate];
            }
            float cv = sigf(g4[1]) * c_reg + sigf(g4[0]) * tanhf(g4[2]);
            float hn = sigf(g4[3]) * tanhf(cv);
            c_reg = cv;
            hout[(bq << 9) + hG * 4 + hl] = hn;
            g_enc_out[((size_t)bq * Ssz + s) * Hd + hG * 4 + hl] = hn;
        }
        bgen++;
        grid_bar(0, bgen);
    }
    if (tid < 128) {
        g_c[(bq << 9) + hG * 4 + hl] = c_reg;
    }
}

// ---------------- persistent decoder scan (attention fused, online softmax) ----------------
#define DEC_SMEM_BYTES (40464 * 4)
__global__ void __launch_bounds__(256, 1) dec_scan_kernel(
    const float* __restrict__ Wih, const float* __restrict__ Whh,
    const float* __restrict__ attnW, const float* __restrict__ attnv)
{
    extern __shared__ float sm[];
    const int tid = threadIdx.x, hG = blockIdx.x;
    const int W0 = 0, WC = 8256, WA = 16512, HX = 18576, RD = 35088,
              HP = 39312, VS = 39824, SC = 40336;

    for (int i = tid; i < 16 * 128; i += 256) {
        int r = i >> 7, k4 = i & 127;
        int j = (r >> 2) * Hd + hG * 4 + (r & 3);
        *(float4*)&sm[W0 + r * 516 + k4 * 4] = *(const float4*)&Whh[(size_t)j * Hd + k4 * 4];
        *(float4*)&sm[WC + r * 516 + k4 * 4] = *(const float4*)&Wih[(size_t)j * (Ed + Hd) + Ed + k4 * 4];
    }
    for (int i = tid; i < 4 * 128; i += 256) {
        int r = i >> 7, k4 = i & 127;
        *(float4*)&sm[WA + r * 516 + k4 * 4] = *(const float4*)&attnW[(size_t)(hG * 4 + r) * (2 * Hd) + k4 * 4];
    }
    for (int i = tid; i < Hd; i += 256) sm[VS + i] = attnv[i];

    float c_reg = 0.f;
    const int hl = tid >> 5, bq = tid & 31;
    if (tid < 128) c_reg = __ldcg(&g_c[(bq << 9) + hG * 4 + hl]);

    const int jg = tid & 3, bg = (tid >> 2) & 7, ks = tid >> 5;
    const int bB = hG >> 2;
    const int part = hG & 3;
    unsigned bgen = 0;

    for (int t = 0; t < T1; t++) {
        const float* hin = g_h[t & 1];
        float* hout = g_h[(t + 1) & 1];

        // ---- phase A: load h, hproj, gates h-part ----
        for (int i = tid; i < 32 * 128; i += 256) {
            int b = i >> 7, k4 = i & 127;
            *(float4*)&sm[HX + b * 516 + k4 * 4] = __ldcg((const float4*)&hin[(b << 9) + k4 * 4]);
        }
        __syncthreads();
        {
            const int ko = tid >> 6, bh = (tid >> 1) & 31, kh = tid & 1;
            float a = 0.f;
            const int kb = kh << 8;
            #pragma unroll 4
            for (int k = kb; k < kb + 256; k += 4) {
                float4 w4 = *(const float4*)&sm[WA + ko * 516 + k];
                float4 h4 = *(const float4*)&sm[HX + bh * 516 + k];
                a += w4.x * h4.x + w4.y * h4.y + w4.z * h4.z + w4.w * h4.w;
            }
            a += __shfl_xor_sync(0xffffffffu, a, 1);
            if (!kh) g_hproj[(bh << 9) + hG * 4 + ko] = a;
        }
        unsigned long long acc[4][4];
        #pragma unroll
        for (int a2 = 0; a2 < 4; a2++)
            #pragma unroll
            for (int b2 = 0; b2 < 4; b2++) acc[a2][b2] = 0ull;
        gates_partial(sm, W0, HX, jg, bg, ks, acc);
        bgen++; grid_bar(1, bgen);

        // ---- phase B: attention partials for (bB, 32-s chunk `part`) ----
        for (int i = tid; i < Hd; i += 256) sm[HP + i] = __ldcg(&g_hproj[(bB << 9) + i]);
        __syncthreads();
        {
            const int s0 = part * 32, w = tid >> 5, lane = tid & 31;
            #pragma unroll
            for (int q = 0; q < 4; q++) {
                int sl = w * 4 + q;
                const float* ep = g_enc_proj + ((size_t)bB * Ssz + s0 + sl) * Hd;
                float a = 0.f;
                for (int kk = lane; kk < Hd; kk += 32)
                    a += tanh_fast(sm[HP + kk] + ep[kk]) * sm[VS + kk];
                #pragma unroll
                for (int off = 16; off; off >>= 1) a += __shfl_xor_sync(0xffffffffu, a, off);
                if (!lane) sm[SC + sl] = a;
            }
        }
        __syncthreads();
        {
            float mloc = sm[SC + 0];
            #pragma unroll
            for (int i2 = 1; i2 < 32; i2++) mloc = fmaxf(mloc, sm[SC + i2]);
            if (tid < 32) sm[SC + 32 + tid] = expf(sm[SC + tid] - mloc);
            __syncthreads();
            float lloc = 0.f;
            #pragma unroll
            for (int i2 = 0; i2 < 32; i2++) lloc += sm[SC + 32 + i2];

            const int s0 = part * 32;
            float a0 = 0.f, a1 = 0.f;
            const float* eo = g_enc_out + ((size_t)bB * Ssz + s0) * Hd;
            #pragma unroll 4
            for (int s2 = 0; s2 < 32; s2++) {
                float p = sm[SC + 32 + s2];
                a0 += p * eo[(size_t)s2 * Hd + tid];
                a1 += p * eo[(size_t)s2 * Hd + tid + 256];
            }
            float* ap = g_attp[bB][part];
            ap[tid] = a0;
            ap[tid + 256] = a1;
            if (tid == 0) { ap[512] = mloc; ap[513] = lloc; }
        }
        bgen++; grid_bar(1, bgen);

        // ---- phase C: combine 4 partials -> g_ctx ----
        if (tid < 128) {
            const int h = part * 128 + tid;
            float m0 = __ldcg(&g_attp[bB][0][512]);
            float m1 = __ldcg(&g_attp[bB][1][512]);
            float m2 = __ldcg(&g_attp[bB][2][512]);
            float m3 = __ldcg(&g_attp[bB][3][512]);
            float M = fmaxf(fmaxf(m0, m1), fmaxf(m2, m3));
            float w0 = expf(m0 - M), w1 = expf(m1 - M), w2 = expf(m2 - M), w3 = expf(m3 - M);
            float l = w0 * __ldcg(&g_attp[bB][0][513]) + w1 * __ldcg(&g_attp[bB][1][513])
                    + w2 * __ldcg(&g_attp[bB][2][513]) + w3 * __ldcg(&g_attp[bB][3][513]);
            float cx = w0 * __ldcg(&g_attp[bB][0][h]) + w1 * __ldcg(&g_attp[bB][1][h])
                     + w2 * __ldcg(&g_attp[bB][2][h]) + w3 * __ldcg(&g_attp[bB][3][h]);
            g_ctx[(bB << 9) + h] = cx / l;
        }
        bgen++; grid_bar(1, bgen);

        // ---- phase D: gates ctx-part + pointwise ----
        float xg[4];
        if (tid < 128) {
            #pragma unroll
            for (int gate = 0; gate < 4; gate++)
                xg[gate] = __ldcg(&g_dec_xg[((size_t)t * Bsz + bq) * FH + gate * Hd + hG * 4 + hl]);
        }
        for (int i = tid; i < 32 * 128; i += 256) {
            int b = i >> 7, k4 = i & 127;
            *(float4*)&sm[HX + b * 516 + k4 * 4] = __ldcg((const float4*)&g_ctx[(b << 9) + k4 * 4]);
        }
        __syncthreads();
        gates_partial(sm, WC, HX, jg, bg, ks, acc);

        #pragma unroll
        for (int jj = 0; jj < 4; jj++)
            #pragma unroll
            for (int bb = 0; bb < 4; bb++)
                sm[RD + ks * 528 + (jj * 4 + jg) * 33 + bb * 8 + bg] = f32x2_sum(acc[jj][bb]);
        __syncthreads();

        if (tid < 128) {
            float g4[4];
            #pragma unroll
            for (int gate = 0; gate < 4; gate++) {
                int r = gate * 4 + hl;
                float a = 0.f;
                #pragma unroll
                for (int q = 0; q < 8; q++) a += sm[RD + q * 528 + r * 33 + bq];
                g4[gate] = a + xg[gate];
            }
            float cv = sigf(g4[1]) * c_reg + sigf(g4[0]) * tanhf(g4[2]);
            float hn = sigf(g4[3]) * tanhf(cv);
            c_reg = cv;
            hout[(bq << 9) + hG * 4 + hl] = hn;
            // direct fp16 store for the FC GEMM
            size_t mi = ((size_t)bq * T1 + t) * Hd + hG * 4 + hl;
            g_hs_f16[mi] = __float2half_rn(hn);
        }
        bgen++; grid_bar(1, bgen);
    }
}

// ---------------- fc_W fp16 conversion ----------------
__global__ void conv_w_kernel(const float* __restrict__ fc_W) {
    size_t i = ((size_t)blockIdx.x * 256 + threadIdx.x) * 4;
    if (i >= (size_t)Vsz * Hd) return;
    float4 x = *(const float4*)&fc_W[i];
    g_fcw_f16[i + 0] = __float2half_rn(x.x);
    g_fcw_f16[i + 1] = __float2half_rn(x.y);
    g_fcw_f16[i + 2] = __float2half_rn(x.z);
    g_fcw_f16[i + 3] = __float2half_rn(x.w);
}

// ---------------- FC GEMM: single-pass fp16, 64x128 tile, cp.async 2-stage ----------------
// 8 warps = 2(m) x 4(n); warp tile 32x32 (2 m16 x 4 n8). K=512 in 8 chunks of 64.
// Per stage: A(64x72) + B(128x72) fp16 = 27648 B; 2 stages = 55296 B.
#define FCA_B  9216u                     // A tile bytes (64*72*2)
#define FCB_B  18432u                    // B tile bytes (128*72*2)
#define FCSTG  27648u                    // stage bytes
#define FC_SMEM_BYTES (2 * FCSTG)        // 55296
__global__ void __launch_bounds__(256, 2) fc_mma_kernel(
    const float* __restrict__ fc_b, float* __restrict__ out)
{
    extern __shared__ __half smh[];
    const int tid = threadIdx.x, lane = tid & 31, wid = tid >> 5;
    const int wm = wid & 1, wn = wid >> 1;
    const int m0 = blockIdx.x * 64, n0 = blockIdx.y * 128;
    const uint32_t smem_base = smem_to_u32(smh);

    const __half* baseA = g_hs_f16  + (size_t)m0 * Hd;
    const __half* baseB = g_fcw_f16 + (size_t)n0 * Hd;

    float acc[2][4][4];
    #pragma unroll
    for (int a = 0; a < 2; a++)
        #pragma unroll
        for (int b = 0; b < 4; b++)
            #pragma unroll
            for (int c = 0; c < 4; c++) acc[a][b][c] = 0.f;

    const int lrow = ((lane >> 3) & 1) * 8 + (lane & 7);
    const int lcol = (lane >> 4) * 8;

    auto issue_stage = [&](int kc, int stg) {
        uint32_t sb = smem_base + (uint32_t)stg * FCSTG;
        // A tile: 64 rows x 8 16B-chunks = 512 cps
        #pragma unroll
        for (int tt = 0; tt < 2; tt++) {
            int idx = tid + tt * 256;
            int r = idx >> 3, c8 = idx & 7;
            uint32_t doff = (uint32_t)(r * 144 + c8 * 16);
            size_t gi = (size_t)r * Hd + kc * 64 + c8 * 8;
            cp_async16(sb + doff, baseA + gi);
        }
        // B tile: 128 rows x 8 chunks = 1024 cps
        #pragma unroll
        for (int tt = 0; tt < 4; tt++) {
            int idx = tid + tt * 256;
            int r = idx >> 3, c8 = idx & 7;
            uint32_t doff = (uint32_t)(r * 144 + c8 * 16);
            size_t gi = (size_t)r * Hd + kc * 64 + c8 * 8;
            cp_async16(sb + FCA_B + doff, baseB + gi);
        }
        asm volatile("cp.async.commit_group;" ::: "memory");
    };

    issue_stage(0, 0);

    for (int kc = 0; kc < 8; kc++) {
        const int stg = kc & 1;
        if (kc < 7) {
            issue_stage(kc + 1, stg ^ 1);
            asm volatile("cp.async.wait_group 1;" ::: "memory");
        } else {
            asm volatile("cp.async.wait_group 0;" ::: "memory");
        }
        __syncthreads();

        const uint32_t sb = smem_base + (uint32_t)stg * FCSTG;
        #pragma unroll
        for (int kk = 0; kk < 4; kk++) {
            uint32_t a[2][4], b[2][4];
            #pragma unroll
            for (int mt = 0; mt < 2; mt++) {
                uint32_t off = sb + (uint32_t)(((wm * 32 + mt * 16 + lrow) * 72 + kk * 16 + lcol) * 2);
                ldsm_x4(a[mt], off);
            }
            #pragma unroll
            for (int ng = 0; ng < 2; ng++) {
                uint32_t off = sb + FCA_B +
                    (uint32_t)(((wn * 32 + ng * 16 + lrow) * 72 + kk * 16 + lcol) * 2);
                ldsm_x4(b[ng], off);
            }
            #pragma unroll
            for (int mt = 0; mt < 2; mt++)
                #pragma unroll
                for (int ng = 0; ng < 2; ng++) {
                    mma_f16(acc[mt][ng * 2],     a[mt], b[ng][0], b[ng][2]);
                    mma_f16(acc[mt][ng * 2 + 1], a[mt], b[ng][1], b[ng][3]);
                }
        }
        __syncthreads();
    }

    const int rbase = m0 + wm * 32 + (lane >> 2);
    const int cbase = n0 + wn * 32 + (lane & 3) * 2;
    #pragma unroll
    for (int mt = 0; mt < 2; mt++)
        #pragma unroll
        for (int nt = 0; nt < 4; nt++) {
            int c = cbase + nt * 8;
            float b0 = fc_b[c], b1 = fc_b[c + 1];
            int r0 = rbase + mt * 16;
            if (r0 < Mrows) {
                float2 v = make_float2(acc[mt][nt][0] + b0, acc[mt][nt][1] + b1);
                *(float2*)&out[(size_t)r0 * Vsz + c] = v;
            }
            int r1 = r0 + 8;
            if (r1 < Mrows) {
                float2 v = make_float2(acc[mt][nt][2] + b0, acc[mt][nt][3] + b1);
                *(float2*)&out[(size_t)r1 * Vsz + c] = v;
            }
        }
}

// ---------------- launch ----------------
extern "C" void kernel_launch(void* const* d_in, const int* in_sizes, int n_in,
                              void* d_out, int out_size)
{
    const int*   src     = (const int*)d_in[0];
    const int*   tgt     = (const int*)d_in[1];
    const float* embed   = (const float*)d_in[2];
    const float* enc_Wih = (const float*)d_in[3];
    const float* enc_Whh = (const float*)d_in[4];
    const float* enc_bih = (const float*)d_in[5];
    const float* enc_bhh = (const float*)d_in[6];
    const float* dec_Wih = (const float*)d_in[7];
    const float* dec_Whh = (const float*)d_in[8];
    const float* dec_bih = (const float*)d_in[9];
    const float* dec_bhh = (const float*)d_in[10];
    const float* attn_W  = (const float*)d_in[11];
    const float* attn_b  = (const float*)d_in[12];
    const float* attn_v  = (const float*)d_in[13];
    const float* fc_W    = (const float*)d_in[14];
    const float* fc_b    = (const float*)d_in[15];
    float* out = (float*)d_out;

    float *p_src_emb, *p_dec_in, *p_enc_xg, *p_dec_xg, *p_enc_out, *p_enc_proj;
    cudaGetSymbolAddress((void**)&p_src_emb,  g_src_emb);
    cudaGetSymbolAddress((void**)&p_dec_in,   g_dec_in);
    cudaGetSymbolAddress((void**)&p_enc_xg,   g_enc_xg);
    cudaGetSymbolAddress((void**)&p_dec_xg,   g_dec_xg);
    cudaGetSymbolAddress((void**)&p_enc_out,  g_enc_out);
    cudaGetSymbolAddress((void**)&p_enc_proj, g_enc_proj);

    cudaFuncSetAttribute(enc_scan_kernel, cudaFuncAttributeMaxDynamicSharedMemorySize, ENC_SMEM_BYTES);
    cudaFuncSetAttribute(dec_scan_kernel, cudaFuncAttributeMaxDynamicSharedMemorySize, DEC_SMEM_BYTES);
    cudaFuncSetAttribute(fc_mma_kernel,  cudaFuncAttributeMaxDynamicSharedMemorySize, FC_SMEM_BYTES);

    init_state_kernel<<<(Bsz * Hd + 255) / 256, 256>>>();
    gather_src_kernel<<<Ssz * Bsz, Ed>>>(src, embed);
    gather_dec_kernel<<<T1 * Bsz, Ed>>>(tgt, embed);

    conv_w_kernel<<<(Vsz * Hd / 4 + 255) / 256, 256>>>(fc_W);

    {   // enc_xg
        dim3 grid(FH / 128, (Ssz * Bsz + 127) / 128);
        sgemm_bias_kernel<<<grid, 256>>>(p_src_emb, Ed, enc_Wih, Ed, 0,
                                         enc_bih, enc_bhh, p_enc_xg, Ssz * Bsz, FH);
    }
    {   // dec_xg
        dim3 grid(FH / 128, (T1 * Bsz + 127) / 128);
        sgemm_bias_kernel<<<grid, 256>>>(p_dec_in, Ed, dec_Wih, Ed + Hd, 0,
                                         dec_bih, dec_bhh, p_dec_xg, T1 * Bsz, FH);
    }

    enc_scan_kernel<<<NBLK, 256, ENC_SMEM_BYTES>>>(enc_Whh);

    {   // enc_proj
        dim3 grid(Hd / 128, (Bsz * Ssz + 127) / 128);
        sgemm_bias_kernel<<<grid, 256>>>(p_enc_out, Hd, attn_W, 2 * Hd, Hd,
                                         attn_b, nullptr, p_enc_proj, Bsz * Ssz, Hd);
    }

    dec_scan_kernel<<<NBLK, 256, DEC_SMEM_BYTES>>>(dec_Wih, dec_Whh, attn_W, attn_v);

    fc_mma_kernel<<<dim3(MrowsPad / 64, Vsz / 128), 256, FC_SMEM_BYTES>>>(fc_b, out);
}

// round 13
// speedup vs baseline: 1.3162x; 1.0069x over previous
#include <cuda_runtime.h>
#include <cuda_bf16.h>
#include <cuda_fp16.h>
#include <cstddef>
#include <cstdint>

#define Bsz 32
#define Ssz 128
#define Tsz 64
#define T1  63
#define Ed  256
#define Hd  512
#define Vsz 32000
#define FH  2048
#define NBLK 128
#define Mrows 2016       // Bsz*T1
#define MrowsPad 2048

// ---------------- device scratch ----------------
__device__ __align__(16) float g_src_emb[(size_t)Ssz * Bsz * Ed];
__device__ __align__(16) float g_dec_in [(size_t)T1  * Bsz * Ed];
__device__ __align__(16) float g_enc_xg [(size_t)Ssz * Bsz * FH];
__device__ __align__(16) float g_dec_xg [(size_t)T1  * Bsz * FH];
__device__ __align__(16) float g_enc_out[(size_t)Bsz * Ssz * Hd];
__device__ __align__(16) float g_enc_proj[(size_t)Bsz * Ssz * Hd];
__device__ __align__(16) float g_h[2][Bsz * Hd];
__device__ __align__(16) float g_c [Bsz * Hd];
__device__ __align__(16) float g_ctx[Bsz * Hd];
__device__ __align__(16) float g_hproj[Bsz * Hd];
__device__ __align__(16) float g_attp[Bsz][4][516];   // per-part: ctx[512], l@513
__device__ unsigned g_cnt[2];
__device__ unsigned g_gen[2];
// fp16 operands for the FC tensor GEMM (single-pass)
__device__ __align__(16) __half g_hs_f16 [(size_t)MrowsPad * Hd];
__device__ __align__(16) __half g_fcw_f16[(size_t)Vsz * Hd];

__device__ __forceinline__ float sigf(float x) { return 1.0f / (1.0f + expf(-x)); }
__device__ __forceinline__ float tanh_fast(float x) {
    float y;
    asm("tanh.approx.f32 %0, %1;" : "=f"(y) : "f"(x));
    return y;
}

// ---------------- packed f32x2 FMA ----------------
__device__ __forceinline__ void ffma2(unsigned long long& d, unsigned long long a, unsigned long long b) {
    asm("fma.rn.f32x2 %0, %1, %2, %0;" : "+l"(d) : "l"(a), "l"(b));
}
__device__ __forceinline__ float f32x2_sum(unsigned long long v) {
    float lo, hi;
    asm("mov.b64 {%0, %1}, %2;" : "=f"(lo), "=f"(hi) : "l"(v));
    return lo + hi;
}
__device__ __forceinline__ void f32x2_unpack(unsigned long long v, float& lo, float& hi) {
    asm("mov.b64 {%0, %1}, %2;" : "=f"(lo), "=f"(hi) : "l"(v));
}
__device__ __forceinline__ unsigned long long pack2(float lo, float hi) {
    unsigned long long v;
    asm("mov.b64 %0, {%1, %2};" : "=l"(v) : "f"(lo), "f"(hi));
    return v;
}

__device__ __forceinline__ uint32_t smem_to_u32(const void* p) {
    uint32_t a;
    asm("{ .reg .u64 t; cvta.to.shared.u64 t, %1; cvt.u32.u64 %0, t; }" : "=r"(a) : "l"(p));
    return a;
}
__device__ __forceinline__ void ldsm_x4(uint32_t* r, uint32_t addr) {
    asm volatile("ldmatrix.sync.aligned.m8n8.x4.shared.b16 {%0,%1,%2,%3}, [%4];"
        : "=r"(r[0]), "=r"(r[1]), "=r"(r[2]), "=r"(r[3]) : "r"(addr));
}
__device__ __forceinline__ void mma_f16(float* d, const uint32_t* a, uint32_t b0, uint32_t b1) {
    asm volatile("mma.sync.aligned.m16n8k16.row.col.f32.f16.f16.f32 "
        "{%0,%1,%2,%3}, {%4,%5,%6,%7}, {%8,%9}, {%0,%1,%2,%3};"
        : "+f"(d[0]), "+f"(d[1]), "+f"(d[2]), "+f"(d[3])
        : "r"(a[0]), "r"(a[1]), "r"(a[2]), "r"(a[3]), "r"(b0), "r"(b1));
}
__device__ __forceinline__ void cp_async16(uint32_t dst, const void* src) {
    asm volatile("cp.async.cg.shared.global [%0], [%1], 16;" :: "r"(dst), "l"(src) : "memory");
}

// ---------------- global barrier: atomic arrivals + single-hop atomic release,
// but pollers use plain volatile LOADS (no L2-atomic-ALU serialization) ----------------
__device__ __forceinline__ void grid_bar(int which, unsigned target) {
    __threadfence();
    __syncthreads();
    if (threadIdx.x == 0) {
        unsigned arr = atomicAdd(&g_cnt[which], 1u);
        if (arr == NBLK - 1u) {
            g_cnt[which] = 0u;
            __threadfence();
            atomicAdd(&g_gen[which], 1u);
        } else {
            const volatile unsigned* gp = (const volatile unsigned*)&g_gen[which];
            while (*gp < target) { }
        }
    }
    __syncthreads();
}

__global__ void init_state_kernel() {
    int i = blockIdx.x * blockDim.x + threadIdx.x;
    if (i < Bsz * Hd) g_h[0][i] = 0.f;
    if (i < 2) { g_cnt[i] = 0u; g_gen[i] = 0u; }
    // zero the M-padding rows of hs_f16 (rows 2016..2047)
    if (i < (MrowsPad - Mrows) * Hd) {
        g_hs_f16[(size_t)Mrows * Hd + i] = __float2half(0.f);
    }
}

// ---------------- embedding gathers ----------------
__global__ void gather_src_kernel(const int* __restrict__ src, const float* __restrict__ embed) {
    int row = blockIdx.x;           // s*B + b
    int s = row >> 5, b = row & 31;
    int idx = src[b * Ssz + s];
    g_src_emb[(size_t)row * Ed + threadIdx.x] = embed[(size_t)idx * Ed + threadIdx.x];
}
__global__ void gather_dec_kernel(const int* __restrict__ tgt, const float* __restrict__ embed) {
    int row = blockIdx.x;           // t*B + b
    int t = row >> 5, b = row & 31;
    int idx = tgt[b * Tsz + t];
    g_dec_in[(size_t)row * Ed + threadIdx.x] = embed[(size_t)idx * Ed + threadIdx.x];
}

// ---------------- fp32 SGEMM with f32x2 FMA (small GEMMs) ----------------
__global__ void __launch_bounds__(256) sgemm_bias_kernel(
    const float* __restrict__ A, int K,
    const float* __restrict__ W, int ldw, int woff,
    const float* __restrict__ b1, const float* __restrict__ b2,
    float* __restrict__ C, int M, int N)
{
    __shared__ __align__(16) float As[8][128];
    __shared__ __align__(16) float Bs[8][128];
    const int bm = blockIdx.y * 128;
    const int bn = blockIdx.x * 128;
    const int t  = threadIdx.x;
    const int tr = (t >> 4) * 8;
    const int tc = (t & 15) * 8;
    const int lr = t >> 1;
    const int lc = (t & 1) * 4;

    unsigned long long acc2[8][4];
    #pragma unroll
    for (int i = 0; i < 8; i++)
        #pragma unroll
        for (int j = 0; j < 4; j++) acc2[i][j] = 0ull;

    const bool aValid = (bm + lr) < M;
    const float* aRow = A + (size_t)(bm + lr) * K + lc;
    const float* wRow = W + (size_t)(bn + lr) * ldw + woff + lc;

    for (int k0 = 0; k0 < K; k0 += 8) {
        float4 av = aValid ? *(const float4*)(aRow + k0) : make_float4(0.f, 0.f, 0.f, 0.f);
        float4 wv = *(const float4*)(wRow + k0);
        As[lc + 0][lr] = av.x; As[lc + 1][lr] = av.y; As[lc + 2][lr] = av.z; As[lc + 3][lr] = av.w;
        Bs[lc + 0][lr] = wv.x; Bs[lc + 1][lr] = wv.y; Bs[lc + 2][lr] = wv.z; Bs[lc + 3][lr] = wv.w;
        __syncthreads();
        #pragma unroll
        for (int kk = 0; kk < 8; kk++) {
            float a[8];
            *(float4*)(a)      = *(const float4*)&As[kk][tr];
            *(float4*)(a + 4)  = *(const float4*)&As[kk][tr + 4];
            unsigned long long bb2[4];
            *(ulonglong2*)&bb2[0] = *(const ulonglong2*)&Bs[kk][tc];
            *(ulonglong2*)&bb2[2] = *(const ulonglong2*)&Bs[kk][tc + 4];
            #pragma unroll
            for (int i = 0; i < 8; i++) {
                unsigned long long ap = pack2(a[i], a[i]);
                #pragma unroll
                for (int j = 0; j < 4; j++) ffma2(acc2[i][j], ap, bb2[j]);
            }
        }
        __syncthreads();
    }

    float bias[8];
    #pragma unroll
    for (int j = 0; j < 8; j++) {
        int n = bn + tc + j;
        bias[j] = b1[n] + (b2 ? b2[n] : 0.f);
    }
    #pragma unroll
    for (int i = 0; i < 8; i++) {
        int m = bm + tr + i;
        if (m >= M) break;
        float* cp = C + (size_t)m * N + bn + tc;
        #pragma unroll
        for (int j = 0; j < 4; j++) {
            float lo, hi;
            f32x2_unpack(acc2[i][j], lo, hi);
            cp[j * 2]     = lo + bias[j * 2];
            cp[j * 2 + 1] = hi + bias[j * 2 + 1];
        }
    }
}

// ---------------- gate partial-GEMM helper (f32x2) ----------------
__device__ __forceinline__ void gates_partial(
    const float* sm, int wbase, int xbase, int jg, int bg, int ks, unsigned long long acc[4][4])
{
    const int k0 = ks * 64;
    #pragma unroll 4
    for (int k4 = 0; k4 < 16; k4++) {
        const int k = k0 + (k4 << 2);
        ulonglong2 wv[4], hv[4];
        #pragma unroll
        for (int jj = 0; jj < 4; jj++)
            wv[jj] = *(const ulonglong2*)&sm[wbase + (jj * 4 + jg) * 516 + k];
        #pragma unroll
        for (int bb = 0; bb < 4; bb++)
            hv[bb] = *(const ulonglong2*)&sm[xbase + (bb * 8 + bg) * 516 + k];
        #pragma unroll
        for (int jj = 0; jj < 4; jj++)
            #pragma unroll
            for (int bb = 0; bb < 4; bb++) {
                ffma2(acc[jj][bb], wv[jj].x, hv[bb].x);
                ffma2(acc[jj][bb], wv[jj].y, hv[bb].y);
            }
    }
}

// ---------------- persistent encoder scan ----------------
#define ENC_SMEM_BYTES (28992 * 4)
__global__ void __launch_bounds__(256, 1) enc_scan_kernel(const float* __restrict__ Whh) {
    extern __shared__ float sm[];
    const int tid = threadIdx.x, hG = blockIdx.x;
    const int W0 = 0, HX = 8256, RD = 24768;

    for (int i = tid; i < 16 * 128; i += 256) {
        int r = i >> 7, k4 = i & 127;
        int j = (r >> 2) * Hd + hG * 4 + (r & 3);
        *(float4*)&sm[W0 + r * 516 + k4 * 4] = *(const float4*)&Whh[(size_t)j * Hd + k4 * 4];
    }

    float c_reg = 0.f;
    const int jg = tid & 3, bg = (tid >> 2) & 7, ks = tid >> 5;
    const int hl = tid >> 5, bq = tid & 31;
    unsigned bgen = 0;

    for (int s = 0; s < Ssz; s++) {
        const float* hin = g_h[s & 1];
        float* hout = g_h[(s + 1) & 1];

        float xg[4];
        if (tid < 128) {
            #pragma unroll
            for (int gate = 0; gate < 4; gate++)
                xg[gate] = __ldcg(&g_enc_xg[((size_t)s * Bsz + bq) * FH + gate * Hd + hG * 4 + hl]);
        }

        for (int i = tid; i < 32 * 128; i += 256) {
            int b = i >> 7, k4 = i & 127;
            *(float4*)&sm[HX + b * 516 + k4 * 4] = __ldcg((const float4*)&hin[(b << 9) + k4 * 4]);
        }
        __syncthreads();

        unsigned long long acc[4][4];
        #pragma unroll
        for (int a = 0; a < 4; a++)
            #pragma unroll
            for (int b2 = 0; b2 < 4; b2++) acc[a][b2] = 0ull;
        gates_partial(sm, W0, HX, jg, bg, ks, acc);

        #pragma unroll
        for (int jj = 0; jj < 4; jj++)
            #pragma unroll
            for (int bb = 0; bb < 4; bb++)
                sm[RD + ks * 528 + (jj * 4 + jg) * 33 + bb * 8 + bg] = f32x2_sum(acc[jj][bb]);
        __syncthreads();

        if (tid < 128) {
            float g4[4];
            #pragma unroll
            for (int gate = 0; gate < 4; gate++) {
                int r = gate * 4 + hl;
                float a = 0.f;
                #pragma unroll
                for (int q = 0; q < 8; q++) a += sm[RD + q * 528 + r * 33 + bq];
                g4[gate] = a + xg[gate];
            }
            float cv = sigf(g4[1]) * c_reg + sigf(g4[0]) * tanhf(g4[2]);
            float hn = sigf(g4[3]) * tanhf(cv);
            c_reg = cv;
            hout[(bq << 9) + hG * 4 + hl] = hn;
            g_enc_out[((size_t)bq * Ssz + s) * Hd + hG * 4 + hl] = hn;
        }
        bgen++;
        grid_bar(0, bgen);
    }
    if (tid < 128) {
        g_c[(bq << 9) + hG * 4 + hl] = c_reg;
    }
}

// ---------------- persistent decoder scan (attention fused, no-max softmax) ----------------
#define DEC_SMEM_BYTES (40464 * 4)
__global__ void __launch_bounds__(256, 1) dec_scan_kernel(
    const float* __restrict__ Wih, const float* __restrict__ Whh,
    const float* __restrict__ attnW, const float* __restrict__ attnv)
{
    extern __shared__ float sm[];
    const int tid = threadIdx.x, hG = blockIdx.x;
    const int W0 = 0, WC = 8256, WA = 16512, HX = 18576, RD = 35088,
              HP = 39312, VS = 39824, SC = 40336;

    for (int i = tid; i < 16 * 128; i += 256) {
        int r = i >> 7, k4 = i & 127;
        int j = (r >> 2) * Hd + hG * 4 + (r & 3);
        *(float4*)&sm[W0 + r * 516 + k4 * 4] = *(const float4*)&Whh[(size_t)j * Hd + k4 * 4];
        *(float4*)&sm[WC + r * 516 + k4 * 4] = *(const float4*)&Wih[(size_t)j * (Ed + Hd) + Ed + k4 * 4];
    }
    for (int i = tid; i < 4 * 128; i += 256) {
        int r = i >> 7, k4 = i & 127;
        *(float4*)&sm[WA + r * 516 + k4 * 4] = *(const float4*)&attnW[(size_t)(hG * 4 + r) * (2 * Hd) + k4 * 4];
    }
    for (int i = tid; i < Hd; i += 256) sm[VS + i] = attnv[i];

    float c_reg = 0.f;
    const int hl = tid >> 5, bq = tid & 31;
    if (tid < 128) c_reg = __ldcg(&g_c[(bq << 9) + hG * 4 + hl]);

    const int jg = tid & 3, bg = (tid >> 2) & 7, ks = tid >> 5;
    const int bB = hG >> 2;
    const int part = hG & 3;
    unsigned bgen = 0;

    for (int t = 0; t < T1; t++) {
        const float* hin = g_h[t & 1];
        float* hout = g_h[(t + 1) & 1];

        // ---- phase A: load h, hproj, gates h-part ----
        for (int i = tid; i < 32 * 128; i += 256) {
            int b = i >> 7, k4 = i & 127;
            *(float4*)&sm[HX + b * 516 + k4 * 4] = __ldcg((const float4*)&hin[(b << 9) + k4 * 4]);
        }
        __syncthreads();
        {
            const int ko = tid >> 6, bh = (tid >> 1) & 31, kh = tid & 1;
            float a = 0.f;
            const int kb = kh << 8;
            #pragma unroll 4
            for (int k = kb; k < kb + 256; k += 4) {
                float4 w4 = *(const float4*)&sm[WA + ko * 516 + k];
                float4 h4 = *(const float4*)&sm[HX + bh * 516 + k];
                a += w4.x * h4.x + w4.y * h4.y + w4.z * h4.z + w4.w * h4.w;
            }
            a += __shfl_xor_sync(0xffffffffu, a, 1);
            if (!kh) g_hproj[(bh << 9) + hG * 4 + ko] = a;
        }
        unsigned long long acc[4][4];
        #pragma unroll
        for (int a2 = 0; a2 < 4; a2++)
            #pragma unroll
            for (int b2 = 0; b2 < 4; b2++) acc[a2][b2] = 0ull;
        gates_partial(sm, W0, HX, jg, bg, ks, acc);
        bgen++; grid_bar(1, bgen);

        // ---- phase B: attention partials for (bB, 32-s chunk `part`) ----
        for (int i = tid; i < Hd; i += 256) sm[HP + i] = __ldcg(&g_hproj[(bB << 9) + i]);
        __syncthreads();
        {
            const int s0 = part * 32, w = tid >> 5, lane = tid & 31;
            #pragma unroll
            for (int q = 0; q < 4; q++) {
                int sl = w * 4 + q;
                const float* ep = g_enc_proj + ((size_t)bB * Ssz + s0 + sl) * Hd;
                float a = 0.f;
                for (int kk = lane; kk < Hd; kk += 32)
                    a += tanh_fast(sm[HP + kk] + ep[kk]) * sm[VS + kk];
                #pragma unroll
                for (int off = 16; off; off >>= 1) a += __shfl_xor_sync(0xffffffffu, a, off);
                if (!lane) sm[SC + sl] = a;
            }
        }
        __syncthreads();
        {
            // no-max softmax: scores are O(+-10), exp overflow-free in fp32
            if (tid < 32) sm[SC + 32 + tid] = __expf(sm[SC + tid]);
            __syncthreads();
            float lloc = 0.f;
            #pragma unroll
            for (int i2 = 0; i2 < 32; i2++) lloc += sm[SC + 32 + i2];

            const int s0 = part * 32;
            float a0 = 0.f, a1 = 0.f;
            const float* eo = g_enc_out + ((size_t)bB * Ssz + s0) * Hd;
            #pragma unroll 4
            for (int s2 = 0; s2 < 32; s2++) {
                float p = sm[SC + 32 + s2];
                a0 += p * eo[(size_t)s2 * Hd + tid];
                a1 += p * eo[(size_t)s2 * Hd + tid + 256];
            }
            float* ap = g_attp[bB][part];
            ap[tid] = a0;
            ap[tid + 256] = a1;
            if (tid == 0) ap[513] = lloc;
        }
        bgen++; grid_bar(1, bgen);

        // ---- phase C: combine 4 partials -> g_ctx ----
        if (tid < 128) {
            const int h = part * 128 + tid;
            float l = __ldcg(&g_attp[bB][0][513]) + __ldcg(&g_attp[bB][1][513])
                    + __ldcg(&g_attp[bB][2][513]) + __ldcg(&g_attp[bB][3][513]);
            float cx = __ldcg(&g_attp[bB][0][h]) + __ldcg(&g_attp[bB][1][h])
                     + __ldcg(&g_attp[bB][2][h]) + __ldcg(&g_attp[bB][3][h]);
            g_ctx[(bB << 9) + h] = cx / l;
        }
        bgen++; grid_bar(1, bgen);

        // ---- phase D: gates ctx-part + pointwise ----
        float xg[4];
        if (tid < 128) {
            #pragma unroll
            for (int gate = 0; gate < 4; gate++)
                xg[gate] = __ldcg(&g_dec_xg[((size_t)t * Bsz + bq) * FH + gate * Hd + hG * 4 + hl]);
        }
        for (int i = tid; i < 32 * 128; i += 256) {
            int b = i >> 7, k4 = i & 127;
            *(float4*)&sm[HX + b * 516 + k4 * 4] = __ldcg((const float4*)&g_ctx[(b << 9) + k4 * 4]);
        }
        __syncthreads();
        gates_partial(sm, WC, HX, jg, bg, ks, acc);

        #pragma unroll
        for (int jj = 0; jj < 4; jj++)
            #pragma unroll
            for (int bb = 0; bb < 4; bb++)
                sm[RD + ks * 528 + (jj * 4 + jg) * 33 + bb * 8 + bg] = f32x2_sum(acc[jj][bb]);
        __syncthreads();

        if (tid < 128) {
            float g4[4];
            #pragma unroll
            for (int gate = 0; gate < 4; gate++) {
                int r = gate * 4 + hl;
                float a = 0.f;
                #pragma unroll
                for (int q = 0; q < 8; q++) a += sm[RD + q * 528 + r * 33 + bq];
                g4[gate] = a + xg[gate];
            }
            float cv = sigf(g4[1]) * c_reg + sigf(g4[0]) * tanhf(g4[2]);
            float hn = sigf(g4[3]) * tanhf(cv);
            c_reg = cv;
            hout[(bq << 9) + hG * 4 + hl] = hn;
            // direct fp16 store for the FC GEMM
            size_t mi = ((size_t)bq * T1 + t) * Hd + hG * 4 + hl;
            g_hs_f16[mi] = __float2half_rn(hn);
        }
        bgen++; grid_bar(1, bgen);
    }
}

// ---------------- fc_W fp16 conversion ----------------
__global__ void conv_w_kernel(const float* __restrict__ fc_W) {
    size_t i = ((size_t)blockIdx.x * 256 + threadIdx.x) * 4;
    if (i >= (size_t)Vsz * Hd) return;
    float4 x = *(const float4*)&fc_W[i];
    g_fcw_f16[i + 0] = __float2half_rn(x.x);
    g_fcw_f16[i + 1] = __float2half_rn(x.y);
    g_fcw_f16[i + 2] = __float2half_rn(x.z);
    g_fcw_f16[i + 3] = __float2half_rn(x.w);
}

// ---------------- FC GEMM: single-pass fp16, 64x128 tile, cp.async 2-stage ----------------
#define FCA_B  9216u                     // A tile bytes (64*72*2)
#define FCB_B  18432u                    // B tile bytes (128*72*2)
#define FCSTG  27648u                    // stage bytes
#define FC_SMEM_BYTES (2 * FCSTG)        // 55296
__global__ void __launch_bounds__(256, 2) fc_mma_kernel(
    const float* __restrict__ fc_b, float* __restrict__ out)
{
    extern __shared__ __half smh[];
    const int tid = threadIdx.x, lane = tid & 31, wid = tid >> 5;
    const int wm = wid & 1, wn = wid >> 1;
    const int m0 = blockIdx.x * 64, n0 = blockIdx.y * 128;
    const uint32_t smem_base = smem_to_u32(smh);

    const __half* baseA = g_hs_f16  + (size_t)m0 * Hd;
    const __half* baseB = g_fcw_f16 + (size_t)n0 * Hd;

    float acc[2][4][4];
    #pragma unroll
    for (int a = 0; a < 2; a++)
        #pragma unroll
        for (int b = 0; b < 4; b++)
            #pragma unroll
            for (int c = 0; c < 4; c++) acc[a][b][c] = 0.f;

    const int lrow = ((lane >> 3) & 1) * 8 + (lane & 7);
    const int lcol = (lane >> 4) * 8;

    auto issue_stage = [&](int kc, int stg) {
        uint32_t sb = smem_base + (uint32_t)stg * FCSTG;
        #pragma unroll
        for (int tt = 0; tt < 2; tt++) {
            int idx = tid + tt * 256;
            int r = idx >> 3, c8 = idx & 7;
            uint32_t doff = (uint32_t)(r * 144 + c8 * 16);
            size_t gi = (size_t)r * Hd + kc * 64 + c8 * 8;
            cp_async16(sb + doff, baseA + gi);
        }
        #pragma unroll
        for (int tt = 0; tt < 4; tt++) {
            int idx = tid + tt * 256;
            int r = idx >> 3, c8 = idx & 7;
            uint32_t doff = (uint32_t)(r * 144 + c8 * 16);
            size_t gi = (size_t)r * Hd + kc * 64 + c8 * 8;
            cp_async16(sb + FCA_B + doff, baseB + gi);
        }
        asm volatile("cp.async.commit_group;" ::: "memory");
    };

    issue_stage(0, 0);

    for (int kc = 0; kc < 8; kc++) {
        const int stg = kc & 1;
        if (kc < 7) {
            issue_stage(kc + 1, stg ^ 1);
            asm volatile("cp.async.wait_group 1;" ::: "memory");
        } else {
            asm volatile("cp.async.wait_group 0;" ::: "memory");
        }
        __syncthreads();

        const uint32_t sb = smem_base + (uint32_t)stg * FCSTG;
        #pragma unroll
        for (int kk = 0; kk < 4; kk++) {
            uint32_t a[2][4], b[2][4];
            #pragma unroll
            for (int mt = 0; mt < 2; mt++) {
                uint32_t off = sb + (uint32_t)(((wm * 32 + mt * 16 + lrow) * 72 + kk * 16 + lcol) * 2);
                ldsm_x4(a[mt], off);
            }
            #pragma unroll
            for (int ng = 0; ng < 2; ng++) {
                uint32_t off = sb + FCA_B +
                    (uint32_t)(((wn * 32 + ng * 16 + lrow) * 72 + kk * 16 + lcol) * 2);
                ldsm_x4(b[ng], off);
            }
            #pragma unroll
            for (int mt = 0; mt < 2; mt++)
                #pragma unroll
                for (int ng = 0; ng < 2; ng++) {
                    mma_f16(acc[mt][ng * 2],     a[mt], b[ng][0], b[ng][2]);
                    mma_f16(acc[mt][ng * 2 + 1], a[mt], b[ng][1], b[ng][3]);
                }
        }
        __syncthreads();
    }

    const int rbase = m0 + wm * 32 + (lane >> 2);
    const int cbase = n0 + wn * 32 + (lane & 3) * 2;
    #pragma unroll
    for (int mt = 0; mt < 2; mt++)
        #pragma unroll
        for (int nt = 0; nt < 4; nt++) {
            int c = cbase + nt * 8;
            float b0 = fc_b[c], b1 = fc_b[c + 1];
            int r0 = rbase + mt * 16;
            if (r0 < Mrows) {
                float2 v = make_float2(acc[mt][nt][0] + b0, acc[mt][nt][1] + b1);
                *(float2*)&out[(size_t)r0 * Vsz + c] = v;
            }
            int r1 = r0 + 8;
            if (r1 < Mrows) {
                float2 v = make_float2(acc[mt][nt][2] + b0, acc[mt][nt][3] + b1);
                *(float2*)&out[(size_t)r1 * Vsz + c] = v;
            }
        }
}

// ---------------- launch ----------------
extern "C" void kernel_launch(void* const* d_in, const int* in_sizes, int n_in,
                              void* d_out, int out_size)
{
    const int*   src     = (const int*)d_in[0];
    const int*   tgt     = (const int*)d_in[1];
    const float* embed   = (const float*)d_in[2];
    const float* enc_Wih = (const float*)d_in[3];
    const float* enc_Whh = (const float*)d_in[4];
    const float* enc_bih = (const float*)d_in[5];
    const float* enc_bhh = (const float*)d_in[6];
    const float* dec_Wih = (const float*)d_in[7];
    const float* dec_Whh = (const float*)d_in[8];
    const float* dec_bih = (const float*)d_in[9];
    const float* dec_bhh = (const float*)d_in[10];
    const float* attn_W  = (const float*)d_in[11];
    const float* attn_b  = (const float*)d_in[12];
    const float* attn_v  = (const float*)d_in[13];
    const float* fc_W    = (const float*)d_in[14];
    const float* fc_b    = (const float*)d_in[15];
    float* out = (float*)d_out;

    float *p_src_emb, *p_dec_in, *p_enc_xg, *p_dec_xg, *p_enc_out, *p_enc_proj;
    cudaGetSymbolAddress((void**)&p_src_emb,  g_src_emb);
    cudaGetSymbolAddress((void**)&p_dec_in,   g_dec_in);
    cudaGetSymbolAddress((void**)&p_enc_xg,   g_enc_xg);
    cudaGetSymbolAddress((void**)&p_dec_xg,   g_dec_xg);
    cudaGetSymbolAddress((void**)&p_enc_out,  g_enc_out);
    cudaGetSymbolAddress((void**)&p_enc_proj, g_enc_proj);

    cudaFuncSetAttribute(enc_scan_kernel, cudaFuncAttributeMaxDynamicSharedMemorySize, ENC_SMEM_BYTES);
    cudaFuncSetAttribute(dec_scan_kernel, cudaFuncAttributeMaxDynamicSharedMemorySize, DEC_SMEM_BYTES);
    cudaFuncSetAttribute(fc_mma_kernel,  cudaFuncAttributeMaxDynamicSharedMemorySize, FC_SMEM_BYTES);

    init_state_kernel<<<(Bsz * Hd + 255) / 256, 256>>>();
    gather_src_kernel<<<Ssz * Bsz, Ed>>>(src, embed);
    gather_dec_kernel<<<T1 * Bsz, Ed>>>(tgt, embed);

    conv_w_kernel<<<(Vsz * Hd / 4 + 255) / 256, 256>>>(fc_W);

    {   // enc_xg
        dim3 grid(FH / 128, (Ssz * Bsz + 127) / 128);
        sgemm_bias_kernel<<<grid, 256>>>(p_src_emb, Ed, enc_Wih, Ed, 0,
                                         enc_bih, enc_bhh, p_enc_xg, Ssz * Bsz, FH);
    }
    {   // dec_xg
        dim3 grid(FH / 128, (T1 * Bsz + 127) / 128);
        sgemm_bias_kernel<<<grid, 256>>>(p_dec_in, Ed, dec_Wih, Ed + Hd, 0,
                                         dec_bih, dec_bhh, p_dec_xg, T1 * Bsz, FH);
    }

    enc_scan_kernel<<<NBLK, 256, ENC_SMEM_BYTES>>>(enc_Whh);

    {   // enc_proj
        dim3 grid(Hd / 128, (Bsz * Ssz + 127) / 128);
        sgemm_bias_kernel<<<grid, 256>>>(p_enc_out, Hd, attn_W, 2 * Hd, Hd,
                                         attn_b, nullptr, p_enc_proj, Bsz * Ssz, Hd);
    }

    dec_scan_kernel<<<NBLK, 256, DEC_SMEM_BYTES>>>(dec_Wih, dec_Whh, attn_W, attn_v);

    fc_mma_kernel<<<dim3(MrowsPad / 64, Vsz / 128), 256, FC_SMEM_BYTES>>>(fc_b, out);
}

// round 14
// speedup vs baseline: 1.3268x; 1.0081x over previous
#include <cuda_runtime.h>
#include <cuda_bf16.h>
#include <cuda_fp16.h>
#include <cstddef>
#include <cstdint>

#define Bsz 32
#define Ssz 128
#define Tsz 64
#define T1  63
#define Ed  256
#define Hd  512
#define Vsz 32000
#define FH  2048
#define NBLK 128
#define Mrows 2016       // Bsz*T1
#define MrowsPad 2048

// ---------------- device scratch ----------------
__device__ __align__(16) float g_src_emb[(size_t)Ssz * Bsz * Ed];
__device__ __align__(16) float g_dec_in [(size_t)T1  * Bsz * Ed];
__device__ __align__(16) float g_enc_xg [(size_t)Ssz * Bsz * FH];
__device__ __align__(16) float g_dec_xg [(size_t)T1  * Bsz * FH];
__device__ __align__(16) float g_enc_out[(size_t)Bsz * Ssz * Hd];
__device__ __align__(16) float g_enc_proj[(size_t)Bsz * Ssz * Hd];
__device__ __align__(16) float g_h[2][Bsz * Hd];
__device__ __align__(16) float g_c [Bsz * Hd];
__device__ __align__(16) float g_ctx[Bsz * Hd];
__device__ __align__(16) float g_hproj[Bsz * Hd];
__device__ __align__(16) float g_attp[Bsz][4][516];   // per-part: ctx[512], l@513
__device__ unsigned g_cnt[2];
__device__ unsigned g_gen[2];
// fp16 operands for the FC tensor GEMM (single-pass)
__device__ __align__(16) __half g_hs_f16 [(size_t)MrowsPad * Hd];
__device__ __align__(16) __half g_fcw_f16[(size_t)Vsz * Hd];

__device__ __forceinline__ float sigf(float x) { return 1.0f / (1.0f + expf(-x)); }
__device__ __forceinline__ float tanh_fast(float x) {
    float y;
    asm("tanh.approx.f32 %0, %1;" : "=f"(y) : "f"(x));
    return y;
}

// ---------------- packed f32x2 FMA ----------------
__device__ __forceinline__ void ffma2(unsigned long long& d, unsigned long long a, unsigned long long b) {
    asm("fma.rn.f32x2 %0, %1, %2, %0;" : "+l"(d) : "l"(a), "l"(b));
}
__device__ __forceinline__ float f32x2_sum(unsigned long long v) {
    float lo, hi;
    asm("mov.b64 {%0, %1}, %2;" : "=f"(lo), "=f"(hi) : "l"(v));
    return lo + hi;
}
__device__ __forceinline__ void f32x2_unpack(unsigned long long v, float& lo, float& hi) {
    asm("mov.b64 {%0, %1}, %2;" : "=f"(lo), "=f"(hi) : "l"(v));
}
__device__ __forceinline__ unsigned long long pack2(float lo, float hi) {
    unsigned long long v;
    asm("mov.b64 %0, {%1, %2};" : "=l"(v) : "f"(lo), "f"(hi));
    return v;
}

__device__ __forceinline__ uint32_t smem_to_u32(const void* p) {
    uint32_t a;
    asm("{ .reg .u64 t; cvta.to.shared.u64 t, %1; cvt.u32.u64 %0, t; }" : "=r"(a) : "l"(p));
    return a;
}
__device__ __forceinline__ void ldsm_x4(uint32_t* r, uint32_t addr) {
    asm volatile("ldmatrix.sync.aligned.m8n8.x4.shared.b16 {%0,%1,%2,%3}, [%4];"
        : "=r"(r[0]), "=r"(r[1]), "=r"(r[2]), "=r"(r[3]) : "r"(addr));
}
__device__ __forceinline__ void mma_f16(float* d, const uint32_t* a, uint32_t b0, uint32_t b1) {
    asm volatile("mma.sync.aligned.m16n8k16.row.col.f32.f16.f16.f32 "
        "{%0,%1,%2,%3}, {%4,%5,%6,%7}, {%8,%9}, {%0,%1,%2,%3};"
        : "+f"(d[0]), "+f"(d[1]), "+f"(d[2]), "+f"(d[3])
        : "r"(a[0]), "r"(a[1]), "r"(a[2]), "r"(a[3]), "r"(b0), "r"(b1));
}
__device__ __forceinline__ void cp_async16(uint32_t dst, const void* src) {
    asm volatile("cp.async.cg.shared.global [%0], [%1], 16;" :: "r"(dst), "l"(src) : "memory");
}

// ---------------- global barrier ----------------
__device__ __forceinline__ void grid_bar(int which, unsigned target) {
    __threadfence();
    __syncthreads();
    if (threadIdx.x == 0) {
        unsigned arr = atomicAdd(&g_cnt[which], 1u);
        if (arr == NBLK - 1u) {
            g_cnt[which] = 0u;
            __threadfence();
            atomicAdd(&g_gen[which], 1u);
        } else {
            const volatile unsigned* gp = (const volatile unsigned*)&g_gen[which];
            while (*gp < target) { }
        }
    }
    __syncthreads();
}

__global__ void init_state_kernel() {
    int i = blockIdx.x * blockDim.x + threadIdx.x;
    if (i < Bsz * Hd) g_h[0][i] = 0.f;
    if (i < 2) { g_cnt[i] = 0u; g_gen[i] = 0u; }
    if (i < (MrowsPad - Mrows) * Hd) {
        g_hs_f16[(size_t)Mrows * Hd + i] = __float2half(0.f);
    }
}

// ---------------- embedding gathers ----------------
__global__ void gather_src_kernel(const int* __restrict__ src, const float* __restrict__ embed) {
    int row = blockIdx.x;           // s*B + b
    int s = row >> 5, b = row & 31;
    int idx = src[b * Ssz + s];
    g_src_emb[(size_t)row * Ed + threadIdx.x] = embed[(size_t)idx * Ed + threadIdx.x];
}
__global__ void gather_dec_kernel(const int* __restrict__ tgt, const float* __restrict__ embed) {
    int row = blockIdx.x;           // t*B + b
    int t = row >> 5, b = row & 31;
    int idx = tgt[b * Tsz + t];
    g_dec_in[(size_t)row * Ed + threadIdx.x] = embed[(size_t)idx * Ed + threadIdx.x];
}

// ---------------- fp32 SGEMM with f32x2 FMA (small GEMMs) ----------------
__global__ void __launch_bounds__(256) sgemm_bias_kernel(
    const float* __restrict__ A, int K,
    const float* __restrict__ W, int ldw, int woff,
    const float* __restrict__ b1, const float* __restrict__ b2,
    float* __restrict__ C, int M, int N)
{
    __shared__ __align__(16) float As[8][128];
    __shared__ __align__(16) float Bs[8][128];
    const int bm = blockIdx.y * 128;
    const int bn = blockIdx.x * 128;
    const int t  = threadIdx.x;
    const int tr = (t >> 4) * 8;
    const int tc = (t & 15) * 8;
    const int lr = t >> 1;
    const int lc = (t & 1) * 4;

    unsigned long long acc2[8][4];
    #pragma unroll
    for (int i = 0; i < 8; i++)
        #pragma unroll
        for (int j = 0; j < 4; j++) acc2[i][j] = 0ull;

    const bool aValid = (bm + lr) < M;
    const float* aRow = A + (size_t)(bm + lr) * K + lc;
    const float* wRow = W + (size_t)(bn + lr) * ldw + woff + lc;

    for (int k0 = 0; k0 < K; k0 += 8) {
        float4 av = aValid ? *(const float4*)(aRow + k0) : make_float4(0.f, 0.f, 0.f, 0.f);
        float4 wv = *(const float4*)(wRow + k0);
        As[lc + 0][lr] = av.x; As[lc + 1][lr] = av.y; As[lc + 2][lr] = av.z; As[lc + 3][lr] = av.w;
        Bs[lc + 0][lr] = wv.x; Bs[lc + 1][lr] = wv.y; Bs[lc + 2][lr] = wv.z; Bs[lc + 3][lr] = wv.w;
        __syncthreads();
        #pragma unroll
        for (int kk = 0; kk < 8; kk++) {
            float a[8];
            *(float4*)(a)      = *(const float4*)&As[kk][tr];
            *(float4*)(a + 4)  = *(const float4*)&As[kk][tr + 4];
            unsigned long long bb2[4];
            *(ulonglong2*)&bb2[0] = *(const ulonglong2*)&Bs[kk][tc];
            *(ulonglong2*)&bb2[2] = *(const ulonglong2*)&Bs[kk][tc + 4];
            #pragma unroll
            for (int i = 0; i < 8; i++) {
                unsigned long long ap = pack2(a[i], a[i]);
                #pragma unroll
                for (int j = 0; j < 4; j++) ffma2(acc2[i][j], ap, bb2[j]);
            }
        }
        __syncthreads();
    }

    float bias[8];
    #pragma unroll
    for (int j = 0; j < 8; j++) {
        int n = bn + tc + j;
        bias[j] = b1[n] + (b2 ? b2[n] : 0.f);
    }
    #pragma unroll
    for (int i = 0; i < 8; i++) {
        int m = bm + tr + i;
        if (m >= M) break;
        float* cp = C + (size_t)m * N + bn + tc;
        #pragma unroll
        for (int j = 0; j < 4; j++) {
            float lo, hi;
            f32x2_unpack(acc2[i][j], lo, hi);
            cp[j * 2]     = lo + bias[j * 2];
            cp[j * 2 + 1] = hi + bias[j * 2 + 1];
        }
    }
}

// ---------------- gate partial-GEMM helper (f32x2) ----------------
__device__ __forceinline__ void gates_partial(
    const float* sm, int wbase, int xbase, int jg, int bg, int ks, unsigned long long acc[4][4])
{
    const int k0 = ks * 64;
    #pragma unroll 4
    for (int k4 = 0; k4 < 16; k4++) {
        const int k = k0 + (k4 << 2);
        ulonglong2 wv[4], hv[4];
        #pragma unroll
        for (int jj = 0; jj < 4; jj++)
            wv[jj] = *(const ulonglong2*)&sm[wbase + (jj * 4 + jg) * 516 + k];
        #pragma unroll
        for (int bb = 0; bb < 4; bb++)
            hv[bb] = *(const ulonglong2*)&sm[xbase + (bb * 8 + bg) * 516 + k];
        #pragma unroll
        for (int jj = 0; jj < 4; jj++)
            #pragma unroll
            for (int bb = 0; bb < 4; bb++) {
                ffma2(acc[jj][bb], wv[jj].x, hv[bb].x);
                ffma2(acc[jj][bb], wv[jj].y, hv[bb].y);
            }
    }
}

// ---------------- persistent encoder scan ----------------
#define ENC_SMEM_BYTES (28992 * 4)
__global__ void __launch_bounds__(256, 1) enc_scan_kernel(const float* __restrict__ Whh) {
    extern __shared__ float sm[];
    const int tid = threadIdx.x, hG = blockIdx.x;
    const int W0 = 0, HX = 8256, RD = 24768;

    for (int i = tid; i < 16 * 128; i += 256) {
        int r = i >> 7, k4 = i & 127;
        int j = (r >> 2) * Hd + hG * 4 + (r & 3);
        *(float4*)&sm[W0 + r * 516 + k4 * 4] = *(const float4*)&Whh[(size_t)j * Hd + k4 * 4];
    }

    float c_reg = 0.f;
    const int jg = tid & 3, bg = (tid >> 2) & 7, ks = tid >> 5;
    const int hl = tid >> 5, bq = tid & 31;
    unsigned bgen = 0;

    for (int s = 0; s < Ssz; s++) {
        const float* hin = g_h[s & 1];
        float* hout = g_h[(s + 1) & 1];

        float xg[4];
        if (tid < 128) {
            #pragma unroll
            for (int gate = 0; gate < 4; gate++)
                xg[gate] = __ldcg(&g_enc_xg[((size_t)s * Bsz + bq) * FH + gate * Hd + hG * 4 + hl]);
        }

        for (int i = tid; i < 32 * 128; i += 256) {
            int b = i >> 7, k4 = i & 127;
            *(float4*)&sm[HX + b * 516 + k4 * 4] = __ldcg((const float4*)&hin[(b << 9) + k4 * 4]);
        }
        __syncthreads();

        unsigned long long acc[4][4];
        #pragma unroll
        for (int a = 0; a < 4; a++)
            #pragma unroll
            for (int b2 = 0; b2 < 4; b2++) acc[a][b2] = 0ull;
        gates_partial(sm, W0, HX, jg, bg, ks, acc);

        #pragma unroll
        for (int jj = 0; jj < 4; jj++)
            #pragma unroll
            for (int bb = 0; bb < 4; bb++)
                sm[RD + ks * 528 + (jj * 4 + jg) * 33 + bb * 8 + bg] = f32x2_sum(acc[jj][bb]);
        __syncthreads();

        if (tid < 128) {
            float g4[4];
            #pragma unroll
            for (int gate = 0; gate < 4; gate++) {
                int r = gate * 4 + hl;
                float a = 0.f;
                #pragma unroll
                for (int q = 0; q < 8; q++) a += sm[RD + q * 528 + r * 33 + bq];
                g4[gate] = a + xg[gate];
            }
            float cv = sigf(g4[1]) * c_reg + sigf(g4[0]) * tanhf(g4[2]);
            float hn = sigf(g4[3]) * tanhf(cv);
            c_reg = cv;
            hout[(bq << 9) + hG * 4 + hl] = hn;
            g_enc_out[((size_t)bq * Ssz + s) * Hd + hG * 4 + hl] = hn;
        }
        bgen++;
        grid_bar(0, bgen);
    }
    if (tid < 128) {
        g_c[(bq << 9) + hG * 4 + hl] = c_reg;
    }
}

// ---------------- persistent decoder scan (attention fused, no-max softmax) ----------------
#define DEC_SMEM_BYTES (40464 * 4)
__global__ void __launch_bounds__(256, 1) dec_scan_kernel(
    const float* __restrict__ Wih, const float* __restrict__ Whh,
    const float* __restrict__ attnW, const float* __restrict__ attnv)
{
    extern __shared__ float sm[];
    const int tid = threadIdx.x, hG = blockIdx.x;
    const int W0 = 0, WC = 8256, WA = 16512, HX = 18576, RD = 35088,
              HP = 39312, VS = 39824, SC = 40336;

    for (int i = tid; i < 16 * 128; i += 256) {
        int r = i >> 7, k4 = i & 127;
        int j = (r >> 2) * Hd + hG * 4 + (r & 3);
        *(float4*)&sm[W0 + r * 516 + k4 * 4] = *(const float4*)&Whh[(size_t)j * Hd + k4 * 4];
        *(float4*)&sm[WC + r * 516 + k4 * 4] = *(const float4*)&Wih[(size_t)j * (Ed + Hd) + Ed + k4 * 4];
    }
    for (int i = tid; i < 4 * 128; i += 256) {
        int r = i >> 7, k4 = i & 127;
        *(float4*)&sm[WA + r * 516 + k4 * 4] = *(const float4*)&attnW[(size_t)(hG * 4 + r) * (2 * Hd) + k4 * 4];
    }
    for (int i = tid; i < Hd; i += 256) sm[VS + i] = attnv[i];

    float c_reg = 0.f;
    const int hl = tid >> 5, bq = tid & 31;
    if (tid < 128) c_reg = __ldcg(&g_c[(bq << 9) + hG * 4 + hl]);

    const int jg = tid & 3, bg = (tid >> 2) & 7, ks = tid >> 5;
    const int bB = hG >> 2;
    const int part = hG & 3;
    unsigned bgen = 0;

    for (int t = 0; t < T1; t++) {
        const float* hin = g_h[t & 1];
        float* hout = g_h[(t + 1) & 1];

        // ---- phase A: load h, hproj, gates h-part ----
        for (int i = tid; i < 32 * 128; i += 256) {
            int b = i >> 7, k4 = i & 127;
            *(float4*)&sm[HX + b * 516 + k4 * 4] = __ldcg((const float4*)&hin[(b << 9) + k4 * 4]);
        }
        __syncthreads();
        {
            const int ko = tid >> 6, bh = (tid >> 1) & 31, kh = tid & 1;
            float a = 0.f;
            const int kb = kh << 8;
            #pragma unroll 4
            for (int k = kb; k < kb + 256; k += 4) {
                float4 w4 = *(const float4*)&sm[WA + ko * 516 + k];
                float4 h4 = *(const float4*)&sm[HX + bh * 516 + k];
                a += w4.x * h4.x + w4.y * h4.y + w4.z * h4.z + w4.w * h4.w;
            }
            a += __shfl_xor_sync(0xffffffffu, a, 1);
            if (!kh) g_hproj[(bh << 9) + hG * 4 + ko] = a;
        }
        unsigned long long acc[4][4];
        #pragma unroll
        for (int a2 = 0; a2 < 4; a2++)
            #pragma unroll
            for (int b2 = 0; b2 < 4; b2++) acc[a2][b2] = 0ull;
        gates_partial(sm, W0, HX, jg, bg, ks, acc);
        bgen++; grid_bar(1, bgen);

        // ---- phase B: attention partials ----
        for (int i = tid; i < Hd; i += 256) sm[HP + i] = __ldcg(&g_hproj[(bB << 9) + i]);
        __syncthreads();
        {
            const int s0 = part * 32, w = tid >> 5, lane = tid & 31;
            #pragma unroll
            for (int q = 0; q < 4; q++) {
                int sl = w * 4 + q;
                const float* ep = g_enc_proj + ((size_t)bB * Ssz + s0 + sl) * Hd;
                float a = 0.f;
                for (int kk = lane; kk < Hd; kk += 32)
                    a += tanh_fast(sm[HP + kk] + ep[kk]) * sm[VS + kk];
                #pragma unroll
                for (int off = 16; off; off >>= 1) a += __shfl_xor_sync(0xffffffffu, a, off);
                if (!lane) sm[SC + sl] = a;
            }
        }
        __syncthreads();
        {
            if (tid < 32) sm[SC + 32 + tid] = __expf(sm[SC + tid]);
            __syncthreads();
            float lloc = 0.f;
            #pragma unroll
            for (int i2 = 0; i2 < 32; i2++) lloc += sm[SC + 32 + i2];

            const int s0 = part * 32;
            float a0 = 0.f, a1 = 0.f;
            const float* eo = g_enc_out + ((size_t)bB * Ssz + s0) * Hd;
            #pragma unroll 4
            for (int s2 = 0; s2 < 32; s2++) {
                float p = sm[SC + 32 + s2];
                a0 += p * eo[(size_t)s2 * Hd + tid];
                a1 += p * eo[(size_t)s2 * Hd + tid + 256];
            }
            float* ap = g_attp[bB][part];
            ap[tid] = a0;
            ap[tid + 256] = a1;
            if (tid == 0) ap[513] = lloc;
        }
        bgen++; grid_bar(1, bgen);

        // ---- phase C: combine 4 partials -> g_ctx ----
        if (tid < 128) {
            const int h = part * 128 + tid;
            float l = __ldcg(&g_attp[bB][0][513]) + __ldcg(&g_attp[bB][1][513])
                    + __ldcg(&g_attp[bB][2][513]) + __ldcg(&g_attp[bB][3][513]);
            float cx = __ldcg(&g_attp[bB][0][h]) + __ldcg(&g_attp[bB][1][h])
                     + __ldcg(&g_attp[bB][2][h]) + __ldcg(&g_attp[bB][3][h]);
            g_ctx[(bB << 9) + h] = cx / l;
        }
        bgen++; grid_bar(1, bgen);

        // ---- phase D: gates ctx-part + pointwise ----
        float xg[4];
        if (tid < 128) {
            #pragma unroll
            for (int gate = 0; gate < 4; gate++)
                xg[gate] = __ldcg(&g_dec_xg[((size_t)t * Bsz + bq) * FH + gate * Hd + hG * 4 + hl]);
        }
        for (int i = tid; i < 32 * 128; i += 256) {
            int b = i >> 7, k4 = i & 127;
            *(float4*)&sm[HX + b * 516 + k4 * 4] = __ldcg((const float4*)&g_ctx[(b << 9) + k4 * 4]);
        }
        __syncthreads();
        gates_partial(sm, WC, HX, jg, bg, ks, acc);

        #pragma unroll
        for (int jj = 0; jj < 4; jj++)
            #pragma unroll
            for (int bb = 0; bb < 4; bb++)
                sm[RD + ks * 528 + (jj * 4 + jg) * 33 + bb * 8 + bg] = f32x2_sum(acc[jj][bb]);
        __syncthreads();

        if (tid < 128) {
            float g4[4];
            #pragma unroll
            for (int gate = 0; gate < 4; gate++) {
                int r = gate * 4 + hl;
                float a = 0.f;
                #pragma unroll
                for (int q = 0; q < 8; q++) a += sm[RD + q * 528 + r * 33 + bq];
                g4[gate] = a + xg[gate];
            }
            float cv = sigf(g4[1]) * c_reg + sigf(g4[0]) * tanhf(g4[2]);
            float hn = sigf(g4[3]) * tanhf(cv);
            c_reg = cv;
            hout[(bq << 9) + hG * 4 + hl] = hn;
            size_t mi = ((size_t)bq * T1 + t) * Hd + hG * 4 + hl;
            g_hs_f16[mi] = __float2half_rn(hn);
        }
        bgen++; grid_bar(1, bgen);
    }
}

// ---------------- fc_W fp16 conversion ----------------
__global__ void conv_w_kernel(const float* __restrict__ fc_W) {
    size_t i = ((size_t)blockIdx.x * 256 + threadIdx.x) * 4;
    if (i >= (size_t)Vsz * Hd) return;
    float4 x = *(const float4*)&fc_W[i];
    g_fcw_f16[i + 0] = __float2half_rn(x.x);
    g_fcw_f16[i + 1] = __float2half_rn(x.y);
    g_fcw_f16[i + 2] = __float2half_rn(x.z);
    g_fcw_f16[i + 3] = __float2half_rn(x.w);
}

// ---------------- FC GEMM: single-pass fp16, 128x128 tile, occ 2, cp.async 2-stage ----------------
// 8 warps = 4(m) x 2(n); warp tile 32x64 (2 m16 x 8 n8). K=512 in 8 chunks of 64.
// Per stage: A(128x72) + B(128x72) fp16 = 36864 B; 2 stages = 73728 B (2 CTAs/SM fit).
#define FCA_B  18432u                    // A tile bytes (128*72*2)
#define FCSTG  36864u                    // stage bytes
#define FC_SMEM_BYTES (2 * FCSTG)        // 73728
__global__ void __launch_bounds__(256, 2) fc_mma_kernel(
    const float* __restrict__ fc_b, float* __restrict__ out)
{
    extern __shared__ __half smh[];
    const int tid = threadIdx.x, lane = tid & 31, wid = tid >> 5;
    const int wm = wid & 3, wn = wid >> 2;
    const int m0 = blockIdx.x * 128, n0 = blockIdx.y * 128;
    const uint32_t smem_base = smem_to_u32(smh);

    const __half* baseA = g_hs_f16  + (size_t)m0 * Hd;
    const __half* baseB = g_fcw_f16 + (size_t)n0 * Hd;

    float acc[2][8][4];
    #pragma unroll
    for (int a = 0; a < 2; a++)
        #pragma unroll
        for (int b = 0; b < 8; b++)
            #pragma unroll
            for (int c = 0; c < 4; c++) acc[a][b][c] = 0.f;

    const int lrow = ((lane >> 3) & 1) * 8 + (lane & 7);
    const int lcol = (lane >> 4) * 8;

    auto issue_stage = [&](int kc, int stg) {
        uint32_t sb = smem_base + (uint32_t)stg * FCSTG;
        #pragma unroll
        for (int tt = 0; tt < 4; tt++) {
            int idx = tid + tt * 256;
            int r = idx >> 3, c8 = idx & 7;
            uint32_t doff = (uint32_t)(r * 144 + c8 * 16);
            size_t gi = (size_t)r * Hd + kc * 64 + c8 * 8;
            cp_async16(sb + doff,         baseA + gi);
            cp_async16(sb + FCA_B + doff, baseB + gi);
        }
        asm volatile("cp.async.commit_group;" ::: "memory");
    };

    issue_stage(0, 0);

    for (int kc = 0; kc < 8; kc++) {
        const int stg = kc & 1;
        if (kc < 7) {
            issue_stage(kc + 1, stg ^ 1);
            asm volatile("cp.async.wait_group 1;" ::: "memory");
        } else {
            asm volatile("cp.async.wait_group 0;" ::: "memory");
        }
        __syncthreads();

        const uint32_t sb = smem_base + (uint32_t)stg * FCSTG;
        #pragma unroll
        for (int kk = 0; kk < 4; kk++) {
            uint32_t a[2][4], b[4][4];
            #pragma unroll
            for (int mt = 0; mt < 2; mt++) {
                uint32_t off = sb + (uint32_t)(((wm * 32 + mt * 16 + lrow) * 72 + kk * 16 + lcol) * 2);
                ldsm_x4(a[mt], off);
            }
            #pragma unroll
            for (int ng = 0; ng < 4; ng++) {
                uint32_t off = sb + FCA_B +
                    (uint32_t)(((wn * 64 + ng * 16 + lrow) * 72 + kk * 16 + lcol) * 2);
                ldsm_x4(b[ng], off);
            }
            #pragma unroll
            for (int mt = 0; mt < 2; mt++)
                #pragma unroll
                for (int ng = 0; ng < 4; ng++) {
                    mma_f16(acc[mt][ng * 2],     a[mt], b[ng][0], b[ng][2]);
                    mma_f16(acc[mt][ng * 2 + 1], a[mt], b[ng][1], b[ng][3]);
                }
        }
        __syncthreads();
    }

    const int rbase = m0 + wm * 32 + (lane >> 2);
    const int cbase = n0 + wn * 64 + (lane & 3) * 2;
    #pragma unroll
    for (int mt = 0; mt < 2; mt++)
        #pragma unroll
        for (int nt = 0; nt < 8; nt++) {
            int c = cbase + nt * 8;
            float b0 = fc_b[c], b1 = fc_b[c + 1];
            int r0 = rbase + mt * 16;
            if (r0 < Mrows) {
                float2 v = make_float2(acc[mt][nt][0] + b0, acc[mt][nt][1] + b1);
                *(float2*)&out[(size_t)r0 * Vsz + c] = v;
            }
            int r1 = r0 + 8;
            if (r1 < Mrows) {
                float2 v = make_float2(acc[mt][nt][2] + b0, acc[mt][nt][3] + b1);
                *(float2*)&out[(size_t)r1 * Vsz + c] = v;
            }
        }
}

// ---------------- launch ----------------
extern "C" void kernel_launch(void* const* d_in, const int* in_sizes, int n_in,
                              void* d_out, int out_size)
{
    const int*   src     = (const int*)d_in[0];
    const int*   tgt     = (const int*)d_in[1];
    const float* embed   = (const float*)d_in[2];
    const float* enc_Wih = (const float*)d_in[3];
    const float* enc_Whh = (const float*)d_in[4];
    const float* enc_bih = (const float*)d_in[5];
    const float* enc_bhh = (const float*)d_in[6];
    const float* dec_Wih = (const float*)d_in[7];
    const float* dec_Whh = (const float*)d_in[8];
    const float* dec_bih = (const float*)d_in[9];
    const float* dec_bhh = (const float*)d_in[10];
    const float* attn_W  = (const float*)d_in[11];
    const float* attn_b  = (const float*)d_in[12];
    const float* attn_v  = (const float*)d_in[13];
    const float* fc_W    = (const float*)d_in[14];
    const float* fc_b    = (const float*)d_in[15];
    float* out = (float*)d_out;

    float *p_src_emb, *p_dec_in, *p_enc_xg, *p_dec_xg, *p_enc_out, *p_enc_proj;
    cudaGetSymbolAddress((void**)&p_src_emb,  g_src_emb);
    cudaGetSymbolAddress((void**)&p_dec_in,   g_dec_in);
    cudaGetSymbolAddress((void**)&p_enc_xg,   g_enc_xg);
    cudaGetSymbolAddress((void**)&p_dec_xg,   g_dec_xg);
    cudaGetSymbolAddress((void**)&p_enc_out,  g_enc_out);
    cudaGetSymbolAddress((void**)&p_enc_proj, g_enc_proj);

    cudaFuncSetAttribute(enc_scan_kernel, cudaFuncAttributeMaxDynamicSharedMemorySize, ENC_SMEM_BYTES);
    cudaFuncSetAttribute(dec_scan_kernel, cudaFuncAttributeMaxDynamicSharedMemorySize, DEC_SMEM_BYTES);
    cudaFuncSetAttribute(fc_mma_kernel,  cudaFuncAttributeMaxDynamicSharedMemorySize, FC_SMEM_BYTES);

    // side stream + events for the independent decoder-input branch (created once;
    // handles only — no device work, identical captured work every call)
    static cudaStream_t s2 = nullptr;
    static cudaEvent_t evFork = nullptr, evJoin = nullptr;
    if (s2 == nullptr) {
        cudaStreamCreateWithFlags(&s2, cudaStreamNonBlocking);
        cudaEventCreateWithFlags(&evFork, cudaEventDisableTiming);
        cudaEventCreateWithFlags(&evJoin, cudaEventDisableTiming);
    }

    init_state_kernel<<<(Bsz * Hd + 255) / 256, 256>>>();
    gather_src_kernel<<<Ssz * Bsz, Ed>>>(src, embed);

    // fork: decoder-input branch (gather_dec -> dec_xg -> conv_w) runs concurrently
    cudaEventRecord(evFork, 0);
    cudaStreamWaitEvent(s2, evFork, 0);
    gather_dec_kernel<<<T1 * Bsz, Ed, 0, s2>>>(tgt, embed);
    {
        dim3 grid(FH / 128, (T1 * Bsz + 127) / 128);
        sgemm_bias_kernel<<<grid, 256, 0, s2>>>(p_dec_in, Ed, dec_Wih, Ed + Hd, 0,
                                                dec_bih, dec_bhh, p_dec_xg, T1 * Bsz, FH);
    }
    conv_w_kernel<<<(Vsz * Hd / 4 + 255) / 256, 256, 0, s2>>>(fc_W);
    cudaEventRecord(evJoin, s2);

    {   // enc_xg (main stream, overlaps with side branch)
        dim3 grid(FH / 128, (Ssz * Bsz + 127) / 128);
        sgemm_bias_kernel<<<grid, 256>>>(p_src_emb, Ed, enc_Wih, Ed, 0,
                                         enc_bih, enc_bhh, p_enc_xg, Ssz * Bsz, FH);
    }

    enc_scan_kernel<<<NBLK, 256, ENC_SMEM_BYTES>>>(enc_Whh);

    {   // enc_proj
        dim3 grid(Hd / 128, (Bsz * Ssz + 127) / 128);
        sgemm_bias_kernel<<<grid, 256>>>(p_enc_out, Hd, attn_W, 2 * Hd, Hd,
                                         attn_b, nullptr, p_enc_proj, Bsz * Ssz, Hd);
    }

    // join: dec_scan needs dec_xg; fc needs conv_w
    cudaStreamWaitEvent(0, evJoin, 0);

    dec_scan_kernel<<<NBLK, 256, DEC_SMEM_BYTES>>>(dec_Wih, dec_Whh, attn_W, attn_v);

    fc_mma_kernel<<<dim3(MrowsPad / 128, Vsz / 128), 256, FC_SMEM_BYTES>>>(fc_b, out);
}

// round 15
// speedup vs baseline: 1.4802x; 1.1156x over previous
#include <cuda_runtime.h>
#include <cuda_bf16.h>
#include <cuda_fp16.h>
#include <cstddef>
#include <cstdint>

#define Bsz 32
#define Ssz 128
#define Tsz 64
#define T1  63
#define Ed  256
#define Hd  512
#define Vsz 32000
#define FH  2048
#define NBLK 128
#define Mrows 2016       // Bsz*T1
#define MrowsPad 2048

// ---------------- device scratch ----------------
__device__ __align__(16) float g_src_emb[(size_t)Ssz * Bsz * Ed];
__device__ __align__(16) float g_dec_in [(size_t)T1  * Bsz * Ed];
__device__ __align__(16) float g_enc_xg [(size_t)Ssz * Bsz * FH];
__device__ __align__(16) float g_dec_xg [(size_t)T1  * Bsz * FH];
__device__ __align__(16) float g_enc_out[(size_t)Bsz * Ssz * Hd];
__device__ __align__(16) float g_enc_proj[(size_t)Bsz * Ssz * Hd];
__device__ __align__(16) __half g_h[2][Bsz * Hd];      // recurrent h in fp16
__device__ __align__(16) float g_c [Bsz * Hd];
__device__ __align__(16) __half g_ctx_f16[Bsz * Hd];   // attention context fp16
__device__ __align__(16) float g_hproj[Bsz * Hd];
__device__ __align__(16) float g_attp[Bsz][4][516];    // per-part: ctx[512], l@513
__device__ unsigned g_cnt[2];
__device__ unsigned g_gen[2];
// fp16 operands for the FC tensor GEMM
__device__ __align__(16) __half g_hs_f16 [(size_t)MrowsPad * Hd];
__device__ __align__(16) __half g_fcw_f16[(size_t)Vsz * Hd];

__device__ __forceinline__ float sigf(float x) { return 1.0f / (1.0f + expf(-x)); }
__device__ __forceinline__ float tanh_fast(float x) {
    float y;
    asm("tanh.approx.f32 %0, %1;" : "=f"(y) : "f"(x));
    return y;
}

// ---------------- packed f32x2 FMA (sgemm only) ----------------
__device__ __forceinline__ void ffma2(unsigned long long& d, unsigned long long a, unsigned long long b) {
    asm("fma.rn.f32x2 %0, %1, %2, %0;" : "+l"(d) : "l"(a), "l"(b));
}
__device__ __forceinline__ void f32x2_unpack(unsigned long long v, float& lo, float& hi) {
    asm("mov.b64 {%0, %1}, %2;" : "=f"(lo), "=f"(hi) : "l"(v));
}
__device__ __forceinline__ unsigned long long pack2(float lo, float hi) {
    unsigned long long v;
    asm("mov.b64 %0, {%1, %2};" : "=l"(v) : "f"(lo), "f"(hi));
    return v;
}

__device__ __forceinline__ uint32_t smem_to_u32(const void* p) {
    uint32_t a;
    asm("{ .reg .u64 t; cvta.to.shared.u64 t, %1; cvt.u32.u64 %0, t; }" : "=r"(a) : "l"(p));
    return a;
}
__device__ __forceinline__ void ldsm_x4(uint32_t* r, uint32_t addr) {
    asm volatile("ldmatrix.sync.aligned.m8n8.x4.shared.b16 {%0,%1,%2,%3}, [%4];"
        : "=r"(r[0]), "=r"(r[1]), "=r"(r[2]), "=r"(r[3]) : "r"(addr));
}
__device__ __forceinline__ void mma_f16(float* d, const uint32_t* a, uint32_t b0, uint32_t b1) {
    asm volatile("mma.sync.aligned.m16n8k16.row.col.f32.f16.f16.f32 "
        "{%0,%1,%2,%3}, {%4,%5,%6,%7}, {%8,%9}, {%0,%1,%2,%3};"
        : "+f"(d[0]), "+f"(d[1]), "+f"(d[2]), "+f"(d[3])
        : "r"(a[0]), "r"(a[1]), "r"(a[2]), "r"(a[3]), "r"(b0), "r"(b1));
}
__device__ __forceinline__ void cp_async16(uint32_t dst, const void* src) {
    asm volatile("cp.async.cg.shared.global [%0], [%1], 16;" :: "r"(dst), "l"(src) : "memory");
}

// ---------------- global barrier ----------------
__device__ __forceinline__ void grid_bar(int which, unsigned target) {
    __threadfence();
    __syncthreads();
    if (threadIdx.x == 0) {
        unsigned arr = atomicAdd(&g_cnt[which], 1u);
        if (arr == NBLK - 1u) {
            g_cnt[which] = 0u;
            __threadfence();
            atomicAdd(&g_gen[which], 1u);
        } else {
            const volatile unsigned* gp = (const volatile unsigned*)&g_gen[which];
            while (*gp < target) { }
        }
    }
    __syncthreads();
}

__global__ void init_state_kernel() {
    int i = blockIdx.x * blockDim.x + threadIdx.x;
    if (i < Bsz * Hd) g_h[0][i] = __float2half(0.f);
    if (i < 2) { g_cnt[i] = 0u; g_gen[i] = 0u; }
    if (i < (MrowsPad - Mrows) * Hd) {
        g_hs_f16[(size_t)Mrows * Hd + i] = __float2half(0.f);
    }
}

// ---------------- embedding gathers ----------------
__global__ void gather_src_kernel(const int* __restrict__ src, const float* __restrict__ embed) {
    int row = blockIdx.x;           // s*B + b
    int s = row >> 5, b = row & 31;
    int idx = src[b * Ssz + s];
    g_src_emb[(size_t)row * Ed + threadIdx.x] = embed[(size_t)idx * Ed + threadIdx.x];
}
__global__ void gather_dec_kernel(const int* __restrict__ tgt, const float* __restrict__ embed) {
    int row = blockIdx.x;           // t*B + b
    int t = row >> 5, b = row & 31;
    int idx = tgt[b * Tsz + t];
    g_dec_in[(size_t)row * Ed + threadIdx.x] = embed[(size_t)idx * Ed + threadIdx.x];
}

// ---------------- fp32 SGEMM with f32x2 FMA (small GEMMs) ----------------
__global__ void __launch_bounds__(256) sgemm_bias_kernel(
    const float* __restrict__ A, int K,
    const float* __restrict__ W, int ldw, int woff,
    const float* __restrict__ b1, const float* __restrict__ b2,
    float* __restrict__ C, int M, int N)
{
    __shared__ __align__(16) float As[8][128];
    __shared__ __align__(16) float Bs[8][128];
    const int bm = blockIdx.y * 128;
    const int bn = blockIdx.x * 128;
    const int t  = threadIdx.x;
    const int tr = (t >> 4) * 8;
    const int tc = (t & 15) * 8;
    const int lr = t >> 1;
    const int lc = (t & 1) * 4;

    unsigned long long acc2[8][4];
    #pragma unroll
    for (int i = 0; i < 8; i++)
        #pragma unroll
        for (int j = 0; j < 4; j++) acc2[i][j] = 0ull;

    const bool aValid = (bm + lr) < M;
    const float* aRow = A + (size_t)(bm + lr) * K + lc;
    const float* wRow = W + (size_t)(bn + lr) * ldw + woff + lc;

    for (int k0 = 0; k0 < K; k0 += 8) {
        float4 av = aValid ? *(const float4*)(aRow + k0) : make_float4(0.f, 0.f, 0.f, 0.f);
        float4 wv = *(const float4*)(wRow + k0);
        As[lc + 0][lr] = av.x; As[lc + 1][lr] = av.y; As[lc + 2][lr] = av.z; As[lc + 3][lr] = av.w;
        Bs[lc + 0][lr] = wv.x; Bs[lc + 1][lr] = wv.y; Bs[lc + 2][lr] = wv.z; Bs[lc + 3][lr] = wv.w;
        __syncthreads();
        #pragma unroll
        for (int kk = 0; kk < 8; kk++) {
            float a[8];
            *(float4*)(a)      = *(const float4*)&As[kk][tr];
            *(float4*)(a + 4)  = *(const float4*)&As[kk][tr + 4];
            unsigned long long bb2[4];
            *(ulonglong2*)&bb2[0] = *(const ulonglong2*)&Bs[kk][tc];
            *(ulonglong2*)&bb2[2] = *(const ulonglong2*)&Bs[kk][tc + 4];
            #pragma unroll
            for (int i = 0; i < 8; i++) {
                unsigned long long ap = pack2(a[i], a[i]);
                #pragma unroll
                for (int j = 0; j < 4; j++) ffma2(acc2[i][j], ap, bb2[j]);
            }
        }
        __syncthreads();
    }

    float bias[8];
    #pragma unroll
    for (int j = 0; j < 8; j++) {
        int n = bn + tc + j;
        bias[j] = b1[n] + (b2 ? b2[n] : 0.f);
    }
    #pragma unroll
    for (int i = 0; i < 8; i++) {
        int m = bm + tr + i;
        if (m >= M) break;
        float* cp = C + (size_t)m * N + bn + tc;
        #pragma unroll
        for (int j = 0; j < 4; j++) {
            float lo, hi;
            f32x2_unpack(acc2[i][j], lo, hi);
            cp[j * 2]     = lo + bias[j * 2];
            cp[j * 2 + 1] = hi + bias[j * 2 + 1];
        }
    }
}

// ---------------- warp-level gate GEMM via mma.sync (fp16) ----------------
// W tile: 16 rows x 520 halves at woff; X tile: 32 rows(batch) x 520 halves at xoff.
// Warp `wid` covers k in [wid*64, wid*64+64). accf[ng][4]: ng = batch-octet 0..3.
__device__ __forceinline__ void gates_mma(
    uint32_t sb, uint32_t woff, uint32_t xoff, int wid, int lrow, int lcol, float accf[4][4])
{
    #pragma unroll
    for (int kk = 0; kk < 4; kk++) {
        const int kb = wid * 64 + kk * 16;
        uint32_t av[4], b0[4], b1[4];
        ldsm_x4(av, sb + woff + (uint32_t)((lrow * 520 + kb + lcol) * 2));
        ldsm_x4(b0, sb + xoff + (uint32_t)((lrow * 520 + kb + lcol) * 2));
        ldsm_x4(b1, sb + xoff + (uint32_t)(((16 + lrow) * 520 + kb + lcol) * 2));
        mma_f16(accf[0], av, b0[0], b0[2]);
        mma_f16(accf[1], av, b0[1], b0[3]);
        mma_f16(accf[2], av, b1[0], b1[2]);
        mma_f16(accf[3], av, b1[1], b1[3]);
    }
}
// store warp's 16x32 partial into RD (16x33 per warp), d-frag mapping
__device__ __forceinline__ void gates_store(float* RDf, int wid, int lane, const float accf[4][4]) {
    const int r0 = lane >> 2, c0 = (lane & 3) * 2;
    float* rd = RDf + wid * 528;
    #pragma unroll
    for (int ng = 0; ng < 4; ng++) {
        const int c = ng * 8 + c0;
        rd[r0 * 33 + c]           = accf[ng][0];
        rd[r0 * 33 + c + 1]       = accf[ng][1];
        rd[(r0 + 8) * 33 + c]     = accf[ng][2];
        rd[(r0 + 8) * 33 + c + 1] = accf[ng][3];
    }
}

// ---------------- persistent encoder scan (mma gates) ----------------
// smem bytes: W0h 16x520 half @0 (16640), HXh 32x520 half @16640 (33280), RD 8x528 f @49920 (16896)
#define E_W0 0
#define E_HX 16640
#define E_RD 49920
#define ENC_SMEM_BYTES 66816
__global__ void __launch_bounds__(256, 1) enc_scan_kernel(const float* __restrict__ Whh) {
    extern __shared__ char smc[];
    __half* W0h = (__half*)(smc + E_W0);
    __half* HXh = (__half*)(smc + E_HX);
    float*  RDf = (float*)(smc + E_RD);
    const uint32_t sb = smem_to_u32(smc);
    const int tid = threadIdx.x, hG = blockIdx.x;
    const int wid = tid >> 5, lane = tid & 31;
    const int hl = tid >> 5, bq = tid & 31;          // (tid<128 users)
    const int lrow = ((lane >> 3) & 1) * 8 + (lane & 7);
    const int lcol = (lane >> 4) * 8;

    for (int i = tid; i < 16 * 512; i += 256) {
        int r = i >> 9, k = i & 511;
        int j = (r >> 2) * Hd + hG * 4 + (r & 3);
        W0h[r * 520 + k] = __float2half_rn(Whh[(size_t)j * Hd + k]);
    }

    float c_reg = 0.f;
    unsigned bgen = 0;

    for (int s = 0; s < Ssz; s++) {
        const __half* hin = g_h[s & 1];
        __half* hout = g_h[(s + 1) & 1];

        float xg[4];
        if (tid < 128) {
            #pragma unroll
            for (int gate = 0; gate < 4; gate++)
                xg[gate] = __ldcg(&g_enc_xg[((size_t)s * Bsz + bq) * FH + gate * Hd + hG * 4 + hl]);
        }

        for (int i = tid; i < 2048; i += 256) {       // 32 x 512 halves, uint4 = 8 halves
            int b = i >> 6, k8 = (i & 63) * 8;
            *(uint4*)&HXh[b * 520 + k8] = __ldcg((const uint4*)&hin[(b << 9) + k8]);
        }
        __syncthreads();

        float accf[4][4];
        #pragma unroll
        for (int a = 0; a < 4; a++)
            #pragma unroll
            for (int b2 = 0; b2 < 4; b2++) accf[a][b2] = 0.f;
        gates_mma(sb, E_W0, E_HX, wid, lrow, lcol, accf);
        gates_store(RDf, wid, lane, accf);
        __syncthreads();

        if (tid < 128) {
            float g4[4];
            #pragma unroll
            for (int gate = 0; gate < 4; gate++) {
                int r = gate * 4 + hl;
                float a = 0.f;
                #pragma unroll
                for (int q = 0; q < 8; q++) a += RDf[q * 528 + r * 33 + bq];
                g4[gate] = a + xg[gate];
            }
            float cv = sigf(g4[1]) * c_reg + sigf(g4[0]) * tanhf(g4[2]);
            float hn = sigf(g4[3]) * tanhf(cv);
            c_reg = cv;
            hout[(bq << 9) + hG * 4 + hl] = __float2half_rn(hn);
            g_enc_out[((size_t)bq * Ssz + s) * Hd + hG * 4 + hl] = hn;
        }
        bgen++;
        grid_bar(0, bgen);
    }
    if (tid < 128) {
        g_c[(bq << 9) + hG * 4 + hl] = c_reg;
    }
}

// ---------------- persistent decoder scan (mma gates, smem-cached attention) ----------------
// byte offsets:
#define D_W0 0          // Whh fp16 16x520            (16640)
#define D_WC 16640      // Wih-ctx fp16 16x520        (16640)
#define D_HX 33280      // h/ctx fp16 32x520          (33280)
#define D_WA 66560      // attnW fp32 4x516           (8256)
#define D_RD 74816      // reduce fp32 8x528          (16896)
#define D_HP 91712      // hproj fp32 512             (2048)
#define D_VS 93760      // attn_v fp32 512            (2048)
#define D_SC 95808      // scores fp32 64             (256)
#define D_EP 96064      // enc_proj slice fp32 32x512 (65536)
#define D_EO 161600     // enc_out  slice fp32 32x512 (65536)
#define DEC_SMEM_BYTES 227136
__global__ void __launch_bounds__(256, 1) dec_scan_kernel(
    const float* __restrict__ Wih, const float* __restrict__ Whh,
    const float* __restrict__ attnW, const float* __restrict__ attnv)
{
    extern __shared__ char smc[];
    __half* W0h = (__half*)(smc + D_W0);
    __half* WCh = (__half*)(smc + D_WC);
    __half* HXh = (__half*)(smc + D_HX);
    float*  WAf = (float*)(smc + D_WA);
    float*  RDf = (float*)(smc + D_RD);
    float*  HPf = (float*)(smc + D_HP);
    float*  VSf = (float*)(smc + D_VS);
    float*  SCf = (float*)(smc + D_SC);
    float*  EPf = (float*)(smc + D_EP);
    float*  EOf = (float*)(smc + D_EO);
    const uint32_t sb = smem_to_u32(smc);
    const int tid = threadIdx.x, hG = blockIdx.x;
    const int wid = tid >> 5, lane = tid & 31;
    const int hl = tid >> 5, bq = tid & 31;
    const int lrow = ((lane >> 3) & 1) * 8 + (lane & 7);
    const int lcol = (lane >> 4) * 8;
    const int bB = hG >> 2;
    const int part = hG & 3;

    // prologue loads (once)
    for (int i = tid; i < 16 * 512; i += 256) {
        int r = i >> 9, k = i & 511;
        int j = (r >> 2) * Hd + hG * 4 + (r & 3);
        W0h[r * 520 + k] = __float2half_rn(Whh[(size_t)j * Hd + k]);
        WCh[r * 520 + k] = __float2half_rn(Wih[(size_t)j * (Ed + Hd) + Ed + k]);
    }
    for (int i = tid; i < 4 * 516; i += 256) {
        int r = i / 516, k = i % 516;
        WAf[i] = (k < Hd) ? attnW[(size_t)(hG * 4 + r) * (2 * Hd) + k] : 0.f;
    }
    for (int i = tid; i < Hd; i += 256) VSf[i] = attnv[i];
    for (int i = tid; i < 32 * 128; i += 256) {       // 32x512 floats via float4
        int sl = i >> 7, k4 = (i & 127) * 4;
        size_t gidx = ((size_t)bB * Ssz + part * 32 + sl) * Hd + k4;
        *(float4*)&EPf[sl * 512 + k4] = *(const float4*)&g_enc_proj[gidx];
        *(float4*)&EOf[sl * 512 + k4] = *(const float4*)&g_enc_out[gidx];
    }

    float c_reg = 0.f;
    if (tid < 128) c_reg = __ldcg(&g_c[(bq << 9) + hG * 4 + hl]);
    unsigned bgen = 0;

    for (int t = 0; t < T1; t++) {
        const __half* hin = g_h[t & 1];
        __half* hout = g_h[(t + 1) & 1];

        // ---- phase A: load h, hproj, gates h-part ----
        for (int i = tid; i < 2048; i += 256) {
            int b = i >> 6, k8 = (i & 63) * 8;
            *(uint4*)&HXh[b * 520 + k8] = __ldcg((const uint4*)&hin[(b << 9) + k8]);
        }
        __syncthreads();
        {
            const int ko = tid >> 6, bh = (tid >> 1) & 31, kh = tid & 1;
            const float* wa = WAf + ko * 516 + (kh << 8);
            const __half2* hh = (const __half2*)&HXh[bh * 520 + (kh << 8)];
            float a = 0.f;
            #pragma unroll 8
            for (int k2 = 0; k2 < 128; k2++) {
                float2 h2 = __half22float2(hh[k2]);
                a += wa[k2 * 2] * h2.x + wa[k2 * 2 + 1] * h2.y;
            }
            a += __shfl_xor_sync(0xffffffffu, a, 1);
            if (!kh) g_hproj[(bh << 9) + hG * 4 + ko] = a;
        }
        float accf[4][4];
        #pragma unroll
        for (int a2 = 0; a2 < 4; a2++)
            #pragma unroll
            for (int b2 = 0; b2 < 4; b2++) accf[a2][b2] = 0.f;
        gates_mma(sb, D_W0, D_HX, wid, lrow, lcol, accf);
        bgen++; grid_bar(1, bgen);

        // ---- phase B: attention partials (all operands in smem) ----
        for (int i = tid; i < Hd; i += 256) HPf[i] = __ldcg(&g_hproj[(bB << 9) + i]);
        __syncthreads();
        {
            const int w = tid >> 5, ln = tid & 31;
            #pragma unroll
            for (int q = 0; q < 4; q++) {
                int sl = w * 4 + q;
                const float* ep = EPf + sl * 512;
                float a = 0.f;
                for (int kk = ln; kk < Hd; kk += 32)
                    a += tanh_fast(HPf[kk] + ep[kk]) * VSf[kk];
                #pragma unroll
                for (int off = 16; off; off >>= 1) a += __shfl_xor_sync(0xffffffffu, a, off);
                if (!ln) SCf[sl] = a;
            }
        }
        __syncthreads();
        {
            if (tid < 32) SCf[32 + tid] = __expf(SCf[tid]);
            __syncthreads();
            float lloc = 0.f;
            #pragma unroll
            for (int i2 = 0; i2 < 32; i2++) lloc += SCf[32 + i2];

            float a0 = 0.f, a1 = 0.f;
            #pragma unroll 4
            for (int s2 = 0; s2 < 32; s2++) {
                float p = SCf[32 + s2];
                a0 += p * EOf[s2 * 512 + tid];
                a1 += p * EOf[s2 * 512 + tid + 256];
            }
            float* ap = g_attp[bB][part];
            ap[tid] = a0;
            ap[tid + 256] = a1;
            if (tid == 0) ap[513] = lloc;
        }
        bgen++; grid_bar(1, bgen);

        // ---- phase C: combine 4 partials -> g_ctx_f16 ----
        if (tid < 128) {
            const int h = part * 128 + tid;
            float l = __ldcg(&g_attp[bB][0][513]) + __ldcg(&g_attp[bB][1][513])
                    + __ldcg(&g_attp[bB][2][513]) + __ldcg(&g_attp[bB][3][513]);
            float cx = __ldcg(&g_attp[bB][0][h]) + __ldcg(&g_attp[bB][1][h])
                     + __ldcg(&g_attp[bB][2][h]) + __ldcg(&g_attp[bB][3][h]);
            g_ctx_f16[(bB << 9) + h] = __float2half_rn(cx / l);
        }
        bgen++; grid_bar(1, bgen);

        // ---- phase D: gates ctx-part + pointwise ----
        float xg[4];
        if (tid < 128) {
            #pragma unroll
            for (int gate = 0; gate < 4; gate++)
                xg[gate] = __ldcg(&g_dec_xg[((size_t)t * Bsz + bq) * FH + gate * Hd + hG * 4 + hl]);
        }
        for (int i = tid; i < 2048; i += 256) {
            int b = i >> 6, k8 = (i & 63) * 8;
            *(uint4*)&HXh[b * 520 + k8] = __ldcg((const uint4*)&g_ctx_f16[(b << 9) + k8]);
        }
        __syncthreads();
        gates_mma(sb, D_WC, D_HX, wid, lrow, lcol, accf);
        gates_store(RDf, wid, lane, accf);
        __syncthreads();

        if (tid < 128) {
            float g4[4];
            #pragma unroll
            for (int gate = 0; gate < 4; gate++) {
                int r = gate * 4 + hl;
                float a = 0.f;
                #pragma unroll
                for (int q = 0; q < 8; q++) a += RDf[q * 528 + r * 33 + bq];
                g4[gate] = a + xg[gate];
            }
            float cv = sigf(g4[1]) * c_reg + sigf(g4[0]) * tanhf(g4[2]);
            float hn = sigf(g4[3]) * tanhf(cv);
            c_reg = cv;
            __half hh = __float2half_rn(hn);
            hout[(bq << 9) + hG * 4 + hl] = hh;
            g_hs_f16[((size_t)bq * T1 + t) * Hd + hG * 4 + hl] = hh;
        }
        bgen++; grid_bar(1, bgen);
    }
}

// ---------------- fc_W fp16 conversion ----------------
__global__ void conv_w_kernel(const float* __restrict__ fc_W) {
    size_t i = ((size_t)blockIdx.x * 256 + threadIdx.x) * 4;
    if (i >= (size_t)Vsz * Hd) return;
    float4 x = *(const float4*)&fc_W[i];
    g_fcw_f16[i + 0] = __float2half_rn(x.x);
    g_fcw_f16[i + 1] = __float2half_rn(x.y);
    g_fcw_f16[i + 2] = __float2half_rn(x.z);
    g_fcw_f16[i + 3] = __float2half_rn(x.w);
}

// ---------------- FC GEMM: single-pass fp16, 128x128 tile, occ 2, cp.async 2-stage ----------------
#define FCA_B  18432u
#define FCSTG  36864u
#define FC_SMEM_BYTES (2 * FCSTG)
__global__ void __launch_bounds__(256, 2) fc_mma_kernel(
    const float* __restrict__ fc_b, float* __restrict__ out)
{
    extern __shared__ __half smh[];
    const int tid = threadIdx.x, lane = tid & 31, wid = tid >> 5;
    const int wm = wid & 3, wn = wid >> 2;
    const int m0 = blockIdx.x * 128, n0 = blockIdx.y * 128;
    const uint32_t smem_base = smem_to_u32(smh);

    const __half* baseA = g_hs_f16  + (size_t)m0 * Hd;
    const __half* baseB = g_fcw_f16 + (size_t)n0 * Hd;

    float acc[2][8][4];
    #pragma unroll
    for (int a = 0; a < 2; a++)
        #pragma unroll
        for (int b = 0; b < 8; b++)
            #pragma unroll
            for (int c = 0; c < 4; c++) acc[a][b][c] = 0.f;

    const int lrow = ((lane >> 3) & 1) * 8 + (lane & 7);
    const int lcol = (lane >> 4) * 8;

    auto issue_stage = [&](int kc, int stg) {
        uint32_t sbs = smem_base + (uint32_t)stg * FCSTG;
        #pragma unroll
        for (int tt = 0; tt < 4; tt++) {
            int idx = tid + tt * 256;
            int r = idx >> 3, c8 = idx & 7;
            uint32_t doff = (uint32_t)(r * 144 + c8 * 16);
            size_t gi = (size_t)r * Hd + kc * 64 + c8 * 8;
            cp_async16(sbs + doff,         baseA + gi);
            cp_async16(sbs + FCA_B + doff, baseB + gi);
        }
        asm volatile("cp.async.commit_group;" ::: "memory");
    };

    issue_stage(0, 0);

    for (int kc = 0; kc < 8; kc++) {
        const int stg = kc & 1;
        if (kc < 7) {
            issue_stage(kc + 1, stg ^ 1);
            asm volatile("cp.async.wait_group 1;" ::: "memory");
        } else {
            asm volatile("cp.async.wait_group 0;" ::: "memory");
        }
        __syncthreads();

        const uint32_t sbs = smem_base + (uint32_t)stg * FCSTG;
        #pragma unroll
        for (int kk = 0; kk < 4; kk++) {
            uint32_t a[2][4], b[4][4];
            #pragma unroll
            for (int mt = 0; mt < 2; mt++) {
                uint32_t off = sbs + (uint32_t)(((wm * 32 + mt * 16 + lrow) * 72 + kk * 16 + lcol) * 2);
                ldsm_x4(a[mt], off);
            }
            #pragma unroll
            for (int ng = 0; ng < 4; ng++) {
                uint32_t off = sbs + FCA_B +
                    (uint32_t)(((wn * 64 + ng * 16 + lrow) * 72 + kk * 16 + lcol) * 2);
                ldsm_x4(b[ng], off);
            }
            #pragma unroll
            for (int mt = 0; mt < 2; mt++)
                #pragma unroll
                for (int ng = 0; ng < 4; ng++) {
                    mma_f16(acc[mt][ng * 2],     a[mt], b[ng][0], b[ng][2]);
                    mma_f16(acc[mt][ng * 2 + 1], a[mt], b[ng][1], b[ng][3]);
                }
        }
        __syncthreads();
    }

    const int rbase = m0 + wm * 32 + (lane >> 2);
    const int cbase = n0 + wn * 64 + (lane & 3) * 2;
    #pragma unroll
    for (int mt = 0; mt < 2; mt++)
        #pragma unroll
        for (int nt = 0; nt < 8; nt++) {
            int c = cbase + nt * 8;
            float b0 = fc_b[c], b1 = fc_b[c + 1];
            int r0 = rbase + mt * 16;
            if (r0 < Mrows) {
                float2 v = make_float2(acc[mt][nt][0] + b0, acc[mt][nt][1] + b1);
                *(float2*)&out[(size_t)r0 * Vsz + c] = v;
            }
            int r1 = r0 + 8;
            if (r1 < Mrows) {
                float2 v = make_float2(acc[mt][nt][2] + b0, acc[mt][nt][3] + b1);
                *(float2*)&out[(size_t)r1 * Vsz + c] = v;
            }
        }
}

// ---------------- launch ----------------
extern "C" void kernel_launch(void* const* d_in, const int* in_sizes, int n_in,
                              void* d_out, int out_size)
{
    const int*   src     = (const int*)d_in[0];
    const int*   tgt     = (const int*)d_in[1];
    const float* embed   = (const float*)d_in[2];
    const float* enc_Wih = (const float*)d_in[3];
    const float* enc_Whh = (const float*)d_in[4];
    const float* enc_bih = (const float*)d_in[5];
    const float* enc_bhh = (const float*)d_in[6];
    const float* dec_Wih = (const float*)d_in[7];
    const float* dec_Whh = (const float*)d_in[8];
    const float* dec_bih = (const float*)d_in[9];
    const float* dec_bhh = (const float*)d_in[10];
    const float* attn_W  = (const float*)d_in[11];
    const float* attn_b  = (const float*)d_in[12];
    const float* attn_v  = (const float*)d_in[13];
    const float* fc_W    = (const float*)d_in[14];
    const float* fc_b    = (const float*)d_in[15];
    float* out = (float*)d_out;

    float *p_src_emb, *p_dec_in, *p_enc_xg, *p_dec_xg, *p_enc_out, *p_enc_proj;
    cudaGetSymbolAddress((void**)&p_src_emb,  g_src_emb);
    cudaGetSymbolAddress((void**)&p_dec_in,   g_dec_in);
    cudaGetSymbolAddress((void**)&p_enc_xg,   g_enc_xg);
    cudaGetSymbolAddress((void**)&p_dec_xg,   g_dec_xg);
    cudaGetSymbolAddress((void**)&p_enc_out,  g_enc_out);
    cudaGetSymbolAddress((void**)&p_enc_proj, g_enc_proj);

    cudaFuncSetAttribute(enc_scan_kernel, cudaFuncAttributeMaxDynamicSharedMemorySize, ENC_SMEM_BYTES);
    cudaFuncSetAttribute(dec_scan_kernel, cudaFuncAttributeMaxDynamicSharedMemorySize, DEC_SMEM_BYTES);
    cudaFuncSetAttribute(fc_mma_kernel,  cudaFuncAttributeMaxDynamicSharedMemorySize, FC_SMEM_BYTES);

    static cudaStream_t s2 = nullptr;
    static cudaEvent_t evFork = nullptr, evJoin = nullptr;
    if (s2 == nullptr) {
        cudaStreamCreateWithFlags(&s2, cudaStreamNonBlocking);
        cudaEventCreateWithFlags(&evFork, cudaEventDisableTiming);
        cudaEventCreateWithFlags(&evJoin, cudaEventDisableTiming);
    }

    init_state_kernel<<<(Bsz * Hd + 255) / 256, 256>>>();
    gather_src_kernel<<<Ssz * Bsz, Ed>>>(src, embed);

    // fork: decoder-input branch runs concurrently with encoder path
    cudaEventRecord(evFork, 0);
    cudaStreamWaitEvent(s2, evFork, 0);
    gather_dec_kernel<<<T1 * Bsz, Ed, 0, s2>>>(tgt, embed);
    {
        dim3 grid(FH / 128, (T1 * Bsz + 127) / 128);
        sgemm_bias_kernel<<<grid, 256, 0, s2>>>(p_dec_in, Ed, dec_Wih, Ed + Hd, 0,
                                                dec_bih, dec_bhh, p_dec_xg, T1 * Bsz, FH);
    }
    conv_w_kernel<<<(Vsz * Hd / 4 + 255) / 256, 256, 0, s2>>>(fc_W);
    cudaEventRecord(evJoin, s2);

    {   // enc_xg
        dim3 grid(FH / 128, (Ssz * Bsz + 127) / 128);
        sgemm_bias_kernel<<<grid, 256>>>(p_src_emb, Ed, enc_Wih, Ed, 0,
                                         enc_bih, enc_bhh, p_enc_xg, Ssz * Bsz, FH);
    }

    enc_scan_kernel<<<NBLK, 256, ENC_SMEM_BYTES>>>(enc_Whh);

    {   // enc_proj
        dim3 grid(Hd / 128, (Bsz * Ssz + 127) / 128);
        sgemm_bias_kernel<<<grid, 256>>>(p_enc_out, Hd, attn_W, 2 * Hd, Hd,
                                         attn_b, nullptr, p_enc_proj, Bsz * Ssz, Hd);
    }

    cudaStreamWaitEvent(0, evJoin, 0);

    dec_scan_kernel<<<NBLK, 256, DEC_SMEM_BYTES>>>(dec_Wih, dec_Whh, attn_W, attn_v);

    fc_mma_kernel<<<dim3(MrowsPad / 128, Vsz / 128), 256, FC_SMEM_BYTES>>>(fc_b, out);
}

// round 16
// speedup vs baseline: 1.5718x; 1.0619x over previous
#include <cuda_runtime.h>
#include <cuda_bf16.h>
#include <cuda_fp16.h>
#include <cstddef>
#include <cstdint>

#define Bsz 32
#define Ssz 128
#define Tsz 64
#define T1  63
#define Ed  256
#define Hd  512
#define Vsz 32000
#define FH  2048
#define NBLK 128
#define Mrows 2016       // Bsz*T1
#define MrowsPad 2048

// ---------------- device scratch ----------------
__device__ __align__(16) __half g_src_emb_f16[(size_t)Ssz * Bsz * Ed];
__device__ __align__(16) float g_dec_in [(size_t)T1  * Bsz * Ed];
__device__ __align__(16) float g_enc_xg [(size_t)Ssz * Bsz * FH];
__device__ __align__(16) float g_dec_xg [(size_t)T1  * Bsz * FH];
__device__ __align__(16) __half g_enc_out_f16[(size_t)Bsz * Ssz * Hd];
__device__ __align__(16) float g_enc_proj[(size_t)Bsz * Ssz * Hd];
__device__ __align__(16) __half g_h[2][Bsz * Hd];      // recurrent h in fp16
__device__ __align__(16) float g_c [Bsz * Hd];
__device__ __align__(16) __half g_ctx_f16[Bsz * Hd];   // attention context fp16
__device__ __align__(16) float g_hproj[Bsz * Hd];
__device__ __align__(16) float g_attp[Bsz][4][516];    // per-part: ctx[512], l@513
__device__ unsigned g_cnt[2];
__device__ unsigned g_gen[2];
// fp16 GEMM operand buffers
__device__ __align__(16) __half g_hs_f16  [(size_t)MrowsPad * Hd];
__device__ __align__(16) __half g_fcw_f16 [(size_t)Vsz * Hd];
__device__ __align__(16) __half g_encWih_f16[(size_t)FH * Ed];
__device__ __align__(16) __half g_attnWe_f16[(size_t)Hd * Hd];

__device__ __forceinline__ float sigf(float x) { return 1.0f / (1.0f + expf(-x)); }
__device__ __forceinline__ float tanh_fast(float x) {
    float y;
    asm("tanh.approx.f32 %0, %1;" : "=f"(y) : "f"(x));
    return y;
}

// ---------------- packed f32x2 FMA (fp32 sgemm only) ----------------
__device__ __forceinline__ void ffma2(unsigned long long& d, unsigned long long a, unsigned long long b) {
    asm("fma.rn.f32x2 %0, %1, %2, %0;" : "+l"(d) : "l"(a), "l"(b));
}
__device__ __forceinline__ void f32x2_unpack(unsigned long long v, float& lo, float& hi) {
    asm("mov.b64 {%0, %1}, %2;" : "=f"(lo), "=f"(hi) : "l"(v));
}
__device__ __forceinline__ unsigned long long pack2(float lo, float hi) {
    unsigned long long v;
    asm("mov.b64 %0, {%1, %2};" : "=l"(v) : "f"(lo), "f"(hi));
    return v;
}

__device__ __forceinline__ uint32_t smem_to_u32(const void* p) {
    uint32_t a;
    asm("{ .reg .u64 t; cvta.to.shared.u64 t, %1; cvt.u32.u64 %0, t; }" : "=r"(a) : "l"(p));
    return a;
}
__device__ __forceinline__ void ldsm_x4(uint32_t* r, uint32_t addr) {
    asm volatile("ldmatrix.sync.aligned.m8n8.x4.shared.b16 {%0,%1,%2,%3}, [%4];"
        : "=r"(r[0]), "=r"(r[1]), "=r"(r[2]), "=r"(r[3]) : "r"(addr));
}
__device__ __forceinline__ void mma_f16(float* d, const uint32_t* a, uint32_t b0, uint32_t b1) {
    asm volatile("mma.sync.aligned.m16n8k16.row.col.f32.f16.f16.f32 "
        "{%0,%1,%2,%3}, {%4,%5,%6,%7}, {%8,%9}, {%0,%1,%2,%3};"
        : "+f"(d[0]), "+f"(d[1]), "+f"(d[2]), "+f"(d[3])
        : "r"(a[0]), "r"(a[1]), "r"(a[2]), "r"(a[3]), "r"(b0), "r"(b1));
}
__device__ __forceinline__ void cp_async16(uint32_t dst, const void* src) {
    asm volatile("cp.async.cg.shared.global [%0], [%1], 16;" :: "r"(dst), "l"(src) : "memory");
}

// ---------------- global barrier ----------------
__device__ __forceinline__ void grid_bar(int which, unsigned target) {
    __threadfence();
    __syncthreads();
    if (threadIdx.x == 0) {
        unsigned arr = atomicAdd(&g_cnt[which], 1u);
        if (arr == NBLK - 1u) {
            g_cnt[which] = 0u;
            __threadfence();
            atomicAdd(&g_gen[which], 1u);
        } else {
            const volatile unsigned* gp = (const volatile unsigned*)&g_gen[which];
            while (*gp < target) { }
        }
    }
    __syncthreads();
}

__global__ void init_state_kernel() {
    int i = blockIdx.x * blockDim.x + threadIdx.x;
    if (i < Bsz * Hd) g_h[0][i] = __float2half(0.f);
    if (i < 2) { g_cnt[i] = 0u; g_gen[i] = 0u; }
    if (i < (MrowsPad - Mrows) * Hd) {
        g_hs_f16[(size_t)Mrows * Hd + i] = __float2half(0.f);
    }
}

// ---------------- embedding gathers ----------------
__global__ void gather_src_kernel(const int* __restrict__ src, const float* __restrict__ embed) {
    int row = blockIdx.x;           // s*B + b
    int s = row >> 5, b = row & 31;
    int idx = src[b * Ssz + s];
    g_src_emb_f16[(size_t)row * Ed + threadIdx.x] =
        __float2half_rn(embed[(size_t)idx * Ed + threadIdx.x]);
}
__global__ void gather_dec_kernel(const int* __restrict__ tgt, const float* __restrict__ embed) {
    int row = blockIdx.x;           // t*B + b
    int t = row >> 5, b = row & 31;
    int idx = tgt[b * Tsz + t];
    g_dec_in[(size_t)row * Ed + threadIdx.x] = embed[(size_t)idx * Ed + threadIdx.x];
}

// ---------------- weight fp16 conversions ----------------
__global__ void conv_weights_kernel(const float* __restrict__ enc_Wih,
                                    const float* __restrict__ attn_W) {
    size_t i = ((size_t)blockIdx.x * 256 + threadIdx.x) * 4;
    if (i < (size_t)FH * Ed) {
        float4 x = *(const float4*)&enc_Wih[i];
        g_encWih_f16[i + 0] = __float2half_rn(x.x);
        g_encWih_f16[i + 1] = __float2half_rn(x.y);
        g_encWih_f16[i + 2] = __float2half_rn(x.z);
        g_encWih_f16[i + 3] = __float2half_rn(x.w);
    }
    if (i < (size_t)Hd * Hd) {
        int r = (int)(i >> 9), k = (int)(i & 511);
        float4 x = *(const float4*)&attn_W[(size_t)r * (2 * Hd) + Hd + k];
        g_attnWe_f16[i + 0] = __float2half_rn(x.x);
        g_attnWe_f16[i + 1] = __float2half_rn(x.y);
        g_attnWe_f16[i + 2] = __float2half_rn(x.z);
        g_attnWe_f16[i + 3] = __float2half_rn(x.w);
    }
}
__global__ void conv_w_kernel(const float* __restrict__ fc_W) {
    size_t i = ((size_t)blockIdx.x * 256 + threadIdx.x) * 4;
    if (i >= (size_t)Vsz * Hd) return;
    float4 x = *(const float4*)&fc_W[i];
    g_fcw_f16[i + 0] = __float2half_rn(x.x);
    g_fcw_f16[i + 1] = __float2half_rn(x.y);
    g_fcw_f16[i + 2] = __float2half_rn(x.z);
    g_fcw_f16[i + 3] = __float2half_rn(x.w);
}

// ---------------- fp32 SGEMM (dec_xg only; overlapped on side stream) ----------------
__global__ void __launch_bounds__(256) sgemm_bias_kernel(
    const float* __restrict__ A, int K,
    const float* __restrict__ W, int ldw, int woff,
    const float* __restrict__ b1, const float* __restrict__ b2,
    float* __restrict__ C, int M, int N)
{
    __shared__ __align__(16) float As[8][128];
    __shared__ __align__(16) float Bs[8][128];
    const int bm = blockIdx.y * 128;
    const int bn = blockIdx.x * 128;
    const int t  = threadIdx.x;
    const int tr = (t >> 4) * 8;
    const int tc = (t & 15) * 8;
    const int lr = t >> 1;
    const int lc = (t & 1) * 4;

    unsigned long long acc2[8][4];
    #pragma unroll
    for (int i = 0; i < 8; i++)
        #pragma unroll
        for (int j = 0; j < 4; j++) acc2[i][j] = 0ull;

    const bool aValid = (bm + lr) < M;
    const float* aRow = A + (size_t)(bm + lr) * K + lc;
    const float* wRow = W + (size_t)(bn + lr) * ldw + woff + lc;

    for (int k0 = 0; k0 < K; k0 += 8) {
        float4 av = aValid ? *(const float4*)(aRow + k0) : make_float4(0.f, 0.f, 0.f, 0.f);
        float4 wv = *(const float4*)(wRow + k0);
        As[lc + 0][lr] = av.x; As[lc + 1][lr] = av.y; As[lc + 2][lr] = av.z; As[lc + 3][lr] = av.w;
        Bs[lc + 0][lr] = wv.x; Bs[lc + 1][lr] = wv.y; Bs[lc + 2][lr] = wv.z; Bs[lc + 3][lr] = wv.w;
        __syncthreads();
        #pragma unroll
        for (int kk = 0; kk < 8; kk++) {
            float a[8];
            *(float4*)(a)      = *(const float4*)&As[kk][tr];
            *(float4*)(a + 4)  = *(const float4*)&As[kk][tr + 4];
            unsigned long long bb2[4];
            *(ulonglong2*)&bb2[0] = *(const ulonglong2*)&Bs[kk][tc];
            *(ulonglong2*)&bb2[2] = *(const ulonglong2*)&Bs[kk][tc + 4];
            #pragma unroll
            for (int i = 0; i < 8; i++) {
                unsigned long long ap = pack2(a[i], a[i]);
                #pragma unroll
                for (int j = 0; j < 4; j++) ffma2(acc2[i][j], ap, bb2[j]);
            }
        }
        __syncthreads();
    }

    float bias[8];
    #pragma unroll
    for (int j = 0; j < 8; j++) {
        int n = bn + tc + j;
        bias[j] = b1[n] + (b2 ? b2[n] : 0.f);
    }
    #pragma unroll
    for (int i = 0; i < 8; i++) {
        int m = bm + tr + i;
        if (m >= M) break;
        float* cp = C + (size_t)m * N + bn + tc;
        #pragma unroll
        for (int j = 0; j < 4; j++) {
            float lo, hi;
            f32x2_unpack(acc2[i][j], lo, hi);
            cp[j * 2]     = lo + bias[j * 2];
            cp[j * 2 + 1] = hi + bias[j * 2 + 1];
        }
    }
}

// ---------------- generic fp16 GEMM: C[m,n] = A[m,:].W[n,:] + b1[n] (+b2[n]) ----------------
// 128x128 tile, 8 warps = 4(m) x 2(n), warp 32x64. K in chunks of 64 (nkc chunks).
#define FCA_B  18432u                    // per-operand chunk tile bytes (128*72*2)
#define FCSTG  36864u                    // stage bytes
#define FC_SMEM_BYTES (2 * FCSTG)        // 73728
__global__ void __launch_bounds__(256, 2) hgemm_bias_kernel(
    const __half* __restrict__ Abase, const __half* __restrict__ Wbase, int K, int nkc,
    const float* __restrict__ b1, const float* __restrict__ b2,
    float* __restrict__ C, int Mreal, int N)
{
    extern __shared__ __half smh[];
    const int tid = threadIdx.x, lane = tid & 31, wid = tid >> 5;
    const int wm = wid & 3, wn = wid >> 2;
    const int m0 = blockIdx.x * 128, n0 = blockIdx.y * 128;
    const uint32_t smem_base = smem_to_u32(smh);

    const __half* baseA = Abase + (size_t)m0 * K;
    const __half* baseB = Wbase + (size_t)n0 * K;

    float acc[2][8][4];
    #pragma unroll
    for (int a = 0; a < 2; a++)
        #pragma unroll
        for (int b = 0; b < 8; b++)
            #pragma unroll
            for (int c = 0; c < 4; c++) acc[a][b][c] = 0.f;

    const int lrow = ((lane >> 3) & 1) * 8 + (lane & 7);
    const int lcol = (lane >> 4) * 8;

    auto issue_stage = [&](int kc, int stg) {
        uint32_t sbs = smem_base + (uint32_t)stg * FCSTG;
        #pragma unroll
        for (int tt = 0; tt < 4; tt++) {
            int idx = tid + tt * 256;
            int r = idx >> 3, c8 = idx & 7;
            uint32_t doff = (uint32_t)(r * 144 + c8 * 16);
            size_t gi = (size_t)r * K + kc * 64 + c8 * 8;
            cp_async16(sbs + doff,         baseA + gi);
            cp_async16(sbs + FCA_B + doff, baseB + gi);
        }
        asm volatile("cp.async.commit_group;" ::: "memory");
    };

    issue_stage(0, 0);

    for (int kc = 0; kc < nkc; kc++) {
        const int stg = kc & 1;
        if (kc < nkc - 1) {
            issue_stage(kc + 1, stg ^ 1);
            asm volatile("cp.async.wait_group 1;" ::: "memory");
        } else {
            asm volatile("cp.async.wait_group 0;" ::: "memory");
        }
        __syncthreads();

        const uint32_t sbs = smem_base + (uint32_t)stg * FCSTG;
        #pragma unroll
        for (int kk = 0; kk < 4; kk++) {
            uint32_t a[2][4], b[4][4];
            #pragma unroll
            for (int mt = 0; mt < 2; mt++) {
                uint32_t off = sbs + (uint32_t)(((wm * 32 + mt * 16 + lrow) * 72 + kk * 16 + lcol) * 2);
                ldsm_x4(a[mt], off);
            }
            #pragma unroll
            for (int ng = 0; ng < 4; ng++) {
                uint32_t off = sbs + FCA_B +
                    (uint32_t)(((wn * 64 + ng * 16 + lrow) * 72 + kk * 16 + lcol) * 2);
                ldsm_x4(b[ng], off);
            }
            #pragma unroll
            for (int mt = 0; mt < 2; mt++)
                #pragma unroll
                for (int ng = 0; ng < 4; ng++) {
                    mma_f16(acc[mt][ng * 2],     a[mt], b[ng][0], b[ng][2]);
                    mma_f16(acc[mt][ng * 2 + 1], a[mt], b[ng][1], b[ng][3]);
                }
        }
        __syncthreads();
    }

    const int rbase = m0 + wm * 32 + (lane >> 2);
    const int cbase = n0 + wn * 64 + (lane & 3) * 2;
    #pragma unroll
    for (int mt = 0; mt < 2; mt++)
        #pragma unroll
        for (int nt = 0; nt < 8; nt++) {
            int c = cbase + nt * 8;
            float bb0 = b1[c]     + (b2 ? b2[c]     : 0.f);
            float bb1 = b1[c + 1] + (b2 ? b2[c + 1] : 0.f);
            int r0 = rbase + mt * 16;
            if (r0 < Mreal) {
                float2 v = make_float2(acc[mt][nt][0] + bb0, acc[mt][nt][1] + bb1);
                *(float2*)&C[(size_t)r0 * N + c] = v;
            }
            int r1 = r0 + 8;
            if (r1 < Mreal) {
                float2 v = make_float2(acc[mt][nt][2] + bb0, acc[mt][nt][3] + bb1);
                *(float2*)&C[(size_t)r1 * N + c] = v;
            }
        }
}

// ---------------- warp-level gate GEMM via mma.sync (fp16) ----------------
__device__ __forceinline__ void gates_mma(
    uint32_t sb, uint32_t woff, uint32_t xoff, int wid, int lrow, int lcol, float accf[4][4])
{
    #pragma unroll
    for (int kk = 0; kk < 4; kk++) {
        const int kb = wid * 64 + kk * 16;
        uint32_t av[4], b0[4], b1[4];
        ldsm_x4(av, sb + woff + (uint32_t)((lrow * 520 + kb + lcol) * 2));
        ldsm_x4(b0, sb + xoff + (uint32_t)((lrow * 520 + kb + lcol) * 2));
        ldsm_x4(b1, sb + xoff + (uint32_t)(((16 + lrow) * 520 + kb + lcol) * 2));
        mma_f16(accf[0], av, b0[0], b0[2]);
        mma_f16(accf[1], av, b0[1], b0[3]);
        mma_f16(accf[2], av, b1[0], b1[2]);
        mma_f16(accf[3], av, b1[1], b1[3]);
    }
}
__device__ __forceinline__ void gates_store(float* RDf, int wid, int lane, const float accf[4][4]) {
    const int r0 = lane >> 2, c0 = (lane & 3) * 2;
    float* rd = RDf + wid * 528;
    #pragma unroll
    for (int ng = 0; ng < 4; ng++) {
        const int c = ng * 8 + c0;
        rd[r0 * 33 + c]           = accf[ng][0];
        rd[r0 * 33 + c + 1]       = accf[ng][1];
        rd[(r0 + 8) * 33 + c]     = accf[ng][2];
        rd[(r0 + 8) * 33 + c + 1] = accf[ng][3];
    }
}

// ---------------- persistent encoder scan (mma gates) ----------------
#define E_W0 0
#define E_HX 16640
#define E_RD 49920
#define ENC_SMEM_BYTES 66816
__global__ void __launch_bounds__(256, 1) enc_scan_kernel(const float* __restrict__ Whh) {
    extern __shared__ char smc[];
    __half* W0h = (__half*)(smc + E_W0);
    __half* HXh = (__half*)(smc + E_HX);
    float*  RDf = (float*)(smc + E_RD);
    const uint32_t sb = smem_to_u32(smc);
    const int tid = threadIdx.x, hG = blockIdx.x;
    const int wid = tid >> 5, lane = tid & 31;
    const int hl = tid >> 5, bq = tid & 31;
    const int lrow = ((lane >> 3) & 1) * 8 + (lane & 7);
    const int lcol = (lane >> 4) * 8;

    for (int i = tid; i < 16 * 512; i += 256) {
        int r = i >> 9, k = i & 511;
        int j = (r >> 2) * Hd + hG * 4 + (r & 3);
        W0h[r * 520 + k] = __float2half_rn(Whh[(size_t)j * Hd + k]);
    }

    float c_reg = 0.f;
    unsigned bgen = 0;

    for (int s = 0; s < Ssz; s++) {
        const __half* hin = g_h[s & 1];
        __half* hout = g_h[(s + 1) & 1];

        float xg[4];
        if (tid < 128) {
            #pragma unroll
            for (int gate = 0; gate < 4; gate++)
                xg[gate] = __ldcg(&g_enc_xg[((size_t)s * Bsz + bq) * FH + gate * Hd + hG * 4 + hl]);
        }

        for (int i = tid; i < 2048; i += 256) {
            int b = i >> 6, k8 = (i & 63) * 8;
            *(uint4*)&HXh[b * 520 + k8] = __ldcg((const uint4*)&hin[(b << 9) + k8]);
        }
        __syncthreads();

        float accf[4][4];
        #pragma unroll
        for (int a = 0; a < 4; a++)
            #pragma unroll
            for (int b2 = 0; b2 < 4; b2++) accf[a][b2] = 0.f;
        gates_mma(sb, E_W0, E_HX, wid, lrow, lcol, accf);
        gates_store(RDf, wid, lane, accf);
        __syncthreads();

        if (tid < 128) {
            float g4[4];
            #pragma unroll
            for (int gate = 0; gate < 4; gate++) {
                int r = gate * 4 + hl;
                float a = 0.f;
                #pragma unroll
                for (int q = 0; q < 8; q++) a += RDf[q * 528 + r * 33 + bq];
                g4[gate] = a + xg[gate];
            }
            float cv = sigf(g4[1]) * c_reg + sigf(g4[0]) * tanhf(g4[2]);
            float hn = sigf(g4[3]) * tanhf(cv);
            c_reg = cv;
            hout[(bq << 9) + hG * 4 + hl] = __float2half_rn(hn);
            g_enc_out_f16[((size_t)bq * Ssz + s) * Hd + hG * 4 + hl] = __float2half_rn(hn);
        }
        bgen++;
        grid_bar(0, bgen);
    }
    if (tid < 128) {
        g_c[(bq << 9) + hG * 4 + hl] = c_reg;
    }
}

// ---------------- persistent decoder scan (mma gates, smem-cached attention) ----------------
#define D_W0 0          // Whh fp16 16x520            (16640)
#define D_WC 16640      // Wih-ctx fp16 16x520        (16640)
#define D_HX 33280      // h/ctx fp16 32x520          (33280)
#define D_WA 66560      // attnW fp32 4x516           (8256)
#define D_RD 74816      // reduce fp32 8x528          (16896)
#define D_HP 91712      // hproj fp32 512             (2048)
#define D_VS 93760      // attn_v fp32 512            (2048)
#define D_SC 95808      // scores fp32 64             (256)
#define D_EP 96064      // enc_proj slice fp32 32x512 (65536)
#define D_EO 161600     // enc_out slice fp16 32x512  (32768)
#define DEC_SMEM_BYTES 194368
__global__ void __launch_bounds__(256, 1) dec_scan_kernel(
    const float* __restrict__ Wih, const float* __restrict__ Whh,
    const float* __restrict__ attnW, const float* __restrict__ attnv)
{
    extern __shared__ char smc[];
    __half* W0h = (__half*)(smc + D_W0);
    __half* WCh = (__half*)(smc + D_WC);
    __half* HXh = (__half*)(smc + D_HX);
    float*  WAf = (float*)(smc + D_WA);
    float*  RDf = (float*)(smc + D_RD);
    float*  HPf = (float*)(smc + D_HP);
    float*  VSf = (float*)(smc + D_VS);
    float*  SCf = (float*)(smc + D_SC);
    float*  EPf = (float*)(smc + D_EP);
    __half* EOh = (__half*)(smc + D_EO);
    const uint32_t sb = smem_to_u32(smc);
    const int tid = threadIdx.x, hG = blockIdx.x;
    const int wid = tid >> 5, lane = tid & 31;
    const int hl = tid >> 5, bq = tid & 31;
    const int lrow = ((lane >> 3) & 1) * 8 + (lane & 7);
    const int lcol = (lane >> 4) * 8;
    const int bB = hG >> 2;
    const int part = hG & 3;

    // prologue loads (once)
    for (int i = tid; i < 16 * 512; i += 256) {
        int r = i >> 9, k = i & 511;
        int j = (r >> 2) * Hd + hG * 4 + (r & 3);
        W0h[r * 520 + k] = __float2half_rn(Whh[(size_t)j * Hd + k]);
        WCh[r * 520 + k] = __float2half_rn(Wih[(size_t)j * (Ed + Hd) + Ed + k]);
    }
    for (int i = tid; i < 4 * 516; i += 256) {
        int r = i / 516, k = i % 516;
        WAf[i] = (k < Hd) ? attnW[(size_t)(hG * 4 + r) * (2 * Hd) + k] : 0.f;
    }
    for (int i = tid; i < Hd; i += 256) VSf[i] = attnv[i];
    for (int i = tid; i < 32 * 128; i += 256) {       // EP fp32 (32x512) via float4
        int sl = i >> 7, k4 = (i & 127) * 4;
        size_t gidx = ((size_t)bB * Ssz + part * 32 + sl) * Hd + k4;
        *(float4*)&EPf[sl * 512 + k4] = *(const float4*)&g_enc_proj[gidx];
    }
    for (int i = tid; i < 2048; i += 256) {           // EO fp16 (32x512) via uint4
        int sl = i >> 6, k8 = (i & 63) * 8;
        size_t gidx = ((size_t)bB * Ssz + part * 32 + sl) * Hd + k8;
        *(uint4*)&EOh[sl * 512 + k8] = *(const uint4*)&g_enc_out_f16[gidx];
    }

    float c_reg = 0.f;
    if (tid < 128) c_reg = __ldcg(&g_c[(bq << 9) + hG * 4 + hl]);
    unsigned bgen = 0;

    for (int t = 0; t < T1; t++) {
        const __half* hin = g_h[t & 1];
        __half* hout = g_h[(t + 1) & 1];

        // ---- phase A: load h, hproj, gates h-part ----
        for (int i = tid; i < 2048; i += 256) {
            int b = i >> 6, k8 = (i & 63) * 8;
            *(uint4*)&HXh[b * 520 + k8] = __ldcg((const uint4*)&hin[(b << 9) + k8]);
        }
        __syncthreads();
        {
            const int ko = tid >> 6, bh = (tid >> 1) & 31, kh = tid & 1;
            const float* wa = WAf + ko * 516 + (kh << 8);
            const __half2* hh = (const __half2*)&HXh[bh * 520 + (kh << 8)];
            float a = 0.f;
            #pragma unroll 8
            for (int k2 = 0; k2 < 128; k2++) {
                float2 h2 = __half22float2(hh[k2]);
                a += wa[k2 * 2] * h2.x + wa[k2 * 2 + 1] * h2.y;
            }
            a += __shfl_xor_sync(0xffffffffu, a, 1);
            if (!kh) g_hproj[(bh << 9) + hG * 4 + ko] = a;
        }
        float accf[4][4];
        #pragma unroll
        for (int a2 = 0; a2 < 4; a2++)
            #pragma unroll
            for (int b2 = 0; b2 < 4; b2++) accf[a2][b2] = 0.f;
        gates_mma(sb, D_W0, D_HX, wid, lrow, lcol, accf);
        bgen++; grid_bar(1, bgen);

        // ---- phase B: attention partials (smem-resident) ----
        for (int i = tid; i < Hd; i += 256) HPf[i] = __ldcg(&g_hproj[(bB << 9) + i]);
        __syncthreads();
        {
            const int w = tid >> 5, ln = tid & 31;
            #pragma unroll
            for (int q = 0; q < 4; q++) {
                int sl = w * 4 + q;
                const float* ep = EPf + sl * 512;
                float a = 0.f;
                for (int kk = ln; kk < Hd; kk += 32)
                    a += tanh_fast(HPf[kk] + ep[kk]) * VSf[kk];
                #pragma unroll
                for (int off = 16; off; off >>= 1) a += __shfl_xor_sync(0xffffffffu, a, off);
                if (!ln) SCf[sl] = a;
            }
        }
        __syncthreads();
        {
            if (tid < 32) SCf[32 + tid] = __expf(SCf[tid]);
            __syncthreads();
            float lloc = 0.f;
            #pragma unroll
            for (int i2 = 0; i2 < 32; i2++) lloc += SCf[32 + i2];

            float a0 = 0.f, a1 = 0.f;
            #pragma unroll 4
            for (int s2 = 0; s2 < 32; s2++) {
                float p = SCf[32 + s2];
                a0 += p * __half2float(EOh[s2 * 512 + tid]);
                a1 += p * __half2float(EOh[s2 * 512 + tid + 256]);
            }
            float* ap = g_attp[bB][part];
            ap[tid] = a0;
            ap[tid + 256] = a1;
            if (tid == 0) ap[513] = lloc;
        }
        bgen++; grid_bar(1, bgen);

        // ---- phase C: combine 4 partials -> g_ctx_f16 ----
        if (tid < 128) {
            const int h = part * 128 + tid;
            float l = __ldcg(&g_attp[bB][0][513]) + __ldcg(&g_attp[bB][1][513])
                    + __ldcg(&g_attp[bB][2][513]) + __ldcg(&g_attp[bB][3][513]);
            float cx = __ldcg(&g_attp[bB][0][h]) + __ldcg(&g_attp[bB][1][h])
                     + __ldcg(&g_attp[bB][2][h]) + __ldcg(&g_attp[bB][3][h]);
            g_ctx_f16[(bB << 9) + h] = __float2half_rn(cx / l);
        }
        bgen++; grid_bar(1, bgen);

        // ---- phase D: gates ctx-part + pointwise ----
        float xg[4];
        if (tid < 128) {
            #pragma unroll
            for (int gate = 0; gate < 4; gate++)
                xg[gate] = __ldcg(&g_dec_xg[((size_t)t * Bsz + bq) * FH + gate * Hd + hG * 4 + hl]);
        }
        for (int i = tid; i < 2048; i += 256) {
            int b = i >> 6, k8 = (i & 63) * 8;
            *(uint4*)&HXh[b * 520 + k8] = __ldcg((const uint4*)&g_ctx_f16[(b << 9) + k8]);
        }
        __syncthreads();
        gates_mma(sb, D_WC, D_HX, wid, lrow, lcol, accf);
        gates_store(RDf, wid, lane, accf);
        __syncthreads();

        if (tid < 128) {
            float g4[4];
            #pragma unroll
            for (int gate = 0; gate < 4; gate++) {
                int r = gate * 4 + hl;
                float a = 0.f;
                #pragma unroll
                for (int q = 0; q < 8; q++) a += RDf[q * 528 + r * 33 + bq];
                g4[gate] = a + xg[gate];
            }
            float cv = sigf(g4[1]) * c_reg + sigf(g4[0]) * tanhf(g4[2]);
            float hn = sigf(g4[3]) * tanhf(cv);
            c_reg = cv;
            __half hh = __float2half_rn(hn);
            hout[(bq << 9) + hG * 4 + hl] = hh;
            g_hs_f16[((size_t)bq * T1 + t) * Hd + hG * 4 + hl] = hh;
        }
        bgen++; grid_bar(1, bgen);
    }
}

// ---------------- launch ----------------
extern "C" void kernel_launch(void* const* d_in, const int* in_sizes, int n_in,
                              void* d_out, int out_size)
{
    const int*   src     = (const int*)d_in[0];
    const int*   tgt     = (const int*)d_in[1];
    const float* embed   = (const float*)d_in[2];
    const float* enc_Wih = (const float*)d_in[3];
    const float* enc_Whh = (const float*)d_in[4];
    const float* enc_bih = (const float*)d_in[5];
    const float* enc_bhh = (const float*)d_in[6];
    const float* dec_Wih = (const float*)d_in[7];
    const float* dec_Whh = (const float*)d_in[8];
    const float* dec_bih = (const float*)d_in[9];
    const float* dec_bhh = (const float*)d_in[10];
    const float* attn_W  = (const float*)d_in[11];
    const float* attn_b  = (const float*)d_in[12];
    const float* attn_v  = (const float*)d_in[13];
    const float* fc_W    = (const float*)d_in[14];
    const float* fc_b    = (const float*)d_in[15];
    float* out = (float*)d_out;

    float *p_dec_in, *p_enc_xg, *p_dec_xg, *p_enc_proj;
    __half *p_src_emb_f16, *p_enc_out_f16, *p_encWih_f16, *p_attnWe_f16, *p_hs_f16, *p_fcw_f16;
    cudaGetSymbolAddress((void**)&p_dec_in,      g_dec_in);
    cudaGetSymbolAddress((void**)&p_enc_xg,      g_enc_xg);
    cudaGetSymbolAddress((void**)&p_dec_xg,      g_dec_xg);
    cudaGetSymbolAddress((void**)&p_enc_proj,    g_enc_proj);
    cudaGetSymbolAddress((void**)&p_src_emb_f16, g_src_emb_f16);
    cudaGetSymbolAddress((void**)&p_enc_out_f16, g_enc_out_f16);
    cudaGetSymbolAddress((void**)&p_encWih_f16,  g_encWih_f16);
    cudaGetSymbolAddress((void**)&p_attnWe_f16,  g_attnWe_f16);
    cudaGetSymbolAddress((void**)&p_hs_f16,      g_hs_f16);
    cudaGetSymbolAddress((void**)&p_fcw_f16,     g_fcw_f16);

    cudaFuncSetAttribute(enc_scan_kernel,  cudaFuncAttributeMaxDynamicSharedMemorySize, ENC_SMEM_BYTES);
    cudaFuncSetAttribute(dec_scan_kernel,  cudaFuncAttributeMaxDynamicSharedMemorySize, DEC_SMEM_BYTES);
    cudaFuncSetAttribute(hgemm_bias_kernel, cudaFuncAttributeMaxDynamicSharedMemorySize, FC_SMEM_BYTES);

    static cudaStream_t s2 = nullptr;
    static cudaEvent_t evFork = nullptr, evJoin = nullptr;
    if (s2 == nullptr) {
        cudaStreamCreateWithFlags(&s2, cudaStreamNonBlocking);
        cudaEventCreateWithFlags(&evFork, cudaEventDisableTiming);
        cudaEventCreateWithFlags(&evJoin, cudaEventDisableTiming);
    }

    init_state_kernel<<<(Bsz * Hd + 255) / 256, 256>>>();
    gather_src_kernel<<<Ssz * Bsz, Ed>>>(src, embed);
    conv_weights_kernel<<<(FH * Ed / 4 + 255) / 256, 256>>>(enc_Wih, attn_W);

    // fork: decoder-input branch runs concurrently with encoder path
    cudaEventRecord(evFork, 0);
    cudaStreamWaitEvent(s2, evFork, 0);
    gather_dec_kernel<<<T1 * Bsz, Ed, 0, s2>>>(tgt, embed);
    {
        dim3 grid(FH / 128, (T1 * Bsz + 127) / 128);
        sgemm_bias_kernel<<<grid, 256, 0, s2>>>(p_dec_in, Ed, dec_Wih, Ed + Hd, 0,
                                                dec_bih, dec_bhh, p_dec_xg, T1 * Bsz, FH);
    }
    conv_w_kernel<<<(Vsz * Hd / 4 + 255) / 256, 256, 0, s2>>>(fc_W);
    cudaEventRecord(evJoin, s2);

    // enc_xg = src_emb_f16 @ encWih_f16^T + (bih+bhh)   (M=4096, N=2048, K=256)
    hgemm_bias_kernel<<<dim3(32, 16), 256, FC_SMEM_BYTES>>>(
        p_src_emb_f16, p_encWih_f16, Ed, Ed / 64,
        enc_bih, enc_bhh, p_enc_xg, Ssz * Bsz, FH);

    enc_scan_kernel<<<NBLK, 256, ENC_SMEM_BYTES>>>(enc_Whh);

    // enc_proj = enc_out_f16 @ attnWe_f16^T + attn_b    (M=4096, N=512, K=512)
    hgemm_bias_kernel<<<dim3(32, 4), 256, FC_SMEM_BYTES>>>(
        p_enc_out_f16, p_attnWe_f16, Hd, Hd / 64,
        attn_b, nullptr, p_enc_proj, Bsz * Ssz, Hd);

    cudaStreamWaitEvent(0, evJoin, 0);

    dec_scan_kernel<<<NBLK, 256, DEC_SMEM_BYTES>>>(dec_Wih, dec_Whh, attn_W, attn_v);

    // final FC = hs_f16 @ fcw_f16^T + fc_b              (M=2016, N=32000, K=512)
    hgemm_bias_kernel<<<dim3(MrowsPad / 128, Vsz / 128), 256, FC_SMEM_BYTES>>>(
        p_hs_f16, p_fcw_f16, Hd, Hd / 64,
        fc_b, nullptr, out, Mrows, Vsz);
}

// round 17
// speedup vs baseline: 1.6342x; 1.0397x over previous
#include <cuda_runtime.h>
#include <cuda_bf16.h>
#include <cuda_fp16.h>
#include <cstddef>
#include <cstdint>

#define Bsz 32
#define Ssz 128
#define Tsz 64
#define T1  63
#define Ed  256
#define Hd  512
#define Vsz 32000
#define FH  2048
#define NBLK 128
#define Mrows 2016       // Bsz*T1
#define MrowsPad 2048

// ---------------- device scratch ----------------
__device__ __align__(16) __half g_src_emb_f16[(size_t)Ssz * Bsz * Ed];
__device__ __align__(16) float g_dec_in [(size_t)T1  * Bsz * Ed];
__device__ __align__(16) float g_enc_xg [(size_t)Ssz * Bsz * FH];
__device__ __align__(16) float g_dec_xg [(size_t)T1  * Bsz * FH];
__device__ __align__(16) __half g_enc_out_f16[(size_t)Bsz * Ssz * Hd];
__device__ __align__(16) float g_enc_proj[(size_t)Bsz * Ssz * Hd];
__device__ __align__(16) __half g_h[2][Bsz * Hd];      // recurrent h in fp16
__device__ __align__(16) float g_c [Bsz * Hd];
__device__ __align__(16) __half g_ctx_f16[Bsz * Hd];   // attention context fp16
__device__ __align__(16) float g_hproj[Bsz * Hd];
__device__ __align__(16) float g_attp[Bsz][4][516];    // per-part: ctx[512], l@513
__device__ unsigned g_cnt[2];
__device__ unsigned g_gen[2];
// fp16 GEMM operand buffers
__device__ __align__(16) __half g_hs_f16  [(size_t)MrowsPad * Hd];
__device__ __align__(16) __half g_fcw_f16 [(size_t)Vsz * Hd];
__device__ __align__(16) __half g_encWih_f16[(size_t)FH * Ed];
__device__ __align__(16) __half g_attnWe_f16[(size_t)Hd * Hd];

__device__ __forceinline__ float sigf(float x) { return 1.0f / (1.0f + __expf(-x)); }
__device__ __forceinline__ float tanh_fast(float x) {
    float y;
    asm("tanh.approx.f32 %0, %1;" : "=f"(y) : "f"(x));
    return y;
}

// ---------------- packed f32x2 FMA (fp32 sgemm only) ----------------
__device__ __forceinline__ void ffma2(unsigned long long& d, unsigned long long a, unsigned long long b) {
    asm("fma.rn.f32x2 %0, %1, %2, %0;" : "+l"(d) : "l"(a), "l"(b));
}
__device__ __forceinline__ void f32x2_unpack(unsigned long long v, float& lo, float& hi) {
    asm("mov.b64 {%0, %1}, %2;" : "=f"(lo), "=f"(hi) : "l"(v));
}
__device__ __forceinline__ unsigned long long pack2(float lo, float hi) {
    unsigned long long v;
    asm("mov.b64 %0, {%1, %2};" : "=l"(v) : "f"(lo), "f"(hi));
    return v;
}

__device__ __forceinline__ uint32_t smem_to_u32(const void* p) {
    uint32_t a;
    asm("{ .reg .u64 t; cvta.to.shared.u64 t, %1; cvt.u32.u64 %0, t; }" : "=r"(a) : "l"(p));
    return a;
}
__device__ __forceinline__ void ldsm_x4(uint32_t* r, uint32_t addr) {
    asm volatile("ldmatrix.sync.aligned.m8n8.x4.shared.b16 {%0,%1,%2,%3}, [%4];"
        : "=r"(r[0]), "=r"(r[1]), "=r"(r[2]), "=r"(r[3]) : "r"(addr));
}
__device__ __forceinline__ void mma_f16(float* d, const uint32_t* a, uint32_t b0, uint32_t b1) {
    asm volatile("mma.sync.aligned.m16n8k16.row.col.f32.f16.f16.f32 "
        "{%0,%1,%2,%3}, {%4,%5,%6,%7}, {%8,%9}, {%0,%1,%2,%3};"
        : "+f"(d[0]), "+f"(d[1]), "+f"(d[2]), "+f"(d[3])
        : "r"(a[0]), "r"(a[1]), "r"(a[2]), "r"(a[3]), "r"(b0), "r"(b1));
}
__device__ __forceinline__ void cp_async16(uint32_t dst, const void* src) {
    asm volatile("cp.async.cg.shared.global [%0], [%1], 16;" :: "r"(dst), "l"(src) : "memory");
}

// ---------------- global barrier (arrive/wait split) ----------------
__device__ __forceinline__ void grid_arrive(int which) {
    __threadfence();
    __syncthreads();
    if (threadIdx.x == 0) {
        unsigned arr = atomicAdd(&g_cnt[which], 1u);
        if (arr == NBLK - 1u) {
            g_cnt[which] = 0u;
            __threadfence();
            atomicAdd(&g_gen[which], 1u);
        }
    }
}
__device__ __forceinline__ void grid_wait(int which, unsigned target) {
    if (threadIdx.x == 0) {
        const volatile unsigned* gp = (const volatile unsigned*)&g_gen[which];
        while (*gp < target) { }
    }
    __syncthreads();
}
__device__ __forceinline__ void grid_bar(int which, unsigned target) {
    grid_arrive(which);
    grid_wait(which, target);
}

__global__ void init_state_kernel() {
    int i = blockIdx.x * blockDim.x + threadIdx.x;
    if (i < Bsz * Hd) g_h[0][i] = __float2half(0.f);
    if (i < 2) { g_cnt[i] = 0u; g_gen[i] = 0u; }
    if (i < (MrowsPad - Mrows) * Hd) {
        g_hs_f16[(size_t)Mrows * Hd + i] = __float2half(0.f);
    }
}

// ---------------- embedding gathers ----------------
__global__ void gather_src_kernel(const int* __restrict__ src, const float* __restrict__ embed) {
    int row = blockIdx.x;           // s*B + b
    int s = row >> 5, b = row & 31;
    int idx = src[b * Ssz + s];
    g_src_emb_f16[(size_t)row * Ed + threadIdx.x] =
        __float2half_rn(embed[(size_t)idx * Ed + threadIdx.x]);
}
__global__ void gather_dec_kernel(const int* __restrict__ tgt, const float* __restrict__ embed) {
    int row = blockIdx.x;           // t*B + b
    int t = row >> 5, b = row & 31;
    int idx = tgt[b * Tsz + t];
    g_dec_in[(size_t)row * Ed + threadIdx.x] = embed[(size_t)idx * Ed + threadIdx.x];
}

// ---------------- weight fp16 conversions ----------------
__global__ void conv_weights_kernel(const float* __restrict__ enc_Wih,
                                    const float* __restrict__ attn_W) {
    size_t i = ((size_t)blockIdx.x * 256 + threadIdx.x) * 4;
    if (i < (size_t)FH * Ed) {
        float4 x = *(const float4*)&enc_Wih[i];
        g_encWih_f16[i + 0] = __float2half_rn(x.x);
        g_encWih_f16[i + 1] = __float2half_rn(x.y);
        g_encWih_f16[i + 2] = __float2half_rn(x.z);
        g_encWih_f16[i + 3] = __float2half_rn(x.w);
    }
    if (i < (size_t)Hd * Hd) {
        int r = (int)(i >> 9), k = (int)(i & 511);
        float4 x = *(const float4*)&attn_W[(size_t)r * (2 * Hd) + Hd + k];
        g_attnWe_f16[i + 0] = __float2half_rn(x.x);
        g_attnWe_f16[i + 1] = __float2half_rn(x.y);
        g_attnWe_f16[i + 2] = __float2half_rn(x.z);
        g_attnWe_f16[i + 3] = __float2half_rn(x.w);
    }
}
__global__ void conv_w_kernel(const float* __restrict__ fc_W) {
    size_t i = ((size_t)blockIdx.x * 256 + threadIdx.x) * 4;
    if (i >= (size_t)Vsz * Hd) return;
    float4 x = *(const float4*)&fc_W[i];
    g_fcw_f16[i + 0] = __float2half_rn(x.x);
    g_fcw_f16[i + 1] = __float2half_rn(x.y);
    g_fcw_f16[i + 2] = __float2half_rn(x.z);
    g_fcw_f16[i + 3] = __float2half_rn(x.w);
}

// ---------------- fp32 SGEMM (dec_xg only; overlapped on side stream) ----------------
__global__ void __launch_bounds__(256) sgemm_bias_kernel(
    const float* __restrict__ A, int K,
    const float* __restrict__ W, int ldw, int woff,
    const float* __restrict__ b1, const float* __restrict__ b2,
    float* __restrict__ C, int M, int N)
{
    __shared__ __align__(16) float As[8][128];
    __shared__ __align__(16) float Bs[8][128];
    const int bm = blockIdx.y * 128;
    const int bn = blockIdx.x * 128;
    const int t  = threadIdx.x;
    const int tr = (t >> 4) * 8;
    const int tc = (t & 15) * 8;
    const int lr = t >> 1;
    const int lc = (t & 1) * 4;

    unsigned long long acc2[8][4];
    #pragma unroll
    for (int i = 0; i < 8; i++)
        #pragma unroll
        for (int j = 0; j < 4; j++) acc2[i][j] = 0ull;

    const bool aValid = (bm + lr) < M;
    const float* aRow = A + (size_t)(bm + lr) * K + lc;
    const float* wRow = W + (size_t)(bn + lr) * ldw + woff + lc;

    for (int k0 = 0; k0 < K; k0 += 8) {
        float4 av = aValid ? *(const float4*)(aRow + k0) : make_float4(0.f, 0.f, 0.f, 0.f);
        float4 wv = *(const float4*)(wRow + k0);
        As[lc + 0][lr] = av.x; As[lc + 1][lr] = av.y; As[lc + 2][lr] = av.z; As[lc + 3][lr] = av.w;
        Bs[lc + 0][lr] = wv.x; Bs[lc + 1][lr] = wv.y; Bs[lc + 2][lr] = wv.z; Bs[lc + 3][lr] = wv.w;
        __syncthreads();
        #pragma unroll
        for (int kk = 0; kk < 8; kk++) {
            float a[8];
            *(float4*)(a)      = *(const float4*)&As[kk][tr];
            *(float4*)(a + 4)  = *(const float4*)&As[kk][tr + 4];
            unsigned long long bb2[4];
            *(ulonglong2*)&bb2[0] = *(const ulonglong2*)&Bs[kk][tc];
            *(ulonglong2*)&bb2[2] = *(const ulonglong2*)&Bs[kk][tc + 4];
            #pragma unroll
            for (int i = 0; i < 8; i++) {
                unsigned long long ap = pack2(a[i], a[i]);
                #pragma unroll
                for (int j = 0; j < 4; j++) ffma2(acc2[i][j], ap, bb2[j]);
            }
        }
        __syncthreads();
    }

    float bias[8];
    #pragma unroll
    for (int j = 0; j < 8; j++) {
        int n = bn + tc + j;
        bias[j] = b1[n] + (b2 ? b2[n] : 0.f);
    }
    #pragma unroll
    for (int i = 0; i < 8; i++) {
        int m = bm + tr + i;
        if (m >= M) break;
        float* cp = C + (size_t)m * N + bn + tc;
        #pragma unroll
        for (int j = 0; j < 4; j++) {
            float lo, hi;
            f32x2_unpack(acc2[i][j], lo, hi);
            cp[j * 2]     = lo + bias[j * 2];
            cp[j * 2 + 1] = hi + bias[j * 2 + 1];
        }
    }
}

// ---------------- generic fp16 GEMM ----------------
#define FCA_B  18432u
#define FCSTG  36864u
#define FC_SMEM_BYTES (2 * FCSTG)
__global__ void __launch_bounds__(256, 2) hgemm_bias_kernel(
    const __half* __restrict__ Abase, const __half* __restrict__ Wbase, int K, int nkc,
    const float* __restrict__ b1, const float* __restrict__ b2,
    float* __restrict__ C, int Mreal, int N)
{
    extern __shared__ __half smh[];
    const int tid = threadIdx.x, lane = tid & 31, wid = tid >> 5;
    const int wm = wid & 3, wn = wid >> 2;
    const int m0 = blockIdx.x * 128, n0 = blockIdx.y * 128;
    const uint32_t smem_base = smem_to_u32(smh);

    const __half* baseA = Abase + (size_t)m0 * K;
    const __half* baseB = Wbase + (size_t)n0 * K;

    float acc[2][8][4];
    #pragma unroll
    for (int a = 0; a < 2; a++)
        #pragma unroll
        for (int b = 0; b < 8; b++)
            #pragma unroll
            for (int c = 0; c < 4; c++) acc[a][b][c] = 0.f;

    const int lrow = ((lane >> 3) & 1) * 8 + (lane & 7);
    const int lcol = (lane >> 4) * 8;

    auto issue_stage = [&](int kc, int stg) {
        uint32_t sbs = smem_base + (uint32_t)stg * FCSTG;
        #pragma unroll
        for (int tt = 0; tt < 4; tt++) {
            int idx = tid + tt * 256;
            int r = idx >> 3, c8 = idx & 7;
            uint32_t doff = (uint32_t)(r * 144 + c8 * 16);
            size_t gi = (size_t)r * K + kc * 64 + c8 * 8;
            cp_async16(sbs + doff,         baseA + gi);
            cp_async16(sbs + FCA_B + doff, baseB + gi);
        }
        asm volatile("cp.async.commit_group;" ::: "memory");
    };

    issue_stage(0, 0);

    for (int kc = 0; kc < nkc; kc++) {
        const int stg = kc & 1;
        if (kc < nkc - 1) {
            issue_stage(kc + 1, stg ^ 1);
            asm volatile("cp.async.wait_group 1;" ::: "memory");
        } else {
            asm volatile("cp.async.wait_group 0;" ::: "memory");
        }
        __syncthreads();

        const uint32_t sbs = smem_base + (uint32_t)stg * FCSTG;
        #pragma unroll
        for (int kk = 0; kk < 4; kk++) {
            uint32_t a[2][4], b[4][4];
            #pragma unroll
            for (int mt = 0; mt < 2; mt++) {
                uint32_t off = sbs + (uint32_t)(((wm * 32 + mt * 16 + lrow) * 72 + kk * 16 + lcol) * 2);
                ldsm_x4(a[mt], off);
            }
            #pragma unroll
            for (int ng = 0; ng < 4; ng++) {
                uint32_t off = sbs + FCA_B +
                    (uint32_t)(((wn * 64 + ng * 16 + lrow) * 72 + kk * 16 + lcol) * 2);
                ldsm_x4(b[ng], off);
            }
            #pragma unroll
            for (int mt = 0; mt < 2; mt++)
                #pragma unroll
                for (int ng = 0; ng < 4; ng++) {
                    mma_f16(acc[mt][ng * 2],     a[mt], b[ng][0], b[ng][2]);
                    mma_f16(acc[mt][ng * 2 + 1], a[mt], b[ng][1], b[ng][3]);
                }
        }
        __syncthreads();
    }

    const int rbase = m0 + wm * 32 + (lane >> 2);
    const int cbase = n0 + wn * 64 + (lane & 3) * 2;
    #pragma unroll
    for (int mt = 0; mt < 2; mt++)
        #pragma unroll
        for (int nt = 0; nt < 8; nt++) {
            int c = cbase + nt * 8;
            float bb0 = b1[c]     + (b2 ? b2[c]     : 0.f);
            float bb1 = b1[c + 1] + (b2 ? b2[c + 1] : 0.f);
            int r0 = rbase + mt * 16;
            if (r0 < Mreal) {
                float2 v = make_float2(acc[mt][nt][0] + bb0, acc[mt][nt][1] + bb1);
                *(float2*)&C[(size_t)r0 * N + c] = v;
            }
            int r1 = r0 + 8;
            if (r1 < Mreal) {
                float2 v = make_float2(acc[mt][nt][2] + bb0, acc[mt][nt][3] + bb1);
                *(float2*)&C[(size_t)r1 * N + c] = v;
            }
        }
}

// ---------------- warp-level gate GEMM via mma.sync (fp16) ----------------
__device__ __forceinline__ void gates_mma(
    uint32_t sb, uint32_t woff, uint32_t xoff, int wid, int lrow, int lcol, float accf[4][4])
{
    #pragma unroll
    for (int kk = 0; kk < 4; kk++) {
        const int kb = wid * 64 + kk * 16;
        uint32_t av[4], b0[4], b1[4];
        ldsm_x4(av, sb + woff + (uint32_t)((lrow * 520 + kb + lcol) * 2));
        ldsm_x4(b0, sb + xoff + (uint32_t)((lrow * 520 + kb + lcol) * 2));
        ldsm_x4(b1, sb + xoff + (uint32_t)(((16 + lrow) * 520 + kb + lcol) * 2));
        mma_f16(accf[0], av, b0[0], b0[2]);
        mma_f16(accf[1], av, b0[1], b0[3]);
        mma_f16(accf[2], av, b1[0], b1[2]);
        mma_f16(accf[3], av, b1[1], b1[3]);
    }
}
__device__ __forceinline__ void gates_store(float* RDf, int wid, int lane, const float accf[4][4]) {
    const int r0 = lane >> 2, c0 = (lane & 3) * 2;
    float* rd = RDf + wid * 528;
    #pragma unroll
    for (int ng = 0; ng < 4; ng++) {
        const int c = ng * 8 + c0;
        rd[r0 * 33 + c]           = accf[ng][0];
        rd[r0 * 33 + c + 1]       = accf[ng][1];
        rd[(r0 + 8) * 33 + c]     = accf[ng][2];
        rd[(r0 + 8) * 33 + c + 1] = accf[ng][3];
    }
}

// ---------------- persistent encoder scan (mma gates, arrive/prefetch/wait) ----------------
#define E_W0 0
#define E_HX 16640
#define E_RD 49920
#define ENC_SMEM_BYTES 66816
__global__ void __launch_bounds__(256, 1) enc_scan_kernel(const float* __restrict__ Whh) {
    extern __shared__ char smc[];
    __half* W0h = (__half*)(smc + E_W0);
    __half* HXh = (__half*)(smc + E_HX);
    float*  RDf = (float*)(smc + E_RD);
    const uint32_t sb = smem_to_u32(smc);
    const int tid = threadIdx.x, hG = blockIdx.x;
    const int wid = tid >> 5, lane = tid & 31;
    const int hl = tid >> 5, bq = tid & 31;
    const int lrow = ((lane >> 3) & 1) * 8 + (lane & 7);
    const int lcol = (lane >> 4) * 8;

    for (int i = tid; i < 16 * 512; i += 256) {
        int r = i >> 9, k = i & 511;
        int j = (r >> 2) * Hd + hG * 4 + (r & 3);
        W0h[r * 520 + k] = __float2half_rn(Whh[(size_t)j * Hd + k]);
    }

    float c_reg = 0.f;
    unsigned bgen = 0;

    float xg[4];
    if (tid < 128) {
        #pragma unroll
        for (int gate = 0; gate < 4; gate++)
            xg[gate] = __ldcg(&g_enc_xg[(size_t)bq * FH + gate * Hd + hG * 4 + hl]);
    }

    for (int s = 0; s < Ssz; s++) {
        if (s > 0) grid_wait(0, bgen);

        const __half* hin = g_h[s & 1];
        __half* hout = g_h[(s + 1) & 1];

        for (int i = tid; i < 2048; i += 256) {
            int b = i >> 6, k8 = (i & 63) * 8;
            *(uint4*)&HXh[b * 520 + k8] = __ldcg((const uint4*)&hin[(b << 9) + k8]);
        }
        __syncthreads();

        float accf[4][4];
        #pragma unroll
        for (int a = 0; a < 4; a++)
            #pragma unroll
            for (int b2 = 0; b2 < 4; b2++) accf[a][b2] = 0.f;
        gates_mma(sb, E_W0, E_HX, wid, lrow, lcol, accf);
        gates_store(RDf, wid, lane, accf);
        __syncthreads();

        if (tid < 128) {
            float g4[4];
            #pragma unroll
            for (int gate = 0; gate < 4; gate++) {
                int r = gate * 4 + hl;
                float a = 0.f;
                #pragma unroll
                for (int q = 0; q < 8; q++) a += RDf[q * 528 + r * 33 + bq];
                g4[gate] = a + xg[gate];
            }
            float cv = sigf(g4[1]) * c_reg + sigf(g4[0]) * tanh_fast(g4[2]);
            float hn = sigf(g4[3]) * tanh_fast(cv);
            c_reg = cv;
            hout[(bq << 9) + hG * 4 + hl] = __float2half_rn(hn);
            g_enc_out_f16[((size_t)bq * Ssz + s) * Hd + hG * 4 + hl] = __float2half_rn(hn);
        }
        bgen++;
        grid_arrive(0);
        // prefetch next step's xg during barrier slack
        if (s + 1 < Ssz && tid < 128) {
            #pragma unroll
            for (int gate = 0; gate < 4; gate++)
                xg[gate] = __ldcg(&g_enc_xg[((size_t)(s + 1) * Bsz + bq) * FH + gate * Hd + hG * 4 + hl]);
        }
    }
    grid_wait(0, bgen);
    if (tid < 128) {
        g_c[(bq << 9) + hG * 4 + hl] = c_reg;
    }
}

// ---------------- persistent decoder scan (mma gates, fp16 smem caches) ----------------
#define D_W0 0          // Whh fp16 16x520            (16640)
#define D_WC 16640      // Wih-ctx fp16 16x520        (16640)
#define D_HX 33280      // h/ctx fp16 32x520          (33280)
#define D_WA 66560      // attnW fp32 4x516           (8256)
#define D_RD 74816      // reduce fp32 8x528          (16896)
#define D_HP 91712      // hproj fp32 512             (2048)
#define D_VS 93760      // attn_v fp32 512            (2048)
#define D_SC 95808      // scores fp32 64             (256)
#define D_EP 96064      // enc_proj slice fp16 32x512 (32768)
#define D_EO 128832     // enc_out slice fp16 32x512  (32768)
#define DEC_SMEM_BYTES 161600
__global__ void __launch_bounds__(256, 1) dec_scan_kernel(
    const float* __restrict__ Wih, const float* __restrict__ Whh,
    const float* __restrict__ attnW, const float* __restrict__ attnv)
{
    extern __shared__ char smc[];
    __half* W0h = (__half*)(smc + D_W0);
    __half* WCh = (__half*)(smc + D_WC);
    __half* HXh = (__half*)(smc + D_HX);
    float*  WAf = (float*)(smc + D_WA);
    float*  RDf = (float*)(smc + D_RD);
    float*  HPf = (float*)(smc + D_HP);
    float*  VSf = (float*)(smc + D_VS);
    float*  SCf = (float*)(smc + D_SC);
    __half* EPh = (__half*)(smc + D_EP);
    __half* EOh = (__half*)(smc + D_EO);
    const uint32_t sb = smem_to_u32(smc);
    const int tid = threadIdx.x, hG = blockIdx.x;
    const int wid = tid >> 5, lane = tid & 31;
    const int hl = tid >> 5, bq = tid & 31;
    const int lrow = ((lane >> 3) & 1) * 8 + (lane & 7);
    const int lcol = (lane >> 4) * 8;
    const int bB = hG >> 2;
    const int part = hG & 3;

    // prologue loads (once)
    for (int i = tid; i < 16 * 512; i += 256) {
        int r = i >> 9, k = i & 511;
        int j = (r >> 2) * Hd + hG * 4 + (r & 3);
        W0h[r * 520 + k] = __float2half_rn(Whh[(size_t)j * Hd + k]);
        WCh[r * 520 + k] = __float2half_rn(Wih[(size_t)j * (Ed + Hd) + Ed + k]);
    }
    for (int i = tid; i < 4 * 516; i += 256) {
        int r = i / 516, k = i % 516;
        WAf[i] = (k < Hd) ? attnW[(size_t)(hG * 4 + r) * (2 * Hd) + k] : 0.f;
    }
    for (int i = tid; i < Hd; i += 256) VSf[i] = attnv[i];
    for (int i = tid; i < 32 * 512; i += 256) {       // EP fp32->fp16
        int sl = i >> 9, k = i & 511;
        EPh[sl * 512 + k] = __float2half_rn(
            g_enc_proj[((size_t)bB * Ssz + part * 32 + sl) * Hd + k]);
    }
    for (int i = tid; i < 2048; i += 256) {           // EO fp16 via uint4
        int sl = i >> 6, k8 = (i & 63) * 8;
        size_t gidx = ((size_t)bB * Ssz + part * 32 + sl) * Hd + k8;
        *(uint4*)&EOh[sl * 512 + k8] = *(const uint4*)&g_enc_out_f16[gidx];
    }

    float c_reg = 0.f;
    if (tid < 128) c_reg = __ldcg(&g_c[(bq << 9) + hG * 4 + hl]);
    unsigned bgen = 0;

    float xg[4];
    if (tid < 128) {
        #pragma unroll
        for (int gate = 0; gate < 4; gate++)
            xg[gate] = __ldcg(&g_dec_xg[(size_t)bq * FH + gate * Hd + hG * 4 + hl]);
    }

    for (int t = 0; t < T1; t++) {
        if (t > 0) grid_wait(1, bgen);

        const __half* hin = g_h[t & 1];
        __half* hout = g_h[(t + 1) & 1];

        // ---- phase A: load h, hproj, gates h-part ----
        for (int i = tid; i < 2048; i += 256) {
            int b = i >> 6, k8 = (i & 63) * 8;
            *(uint4*)&HXh[b * 520 + k8] = __ldcg((const uint4*)&hin[(b << 9) + k8]);
        }
        __syncthreads();
        {
            const int ko = tid >> 6, bh = (tid >> 1) & 31, kh = tid & 1;
            const float* wa = WAf + ko * 516 + (kh << 8);
            const __half2* hh = (const __half2*)&HXh[bh * 520 + (kh << 8)];
            float a = 0.f;
            #pragma unroll 8
            for (int k2 = 0; k2 < 128; k2++) {
                float2 h2 = __half22float2(hh[k2]);
                a += wa[k2 * 2] * h2.x + wa[k2 * 2 + 1] * h2.y;
            }
            a += __shfl_xor_sync(0xffffffffu, a, 1);
            if (!kh) g_hproj[(bh << 9) + hG * 4 + ko] = a;
        }
        float accf[4][4];
        #pragma unroll
        for (int a2 = 0; a2 < 4; a2++)
            #pragma unroll
            for (int b2 = 0; b2 < 4; b2++) accf[a2][b2] = 0.f;
        gates_mma(sb, D_W0, D_HX, wid, lrow, lcol, accf);
        bgen++; grid_bar(1, bgen);

        // ---- phase B: attention partials (smem-resident) ----
        for (int i = tid; i < Hd; i += 256) HPf[i] = __ldcg(&g_hproj[(bB << 9) + i]);
        __syncthreads();
        {
            const int w = tid >> 5, ln = tid & 31;
            #pragma unroll
            for (int q = 0; q < 4; q++) {
                int sl = w * 4 + q;
                const __half2* ep2 = (const __half2*)&EPh[sl * 512];
                float a = 0.f;
                for (int k2 = ln; k2 < 256; k2 += 32) {
                    float2 e = __half22float2(ep2[k2]);
                    a += tanh_fast(HPf[2 * k2] + e.x) * VSf[2 * k2]
                       + tanh_fast(HPf[2 * k2 + 1] + e.y) * VSf[2 * k2 + 1];
                }
                #pragma unroll
                for (int off = 16; off; off >>= 1) a += __shfl_xor_sync(0xffffffffu, a, off);
                if (!ln) SCf[sl] = a;
            }
        }
        __syncthreads();
        {
            if (tid < 32) SCf[32 + tid] = __expf(SCf[tid]);
            __syncthreads();
            float lloc = 0.f;
            #pragma unroll
            for (int i2 = 0; i2 < 32; i2++) lloc += SCf[32 + i2];

            float a0 = 0.f, a1 = 0.f;
            #pragma unroll 4
            for (int s2 = 0; s2 < 32; s2++) {
                float p = SCf[32 + s2];
                a0 += p * __half2float(EOh[s2 * 512 + tid]);
                a1 += p * __half2float(EOh[s2 * 512 + tid + 256]);
            }
            float* ap = g_attp[bB][part];
            ap[tid] = a0;
            ap[tid + 256] = a1;
            if (tid == 0) ap[513] = lloc;
        }
        bgen++; grid_bar(1, bgen);

        // ---- phase C: combine 4 partials -> g_ctx_f16 ----
        if (tid < 128) {
            const int h = part * 128 + tid;
            float l = __ldcg(&g_attp[bB][0][513]) + __ldcg(&g_attp[bB][1][513])
                    + __ldcg(&g_attp[bB][2][513]) + __ldcg(&g_attp[bB][3][513]);
            float cx = __ldcg(&g_attp[bB][0][h]) + __ldcg(&g_attp[bB][1][h])
                     + __ldcg(&g_attp[bB][2][h]) + __ldcg(&g_attp[bB][3][h]);
            g_ctx_f16[(bB << 9) + h] = __float2half_rn(cx / l);
        }
        bgen++; grid_bar(1, bgen);

        // ---- phase D: gates ctx-part + pointwise ----
        for (int i = tid; i < 2048; i += 256) {
            int b = i >> 6, k8 = (i & 63) * 8;
            *(uint4*)&HXh[b * 520 + k8] = __ldcg((const uint4*)&g_ctx_f16[(b << 9) + k8]);
        }
        __syncthreads();
        gates_mma(sb, D_WC, D_HX, wid, lrow, lcol, accf);
        gates_store(RDf, wid, lane, accf);
        __syncthreads();

        if (tid < 128) {
            float g4[4];
            #pragma unroll
            for (int gate = 0; gate < 4; gate++) {
                int r = gate * 4 + hl;
                float a = 0.f;
                #pragma unroll
                for (int q = 0; q < 8; q++) a += RDf[q * 528 + r * 33 + bq];
                g4[gate] = a + xg[gate];
            }
            float cv = sigf(g4[1]) * c_reg + sigf(g4[0]) * tanh_fast(g4[2]);
            float hn = sigf(g4[3]) * tanh_fast(cv);
            c_reg = cv;
            __half hh = __float2half_rn(hn);
            hout[(bq << 9) + hG * 4 + hl] = hh;
            g_hs_f16[((size_t)bq * T1 + t) * Hd + hG * 4 + hl] = hh;
        }
        bgen++;
        grid_arrive(1);
        // prefetch next step's xg during barrier slack
        if (t + 1 < T1 && tid < 128) {
            #pragma unroll
            for (int gate = 0; gate < 4; gate++)
                xg[gate] = __ldcg(&g_dec_xg[((size_t)(t + 1) * Bsz + bq) * FH + gate * Hd + hG * 4 + hl]);
        }
    }
}

// ---------------- launch ----------------
extern "C" void kernel_launch(void* const* d_in, const int* in_sizes, int n_in,
                              void* d_out, int out_size)
{
    const int*   src     = (const int*)d_in[0];
    const int*   tgt     = (const int*)d_in[1];
    const float* embed   = (const float*)d_in[2];
    const float* enc_Wih = (const float*)d_in[3];
    const float* enc_Whh = (const float*)d_in[4];
    const float* enc_bih = (const float*)d_in[5];
    const float* enc_bhh = (const float*)d_in[6];
    const float* dec_Wih = (const float*)d_in[7];
    const float* dec_Whh = (const float*)d_in[8];
    const float* dec_bih = (const float*)d_in[9];
    const float* dec_bhh = (const float*)d_in[10];
    const float* attn_W  = (const float*)d_in[11];
    const float* attn_b  = (const float*)d_in[12];
    const float* attn_v  = (const float*)d_in[13];
    const float* fc_W    = (const float*)d_in[14];
    const float* fc_b    = (const float*)d_in[15];
    float* out = (float*)d_out;

    float *p_dec_in, *p_enc_xg, *p_dec_xg, *p_enc_proj;
    __half *p_src_emb_f16, *p_enc_out_f16, *p_encWih_f16, *p_attnWe_f16, *p_hs_f16, *p_fcw_f16;
    cudaGetSymbolAddress((void**)&p_dec_in,      g_dec_in);
    cudaGetSymbolAddress((void**)&p_enc_xg,      g_enc_xg);
    cudaGetSymbolAddress((void**)&p_dec_xg,      g_dec_xg);
    cudaGetSymbolAddress((void**)&p_enc_proj,    g_enc_proj);
    cudaGetSymbolAddress((void**)&p_src_emb_f16, g_src_emb_f16);
    cudaGetSymbolAddress((void**)&p_enc_out_f16, g_enc_out_f16);
    cudaGetSymbolAddress((void**)&p_encWih_f16,  g_encWih_f16);
    cudaGetSymbolAddress((void**)&p_attnWe_f16,  g_attnWe_f16);
    cudaGetSymbolAddress((void**)&p_hs_f16,      g_hs_f16);
    cudaGetSymbolAddress((void**)&p_fcw_f16,     g_fcw_f16);

    cudaFuncSetAttribute(enc_scan_kernel,  cudaFuncAttributeMaxDynamicSharedMemorySize, ENC_SMEM_BYTES);
    cudaFuncSetAttribute(dec_scan_kernel,  cudaFuncAttributeMaxDynamicSharedMemorySize, DEC_SMEM_BYTES);
    cudaFuncSetAttribute(hgemm_bias_kernel, cudaFuncAttributeMaxDynamicSharedMemorySize, FC_SMEM_BYTES);

    static cudaStream_t s2 = nullptr;
    static cudaEvent_t evFork = nullptr, evJoin = nullptr;
    if (s2 == nullptr) {
        cudaStreamCreateWithFlags(&s2, cudaStreamNonBlocking);
        cudaEventCreateWithFlags(&evFork, cudaEventDisableTiming);
        cudaEventCreateWithFlags(&evJoin, cudaEventDisableTiming);
    }

    init_state_kernel<<<(Bsz * Hd + 255) / 256, 256>>>();
    gather_src_kernel<<<Ssz * Bsz, Ed>>>(src, embed);
    conv_weights_kernel<<<(FH * Ed / 4 + 255) / 256, 256>>>(enc_Wih, attn_W);

    // fork: decoder-input branch runs concurrently with encoder path
    cudaEventRecord(evFork, 0);
    cudaStreamWaitEvent(s2, evFork, 0);
    gather_dec_kernel<<<T1 * Bsz, Ed, 0, s2>>>(tgt, embed);
    {
        dim3 grid(FH / 128, (T1 * Bsz + 127) / 128);
        sgemm_bias_kernel<<<grid, 256, 0, s2>>>(p_dec_in, Ed, dec_Wih, Ed + Hd, 0,
                                                dec_bih, dec_bhh, p_dec_xg, T1 * Bsz, FH);
    }
    conv_w_kernel<<<(Vsz * Hd / 4 + 255) / 256, 256, 0, s2>>>(fc_W);
    cudaEventRecord(evJoin, s2);

    // enc_xg = src_emb_f16 @ encWih_f16^T + (bih+bhh)
    hgemm_bias_kernel<<<dim3(32, 16), 256, FC_SMEM_BYTES>>>(
        p_src_emb_f16, p_encWih_f16, Ed, Ed / 64,
        enc_bih, enc_bhh, p_enc_xg, Ssz * Bsz, FH);

    enc_scan_kernel<<<NBLK, 256, ENC_SMEM_BYTES>>>(enc_Whh);

    // enc_proj = enc_out_f16 @ attnWe_f16^T + attn_b
    hgemm_bias_kernel<<<dim3(32, 4), 256, FC_SMEM_BYTES>>>(
        p_enc_out_f16, p_attnWe_f16, Hd, Hd / 64,
        attn_b, nullptr, p_enc_proj, Bsz * Ssz, Hd);

    cudaStreamWaitEvent(0, evJoin, 0);

    dec_scan_kernel<<<NBLK, 256, DEC_SMEM_BYTES>>>(dec_Wih, dec_Whh, attn_W, attn_v);

    // final FC = hs_f16 @ fcw_f16^T + fc_b
    hgemm_bias_kernel<<<dim3(MrowsPad / 128, Vsz / 128), 256, FC_SMEM_BYTES>>>(
        p_hs_f16, p_fcw_f16, Hd, Hd / 64,
        fc_b, nullptr, out, Mrows, Vsz);
}